// round 4
// baseline (speedup 1.0000x reference)
#include <cuda_runtime.h>
#include <cstdint>
#include <float.h>
#include <math.h>

// ---------------- problem constants ----------------
#define T_    12
#define K_    50
#define V_    5000
#define B_    256
#define RHO_  300
#define HT_   800
#define HE_   256
#define VK_   (V_ + K_)     // 5050
#define HEK_  (HE_ + K_)    // 306
#define LOGD  (-5.2983173665480363f)   // log(0.005)

#define NA_   (T_*K_*RHO_)  // 180000
#define NE_   (T_*B_*K_)    // 153600

// ---------------- device scratch ----------------
__device__ float g_eps_a[NA_];
__device__ float g_eps_e[NE_];
__device__ float g_eps_t[NE_];
__device__ float g_alphas[NA_];
__device__ float g_beta[T_*K_*V_];      // logits -> beta (in place)  12MB
__device__ float g_inp[B_*T_*HE_];
__device__ float g_gates[B_*4*HE_];
__device__ float g_hstate[B_*HE_];
__device__ float g_cstate[B_*HE_];
__device__ float g_lstm[T_*B_*HE_];
__device__ float g_eta_prev[B_*K_];
__device__ float g_etas[NE_];
__device__ float g_h1e[T_*B_*HT_];
__device__ float g_h1b[B_*HT_];
__device__ float g_h1[T_*B_*HT_];
__device__ float g_h2[T_*B_*HT_];
__device__ float g_mu[NE_];
__device__ float g_ls[NE_];
__device__ float g_theta[NE_];

#define RB_NLL  (12*4*79)   // 3792 blocks of fused NLL gemm
#define RB_COND (79*10)     // 790 blocks of fused cond gemm
#define RB_A    256
__device__ float g_part_nll[RB_NLL];
__device__ float g_part_cond[RB_COND];
__device__ float g_part_a[RB_A];
__device__ float g_part_kt[T_*B_];
__device__ float g_part_ke[T_*B_];

// ---------------- threefry2x32 (exactly JAX's) ----------------
__host__ __device__ inline void tf2x32(unsigned k0, unsigned k1,
                                       unsigned x0, unsigned x1,
                                       unsigned* o0, unsigned* o1) {
    unsigned ks0 = k0, ks1 = k1, ks2 = k0 ^ k1 ^ 0x1BD11BDAu;
    x0 += ks0; x1 += ks1;
#define TF_R(r) { x0 += x1; x1 = (x1 << (r)) | (x1 >> (32 - (r))); x1 ^= x0; }
    TF_R(13) TF_R(15) TF_R(26) TF_R(6)
    x0 += ks1; x1 += ks2 + 1u;
    TF_R(17) TF_R(29) TF_R(16) TF_R(24)
    x0 += ks2; x1 += ks0 + 2u;
    TF_R(13) TF_R(15) TF_R(26) TF_R(6)
    x0 += ks0; x1 += ks1 + 3u;
    TF_R(17) TF_R(29) TF_R(16) TF_R(24)
    x0 += ks1; x1 += ks2 + 4u;
    TF_R(13) TF_R(15) TF_R(26) TF_R(6)
    x0 += ks2; x1 += ks0 + 5u;
#undef TF_R
    *o0 = x0; *o1 = x1;
}

__device__ __forceinline__ float bits2normal(unsigned bits) {
    float f = __uint_as_float((bits >> 9) | 0x3F800000u) - 1.0f;
    const float lo = -0.99999994f;
    float u = fmaf(f, 2.0f, lo);
    u = fmaxf(lo, u);
    return 1.4142135381698608f * erfinvf(u);
}

// partitionable threefry random bits: bits[i] = o0 ^ o1 of tf(key, hi(i)=0, lo(i)=i)
__device__ __forceinline__ float partitionable_normal(unsigned k0, unsigned k1, unsigned i) {
    unsigned o0, o1;
    tf2x32(k0, k1, 0u, i, &o0, &o1);
    return bits2normal(o0 ^ o1);
}

// ---------------- block reductions (fixed order -> deterministic) ----------------
__device__ __forceinline__ float block_sum(float v, float* red) {
    int tid = threadIdx.x, n = blockDim.x;
    red[tid] = v; __syncthreads();
    for (int s = n >> 1; s > 0; s >>= 1) {
        if (tid < s) red[tid] += red[tid + s];
        __syncthreads();
    }
    v = red[0]; __syncthreads();
    return v;
}
__device__ __forceinline__ float block_max(float v, float* red) {
    int tid = threadIdx.x, n = blockDim.x;
    red[tid] = v; __syncthreads();
    for (int s = n >> 1; s > 0; s >>= 1) {
        if (tid < s) red[tid] = fmaxf(red[tid], red[tid + s]);
        __syncthreads();
    }
    v = red[0]; __syncthreads();
    return v;
}

// ---------------- generic tiled fp32 GEMM ----------------
// BNN=false: B row-major [N,Kd] (NT). BNN=true: B row-major [Kd,N] (NN).
template<bool BNN, bool RELU, bool ACC>
__global__ void gemm_k(const float* __restrict__ A, int lda,
                       const float* __restrict__ Bm, int ldb,
                       const float* __restrict__ bias,
                       float* __restrict__ C, int ldc,
                       int M, int N, int Kd) {
    __shared__ float As[16][65];
    __shared__ float Bs[16][65];
    int tid = threadIdx.x;
    int tx = tid & 15, ty = tid >> 4;
    int m0 = blockIdx.y * 64, n0 = blockIdx.x * 64;
    float acc[4][4] = {};
    for (int k0 = 0; k0 < Kd; k0 += 16) {
#pragma unroll
        for (int i = 0; i < 4; i++) {
            int e = tid + i * 256;
            int m = e >> 4, kk = e & 15;
            int gm = m0 + m, gk = k0 + kk;
            float v = 0.f;
            if (gm < M && gk < Kd) v = A[(long)gm * lda + gk];
            As[kk][m] = v;
        }
#pragma unroll
        for (int i = 0; i < 4; i++) {
            int e = tid + i * 256;
            float v = 0.f;
            if (BNN) {
                int kk = e >> 6, n = e & 63;
                int gk = k0 + kk, gn = n0 + n;
                if (gk < Kd && gn < N) v = Bm[(long)gk * ldb + gn];
                Bs[kk][n] = v;
            } else {
                int n = e >> 4, kk = e & 15;
                int gn = n0 + n, gk = k0 + kk;
                if (gn < N && gk < Kd) v = Bm[(long)gn * ldb + gk];
                Bs[kk][n] = v;
            }
        }
        __syncthreads();
#pragma unroll
        for (int kk = 0; kk < 16; kk++) {
            float a[4], b[4];
#pragma unroll
            for (int i = 0; i < 4; i++) a[i] = As[kk][ty + 16 * i];
#pragma unroll
            for (int j = 0; j < 4; j++) b[j] = Bs[kk][tx + 16 * j];
#pragma unroll
            for (int i = 0; i < 4; i++)
#pragma unroll
                for (int j = 0; j < 4; j++)
                    acc[i][j] = fmaf(a[i], b[j], acc[i][j]);
        }
        __syncthreads();
    }
#pragma unroll
    for (int i = 0; i < 4; i++) {
        int m = m0 + ty + 16 * i;
        if (m >= M) continue;
#pragma unroll
        for (int j = 0; j < 4; j++) {
            int n = n0 + tx + 16 * j;
            if (n >= N) continue;
            float v = acc[i][j];
            if (bias) v += bias[n];
            if (ACC) v += C[(long)m * ldc + n];
            if (RELU) v = fmaxf(v, 0.f);
            C[(long)m * ldc + n] = v;
        }
    }
}

// ---------------- fused: tmp = beta@adj, partial += sum(tmp*beta) ----------------
__global__ void gemm_cond_k(const float* __restrict__ adj) {
    __shared__ float As[16][65];
    __shared__ float Bs[16][65];
    __shared__ float red[256];
    const int M = T_ * K_, N = V_, Kd = V_;
    int tid = threadIdx.x;
    int tx = tid & 15, ty = tid >> 4;
    int m0 = blockIdx.y * 64, n0 = blockIdx.x * 64;
    float acc[4][4] = {};
    for (int k0 = 0; k0 < Kd; k0 += 16) {
#pragma unroll
        for (int i = 0; i < 4; i++) {
            int e = tid + i * 256;
            int m = e >> 4, kk = e & 15;
            int gm = m0 + m, gk = k0 + kk;
            float v = 0.f;
            if (gm < M) v = g_beta[(long)gm * V_ + gk];
            As[kk][m] = v;
        }
#pragma unroll
        for (int i = 0; i < 4; i++) {
            int e = tid + i * 256;
            int kk = e >> 6, n = e & 63;
            int gk = k0 + kk, gn = n0 + n;
            float v = 0.f;
            if (gn < N) v = adj[(long)gk * V_ + gn];
            Bs[kk][n] = v;
        }
        __syncthreads();
#pragma unroll
        for (int kk = 0; kk < 16; kk++) {
            float a[4], b[4];
#pragma unroll
            for (int i = 0; i < 4; i++) a[i] = As[kk][ty + 16 * i];
#pragma unroll
            for (int j = 0; j < 4; j++) b[j] = Bs[kk][tx + 16 * j];
#pragma unroll
            for (int i = 0; i < 4; i++)
#pragma unroll
                for (int j = 0; j < 4; j++)
                    acc[i][j] = fmaf(a[i], b[j], acc[i][j]);
        }
        __syncthreads();
    }
    float local = 0.f;
#pragma unroll
    for (int i = 0; i < 4; i++) {
        int m = m0 + ty + 16 * i;
        if (m >= M) continue;
#pragma unroll
        for (int j = 0; j < 4; j++) {
            int n = n0 + tx + 16 * j;
            if (n >= N) continue;
            local += acc[i][j] * g_beta[(long)m * V_ + n];
        }
    }
    float s = block_sum(local, red);
    if (tid == 0) g_part_cond[blockIdx.y * gridDim.x + blockIdx.x] = s;
}

// ---------------- fused: lik = theta_t@beta_t, partial += -log(lik+1e-6)*bow ----------------
// grid: (79, 4, 12)   M=B_ per t, N=V_, Kd=K_
__global__ void gemm_nll_k(const float* __restrict__ bow) {
    __shared__ float As[16][65];
    __shared__ float Bs[16][65];
    __shared__ float red[256];
    const int M = B_, N = V_, Kd = K_;
    int t = blockIdx.z;
    const float* Ath = g_theta + (long)t * B_ * K_;
    const float* Bbe = g_beta + (long)t * K_ * V_;
    int tid = threadIdx.x;
    int tx = tid & 15, ty = tid >> 4;
    int m0 = blockIdx.y * 64, n0 = blockIdx.x * 64;
    float acc[4][4] = {};
    for (int k0 = 0; k0 < Kd; k0 += 16) {
#pragma unroll
        for (int i = 0; i < 4; i++) {
            int e = tid + i * 256;
            int m = e >> 4, kk = e & 15;
            int gm = m0 + m, gk = k0 + kk;
            float v = 0.f;
            if (gm < M && gk < Kd) v = Ath[(long)gm * Kd + gk];
            As[kk][m] = v;
        }
#pragma unroll
        for (int i = 0; i < 4; i++) {
            int e = tid + i * 256;
            int kk = e >> 6, n = e & 63;
            int gk = k0 + kk, gn = n0 + n;
            float v = 0.f;
            if (gk < Kd && gn < N) v = Bbe[(long)gk * V_ + gn];
            Bs[kk][n] = v;
        }
        __syncthreads();
#pragma unroll
        for (int kk = 0; kk < 16; kk++) {
            float a[4], b[4];
#pragma unroll
            for (int i = 0; i < 4; i++) a[i] = As[kk][ty + 16 * i];
#pragma unroll
            for (int j = 0; j < 4; j++) b[j] = Bs[kk][tx + 16 * j];
#pragma unroll
            for (int i = 0; i < 4; i++)
#pragma unroll
                for (int j = 0; j < 4; j++)
                    acc[i][j] = fmaf(a[i], b[j], acc[i][j]);
        }
        __syncthreads();
    }
    float local = 0.f;
#pragma unroll
    for (int i = 0; i < 4; i++) {
        int b = m0 + ty + 16 * i;   // batch index
        if (b >= M) continue;
#pragma unroll
        for (int j = 0; j < 4; j++) {
            int v = n0 + tx + 16 * j;
            if (v >= N) continue;
            float w = bow[((long)b * T_ + t) * V_ + v];
            local += -logf(acc[i][j] + 1e-6f) * w;
        }
    }
    float s = block_sum(local, red);
    if (tid == 0)
        g_part_nll[(blockIdx.z * gridDim.y + blockIdx.y) * gridDim.x + blockIdx.x] = s;
}

// ---------------- small kernels ----------------
__global__ void init_zero_kernel() {
    int idx = blockIdx.x * blockDim.x + threadIdx.x;
    if (idx < B_ * HE_) { g_hstate[idx] = 0.f; g_cstate[idx] = 0.f; }
    int j = idx - B_ * HE_;
    if (j >= 0 && j < B_ * K_) g_eta_prev[j] = 0.f;
}

// partitionable random_bits: one threefry eval per element, XOR of halves
__global__ void eps_kernel(unsigned a0, unsigned a1, unsigned e0, unsigned e1,
                           unsigned t0, unsigned t1) {
    int i = blockIdx.x * blockDim.x + threadIdx.x;
    if (i < NA_) {
        g_eps_a[i] = partitionable_normal(a0, a1, (unsigned)i);
    } else if (i < NA_ + NE_) {
        int j = i - NA_;
        g_eps_e[j] = partitionable_normal(e0, e1, (unsigned)j);
    } else if (i < NA_ + 2 * NE_) {
        int j = i - NA_ - NE_;
        g_eps_t[j] = partitionable_normal(t0, t1, (unsigned)j);
    }
}

__global__ void alphas_kernel(const float* __restrict__ muq, const float* __restrict__ lsq) {
    int idx = blockIdx.x * blockDim.x + threadIdx.x;
    if (idx >= NA_) return;
    int t = idx / (K_ * RHO_), rem = idx % (K_ * RHO_);
    int k = rem / RHO_, r = rem % RHO_;
    int src = (k * T_ + t) * RHO_ + r;
    g_alphas[idx] = muq[src] + g_eps_a[idx] * expf(0.5f * lsq[src]);
}

__global__ void kld_alpha_kernel(const float* __restrict__ muq, const float* __restrict__ lsq) {
    __shared__ float red[256];
    float acc = 0.f;
    for (int idx = blockIdx.x * blockDim.x + threadIdx.x; idx < NA_;
         idx += gridDim.x * blockDim.x) {
        int t = idx / (K_ * RHO_), rem = idx % (K_ * RHO_);
        int k = rem / RHO_, r = rem % RHO_;
        int src = (k * T_ + t) * RHO_ + r;
        float mu = muq[src];
        float ls = lsq[src];
        float qls = fminf(fmaxf(ls, -100.f), 100.f);
        float pmu = (t == 0) ? 0.f : g_alphas[idx - K_ * RHO_];
        float pls = (t == 0) ? 0.f : LOGD;
        float d = mu - pmu;
        acc += (expf(qls) + d * d) / (expf(pls) + 1e-6f) - 1.f + pls - qls;
    }
    float s = block_sum(acc, red);
    if (threadIdx.x == 0) g_part_a[blockIdx.x] = s;
}

__global__ void softmax_rows_kernel(float* data, int cols) {
    __shared__ float red[256];
    long base = (long)blockIdx.x * cols;
    int tid = threadIdx.x;
    float m = -FLT_MAX;
    for (int c = tid; c < cols; c += 256) m = fmaxf(m, data[base + c]);
    m = block_max(m, red);
    float s = 0.f;
    for (int c = tid; c < cols; c += 256) {
        float e = expf(data[base + c] - m);
        data[base + c] = e; s += e;
    }
    s = block_sum(s, red);
    for (int c = tid; c < cols; c += 256) data[base + c] = data[base + c] / s;
}

__global__ void lstm_cell_kernel(int t) {
    int idx = blockIdx.x * blockDim.x + threadIdx.x;
    if (idx >= B_ * HE_) return;
    int b = idx / HE_, j = idx % HE_;
    const float* g = g_gates + b * 4 * HE_;
    float gi = g[j], gf = g[HE_ + j], gg = g[2 * HE_ + j], go = g[3 * HE_ + j];
    float si = 1.f / (1.f + expf(-gi));
    float sf = 1.f / (1.f + expf(-gf));
    float so = 1.f / (1.f + expf(-go));
    float c = sf * g_cstate[idx] + si * tanhf(gg);
    float h = so * tanhf(c);
    g_cstate[idx] = c; g_hstate[idx] = h;
    g_lstm[((long)t * B_ + b) * HE_ + j] = h;
}

__global__ void eta_step_kernel(const float* __restrict__ mueW, const float* __restrict__ mueb,
                                const float* __restrict__ lseW, const float* __restrict__ lseb,
                                int t) {
    __shared__ float z[HEK_];
    __shared__ float red[64];
    int b = blockIdx.x, tid = threadIdx.x;
    for (int c = tid; c < HE_; c += 64) z[c] = g_lstm[((long)t * B_ + b) * HE_ + c];
    for (int c = tid; c < K_; c += 64) z[HE_ + c] = g_eta_prev[b * K_ + c];
    __syncthreads();
    float kl = 0.f, eta = 0.f;
    if (tid < K_) {
        const float* wm = mueW + tid * HEK_;
        const float* wl = lseW + tid * HEK_;
        float mu = mueb[tid], ls = lseb[tid];
#pragma unroll 2
        for (int c = 0; c < HEK_; c++) {
            float zc = z[c];
            mu = fmaf(zc, wm[c], mu);
            ls = fmaf(zc, wl[c], ls);
        }
        float eps = g_eps_e[((long)t * B_ + b) * K_ + tid];
        eta = mu + eps * expf(0.5f * ls);
        g_etas[((long)t * B_ + b) * K_ + tid] = eta;
        float qls = fminf(fmaxf(ls, -100.f), 100.f);
        float pmu = z[HE_ + tid];
        float pls = (t == 0) ? 0.f : LOGD;
        float d = mu - pmu;
        kl = (expf(qls) + d * d) / (expf(pls) + 1e-6f) - 1.f + pls - qls;
    }
    float s = block_sum((tid < K_) ? kl : 0.f, red);
    if (tid == 0) g_part_ke[t * B_ + b] = s;
    if (tid < K_) g_eta_prev[b * K_ + tid] = eta;
}

__global__ void combine_h1_kernel() {
    int idx = blockIdx.x * blockDim.x + threadIdx.x;
    if (idx >= T_ * B_ * HT_) return;
    int row = idx / HT_, j = idx % HT_;
    int b = row % B_;
    g_h1[idx] = fmaxf(g_h1e[idx] + g_h1b[b * HT_ + j], 0.f);
}

__global__ void theta_kernel() {
    __shared__ float red[64];
    int row = blockIdx.x, k = threadIdx.x;
    long base = (long)row * K_;
    bool val = k < K_;
    float mu = 0.f, ls = 0.f, zv = -FLT_MAX;
    if (val) {
        mu = g_mu[base + k];
        ls = g_ls[base + k];
        zv = mu + g_eps_t[base + k] * expf(0.5f * ls);
    }
    float mx = block_max(zv, red);
    float e = val ? expf(zv - mx) : 0.f;
    float sum = block_sum(e, red);
    if (val) g_theta[base + k] = e / sum;
    float kl = 0.f;
    if (val) {
        float qls = fminf(fmaxf(ls, -100.f), 100.f);
        float d = mu - g_etas[base + k];
        kl = (expf(qls) + d * d) / (1.f + 1e-6f) - 1.f - qls;
    }
    float s = block_sum(kl, red);
    if (k == 0) g_part_kt[row] = s;
}

__global__ void final_reduce_kernel(float* out, int out_size) {
    __shared__ float red[256];
    int tid = threadIdx.x;
    float v;
    v = 0.f; for (int i = tid; i < RB_NLL;  i += 256) v += g_part_nll[i];
    float nll  = block_sum(v, red) * (10.0f / B_);
    v = 0.f; for (int i = tid; i < T_ * B_; i += 256) v += g_part_kt[i];
    float kt   = block_sum(v, red) * (0.5f / (T_ * B_));
    v = 0.f; for (int i = tid; i < RB_A;    i += 256) v += g_part_a[i];
    float ka   = block_sum(v, red) * (0.5f / (T_ * K_));
    v = 0.f; for (int i = tid; i < T_ * B_; i += 256) v += g_part_ke[i];
    float ke   = block_sum(v, red) * (0.5f / B_);
    v = 0.f; for (int i = tid; i < RB_COND; i += 256) v += g_part_cond[i];
    float cond = block_sum(v, red) * (-0.01f);
    if (tid == 0) {
        if (out_size > 0) out[0] = nll;
        if (out_size > 1) out[1] = kt;
        if (out_size > 2) out[2] = ka;
        if (out_size > 3) out[3] = ke;
        if (out_size > 4) out[4] = cond;
    }
}

// ---------------- host driver ----------------
extern "C" void kernel_launch(void* const* d_in, const int* in_sizes, int n_in,
                              void* d_out, int out_size) {
    (void)in_sizes; (void)n_in;
    const float* nb   = (const float*)d_in[0];
    const float* bow  = (const float*)d_in[1];
    const float* adj  = (const float*)d_in[2];
    const float* muqa = (const float*)d_in[3];
    const float* lsqa = (const float*)d_in[4];
    const float* rhoW = (const float*)d_in[5];
    const float* rhob = (const float*)d_in[6];
    const float* W1   = (const float*)d_in[7];
    const float* b1   = (const float*)d_in[8];
    const float* W2   = (const float*)d_in[9];
    const float* b2   = (const float*)d_in[10];
    const float* mutW = (const float*)d_in[11];
    const float* mutb = (const float*)d_in[12];
    const float* lstW = (const float*)d_in[13];
    const float* lstb = (const float*)d_in[14];
    const float* qeW  = (const float*)d_in[15];
    const float* qeb  = (const float*)d_in[16];
    const float* Wih  = (const float*)d_in[17];
    const float* Whh  = (const float*)d_in[18];
    const float* bih  = (const float*)d_in[19];
    const float* bhh  = (const float*)d_in[20];
    const float* mueW = (const float*)d_in[21];
    const float* mueb = (const float*)d_in[22];
    const float* lseW = (const float*)d_in[23];
    const float* lseb = (const float*)d_in[24];
    float* out = (float*)d_out;

    // JAX partitionable threefry: split(key(42), 3) -> key_i = tf((0,42), 0, i)
    unsigned ka0, ka1, ke0, ke1, kt0, kt1;
    tf2x32(0u, 42u, 0u, 0u, &ka0, &ka1);   // ek[0] -> eps_alpha
    tf2x32(0u, 42u, 0u, 1u, &ke0, &ke1);   // ek[1] -> eps_eta
    tf2x32(0u, 42u, 0u, 2u, &kt0, &kt1);   // ek[2] -> eps_theta

    float *p_alphas, *p_beta, *p_inp, *p_gates, *p_h, *p_etas;
    float *p_h1e, *p_h1b, *p_h1, *p_h2, *p_mu, *p_ls;
    cudaGetSymbolAddress((void**)&p_alphas, g_alphas);
    cudaGetSymbolAddress((void**)&p_beta,   g_beta);
    cudaGetSymbolAddress((void**)&p_inp,    g_inp);
    cudaGetSymbolAddress((void**)&p_gates,  g_gates);
    cudaGetSymbolAddress((void**)&p_h,      g_hstate);
    cudaGetSymbolAddress((void**)&p_etas,   g_etas);
    cudaGetSymbolAddress((void**)&p_h1e,    g_h1e);
    cudaGetSymbolAddress((void**)&p_h1b,    g_h1b);
    cudaGetSymbolAddress((void**)&p_h1,     g_h1);
    cudaGetSymbolAddress((void**)&p_h2,     g_h2);
    cudaGetSymbolAddress((void**)&p_mu,     g_mu);
    cudaGetSymbolAddress((void**)&p_ls,     g_ls);

    // 1. re-init recurrent state (every replay)
    init_zero_kernel<<<(B_ * HE_ + B_ * K_ + 255) / 256, 256>>>();

    // 2. RNG (one threefry eval per element, partitionable scheme)
    int totalElems = NA_ + 2 * NE_;
    eps_kernel<<<(totalElems + 255) / 256, 256>>>(ka0, ka1, ke0, ke1, kt0, kt1);

    // 3. alphas + KL(alpha)
    alphas_kernel<<<(NA_ + 255) / 256, 256>>>(muqa, lsqa);
    kld_alpha_kernel<<<RB_A, 256>>>(muqa, lsqa);

    // 4. beta = softmax(alphas @ rho_W^T + rho_b)   [600, V]
    gemm_k<false, false, false><<<dim3(79, 10), 256>>>(
        p_alphas, RHO_, rhoW, RHO_, rhob, p_beta, V_, T_ * K_, V_, RHO_);
    softmax_rows_kernel<<<T_ * K_, 256>>>(p_beta, V_);

    // 5. adjacency GEMM fused with trace reduction
    gemm_cond_k<<<dim3(79, 10), 256>>>(adj);

    // 6. LSTM input: inp = bow_t @ qe_W^T + qe_b  [(b,t), HE]
    gemm_k<false, false, false><<<dim3(4, 48), 256>>>(
        bow, V_, qeW, V_, qeb, p_inp, HE_, B_ * T_, HE_, V_);

    // 7. LSTM scan
    for (int t = 0; t < T_; t++) {
        gemm_k<false, false, false><<<dim3(16, 4), 256>>>(
            p_inp + t * HE_, T_ * HE_, Wih, HE_, bih, p_gates, 4 * HE_, B_, 4 * HE_, HE_);
        gemm_k<false, false, true><<<dim3(16, 4), 256>>>(
            p_h, HE_, Whh, HE_, bhh, p_gates, 4 * HE_, B_, 4 * HE_, HE_);
        lstm_cell_kernel<<<(B_ * HE_ + 255) / 256, 256>>>(t);
    }

    // 8. eta recurrence
    for (int t = 0; t < T_; t++)
        eta_step_kernel<<<B_, 64>>>(mueW, mueb, lseW, lseb, t);

    // 9. theta encoder: split W1 into t-invariant bow-part + tiny eta-part
    gemm_k<false, false, false><<<dim3(13, 48), 256>>>(
        p_etas, K_, W1 + V_, VK_, b1, p_h1e, HT_, T_ * B_, HT_, K_);
    gemm_k<false, false, false><<<dim3(13, 4), 256>>>(
        nb, V_, W1, VK_, nullptr, p_h1b, HT_, B_, HT_, V_);
    combine_h1_kernel<<<(T_ * B_ * HT_ + 255) / 256, 256>>>();
    gemm_k<false, true, false><<<dim3(13, 48), 256>>>(
        p_h1, HT_, W2, HT_, b2, p_h2, HT_, T_ * B_, HT_, HT_);
    gemm_k<false, false, false><<<dim3(1, 48), 256>>>(
        p_h2, HT_, mutW, HT_, mutb, p_mu, K_, T_ * B_, K_, HT_);
    gemm_k<false, false, false><<<dim3(1, 48), 256>>>(
        p_h2, HT_, lstW, HT_, lstb, p_ls, K_, T_ * B_, K_, HT_);

    // 10. theta softmax + KL(theta)
    theta_kernel<<<T_ * B_, 64>>>();

    // 11. decode GEMM fused with NLL reduction (all t in one launch)
    gemm_nll_k<<<dim3(79, 4, 12), 256>>>(bow);

    // 12. final scalars
    final_reduce_kernel<<<1, 256>>>(out, out_size);
}

// round 9
// speedup vs baseline: 1.7105x; 1.7105x over previous
#include <cuda_runtime.h>
#include <cuda_bf16.h>
#include <cstdint>
#include <float.h>
#include <math.h>

// ---------------- problem constants ----------------
#define T_    12
#define K_    50
#define V_    5000
#define B_    256
#define RHO_  300
#define HT_   800
#define HE_   256
#define VK_   (V_ + K_)     // 5050
#define HEK_  (HE_ + K_)    // 306
#define LOGD  (-5.2983173665480363f)

#define NA_   (T_*K_*RHO_)  // 180000
#define NE_   (T_*B_*K_)    // 153600

// padded dims for tensor-core tiles (rows -> mult of 128, K -> mult of 32)
#define KP_V   5024
#define KP_RHO 320
#define NP_V   5120
#define MP_TK  640
#define NP_HT  896

// ---------------- device scratch (zero-initialized .bss; pads never written) ----
__device__ float g_eps_a[NA_];
__device__ float g_eps_e[NE_];
__device__ float g_eps_t[NE_];
__device__ float g_alphas[NA_];
__device__ __nv_bfloat16 g_alphas_bf[MP_TK*KP_RHO];
__device__ float g_beta[T_*K_*V_];                 // fp32 beta (softmax out)
__device__ __nv_bfloat16 g_beta_bf[MP_TK*KP_V];
__device__ __nv_bfloat16 g_adjT_bf[NP_V*KP_V];     // adj transposed [n][k]
__device__ __nv_bfloat16 g_bow_bf[B_*T_*KP_V];
__device__ __nv_bfloat16 g_qew_bf[HE_*KP_V];
__device__ __nv_bfloat16 g_nb_bf[B_*KP_V];
__device__ __nv_bfloat16 g_w1_bf[NP_HT*KP_V];
__device__ __nv_bfloat16 g_rhow_bf[NP_V*KP_RHO];
__device__ __nv_bfloat16 g_w2_bf[NP_HT*HT_];
__device__ __nv_bfloat16 g_wml_bf[128*HT_];
__device__ float g_wmlb[128];
__device__ float g_wih_int[4*HE_*HE_];
__device__ float g_whh_int[4*HE_*HE_];
__device__ float g_bi_int[4*HE_];
__device__ float g_inp[B_*T_*HE_];                 // [b*T+t][HE]
__device__ float g_gx[B_*T_*4*HE_];                // [b*T+t][1024]
__device__ float g_hbuf[2][B_*HE_];
__device__ float g_cstate[B_*HE_];
__device__ float g_lstm[T_*B_*HE_];                // [t*B+b][HE]
__device__ float g_eta_prev[B_*K_];
__device__ float g_etas[NE_];                      // [t*B+b][K]
__device__ float g_h1e[T_*B_*HT_];
__device__ float g_h1b[B_*HT_];
__device__ __nv_bfloat16 g_h1_bf[T_*B_*HT_];
__device__ __nv_bfloat16 g_h2_bf[T_*B_*HT_];
__device__ float g_mls[T_*B_*100];
__device__ float g_theta_arr[NE_];

#define RB_NLL  (12*4*79)
#define RB_COND 200         // 40 x 5 tc blocks
#define RB_A    256
__device__ float g_part_nll[RB_NLL];
__device__ float g_part_cond[RB_COND];
__device__ float g_part_a[RB_A];
__device__ float g_part_kt[T_*B_];
__device__ float g_part_ke[T_*B_];

// ---------------- threefry2x32 (JAX partitionable) ----------------
__host__ __device__ inline void tf2x32(unsigned k0, unsigned k1,
                                       unsigned x0, unsigned x1,
                                       unsigned* o0, unsigned* o1) {
    unsigned ks0 = k0, ks1 = k1, ks2 = k0 ^ k1 ^ 0x1BD11BDAu;
    x0 += ks0; x1 += ks1;
#define TF_R(r) { x0 += x1; x1 = (x1 << (r)) | (x1 >> (32 - (r))); x1 ^= x0; }
    TF_R(13) TF_R(15) TF_R(26) TF_R(6)
    x0 += ks1; x1 += ks2 + 1u;
    TF_R(17) TF_R(29) TF_R(16) TF_R(24)
    x0 += ks2; x1 += ks0 + 2u;
    TF_R(13) TF_R(15) TF_R(26) TF_R(6)
    x0 += ks0; x1 += ks1 + 3u;
    TF_R(17) TF_R(29) TF_R(16) TF_R(24)
    x0 += ks1; x1 += ks2 + 4u;
    TF_R(13) TF_R(15) TF_R(26) TF_R(6)
    x0 += ks2; x1 += ks0 + 5u;
#undef TF_R
    *o0 = x0; *o1 = x1;
}

__device__ __forceinline__ float bits2normal(unsigned bits) {
    float f = __uint_as_float((bits >> 9) | 0x3F800000u) - 1.0f;
    const float lo = -0.99999994f;
    float u = fmaf(f, 2.0f, lo);
    u = fmaxf(lo, u);
    return 1.4142135381698608f * erfinvf(u);
}

__device__ __forceinline__ float partitionable_normal(unsigned k0, unsigned k1, unsigned i) {
    unsigned o0, o1;
    tf2x32(k0, k1, 0u, i, &o0, &o1);
    return bits2normal(o0 ^ o1);
}

// ---------------- block reductions ----------------
__device__ __forceinline__ float block_sum(float v, float* red) {
    int tid = threadIdx.x, n = blockDim.x;
    red[tid] = v; __syncthreads();
    for (int s = n >> 1; s > 0; s >>= 1) {
        if (tid < s) red[tid] += red[tid + s];
        __syncthreads();
    }
    v = red[0]; __syncthreads();
    return v;
}
__device__ __forceinline__ float block_max(float v, float* red) {
    int tid = threadIdx.x, n = blockDim.x;
    red[tid] = v; __syncthreads();
    for (int s = n >> 1; s > 0; s >>= 1) {
        if (tid < s) red[tid] = fmaxf(red[tid], red[tid + s]);
        __syncthreads();
    }
    v = red[0]; __syncthreads();
    return v;
}

// ---------------- bf16 tensor-core GEMM (NT): C[M,N] = A[M,Kp] * B[N,Kp]^T ----------------
// A, B pre-padded: rows to mult of 128 (zeros), K to mult of 32 (zeros). No guards in hot loop.
__device__ __forceinline__ void mma16816(float* c, const uint32_t* a, uint32_t b0, uint32_t b1) {
    asm volatile(
        "mma.sync.aligned.m16n8k16.row.col.f32.bf16.bf16.f32 "
        "{%0,%1,%2,%3}, {%4,%5,%6,%7}, {%8,%9}, {%0,%1,%2,%3};\n"
        : "+f"(c[0]), "+f"(c[1]), "+f"(c[2]), "+f"(c[3])
        : "r"(a[0]), "r"(a[1]), "r"(a[2]), "r"(a[3]), "r"(b0), "r"(b1));
}

template<bool BIAS, bool RELU, bool OUTBF, bool CONDEPI>
__global__ void __launch_bounds__(256) tc_gemm_k(
    const __nv_bfloat16* __restrict__ A, int lda,
    const __nv_bfloat16* __restrict__ B, int ldb,
    const float* __restrict__ bias,
    float* __restrict__ C, __nv_bfloat16* __restrict__ Cbf, int ldc,
    const float* __restrict__ Cf,   // cond: fp32 beta, pitch ldc
    float* __restrict__ part,
    int M, int N, int Kp) {
    __shared__ __nv_bfloat16 As[128][40];
    __shared__ __nv_bfloat16 Bs[128][40];
    __shared__ float red[256];
    int tid = threadIdx.x;
    int lane = tid & 31, wid = tid >> 5;
    int wm = wid & 3, wn = wid >> 2;          // 4 m-warps x 2 n-warps
    int g = lane >> 2, t4 = lane & 3;
    long m0 = (long)blockIdx.y * 128, n0 = (long)blockIdx.x * 128;
    float acc[2][8][4] = {};
    int arow = tid >> 2;                       // 0..63
    int akc = (tid & 3) * 8;
    for (int k0 = 0; k0 < Kp; k0 += 32) {
#pragma unroll
        for (int h = 0; h < 2; h++) {
            int r = arow + h * 64;
            *(uint4*)&As[r][akc] = *(const uint4*)&A[(m0 + r) * (long)lda + k0 + akc];
            *(uint4*)&Bs[r][akc] = *(const uint4*)&B[(n0 + r) * (long)ldb + k0 + akc];
        }
        __syncthreads();
#pragma unroll
        for (int ks = 0; ks < 32; ks += 16) {
            uint32_t a[2][4];
#pragma unroll
            for (int i = 0; i < 2; i++) {
                int r = wm * 32 + i * 16 + g;
                a[i][0] = *(const uint32_t*)&As[r][ks + 2 * t4];
                a[i][1] = *(const uint32_t*)&As[r + 8][ks + 2 * t4];
                a[i][2] = *(const uint32_t*)&As[r][ks + 2 * t4 + 8];
                a[i][3] = *(const uint32_t*)&As[r + 8][ks + 2 * t4 + 8];
            }
#pragma unroll
            for (int j = 0; j < 8; j++) {
                int n = wn * 64 + j * 8 + g;
                uint32_t b0 = *(const uint32_t*)&Bs[n][ks + 2 * t4];
                uint32_t b1 = *(const uint32_t*)&Bs[n][ks + 2 * t4 + 8];
#pragma unroll
                for (int i = 0; i < 2; i++)
                    mma16816(acc[i][j], a[i], b0, b1);
            }
        }
        __syncthreads();
    }
    if (CONDEPI) {
        float local = 0.f;
#pragma unroll
        for (int i = 0; i < 2; i++) {
#pragma unroll
            for (int j = 0; j < 8; j++) {
                long m = m0 + wm * 32 + i * 16 + g;
                long n = n0 + wn * 64 + j * 8 + 2 * t4;
                if (m < M) {
                    if (n < N)     local += acc[i][j][0] * Cf[m * ldc + n];
                    if (n + 1 < N) local += acc[i][j][1] * Cf[m * ldc + n + 1];
                }
                if (m + 8 < M) {
                    if (n < N)     local += acc[i][j][2] * Cf[(m + 8) * ldc + n];
                    if (n + 1 < N) local += acc[i][j][3] * Cf[(m + 8) * ldc + n + 1];
                }
            }
        }
        float s = block_sum(local, red);
        if (tid == 0) part[blockIdx.y * gridDim.x + blockIdx.x] = s;
    } else {
#pragma unroll
        for (int i = 0; i < 2; i++) {
#pragma unroll
            for (int j = 0; j < 8; j++) {
                long m = m0 + wm * 32 + i * 16 + g;
                long n = n0 + wn * 64 + j * 8 + 2 * t4;
#pragma unroll
                for (int q = 0; q < 4; q++) {
                    long mm = m + (q >> 1) * 8;
                    long nn = n + (q & 1);
                    if (mm < M && nn < N) {
                        float v = acc[i][j][q];
                        if (BIAS) v += bias[nn];
                        if (RELU) v = fmaxf(v, 0.f);
                        if (OUTBF) Cbf[mm * ldc + nn] = __float2bfloat16(v);
                        else       C[mm * ldc + nn] = v;
                    }
                }
            }
        }
    }
}

// ---------------- generic tiled fp32 GEMM (NT) ----------------
template<bool RELU>
__global__ void gemm_k(const float* __restrict__ A, int lda,
                       const float* __restrict__ Bm, int ldb,
                       const float* __restrict__ bias,
                       float* __restrict__ C, int ldc,
                       int M, int N, int Kd) {
    __shared__ float As[16][65];
    __shared__ float Bs[16][65];
    int tid = threadIdx.x;
    int tx = tid & 15, ty = tid >> 4;
    int m0 = blockIdx.y * 64, n0 = blockIdx.x * 64;
    float acc[4][4] = {};
    for (int k0 = 0; k0 < Kd; k0 += 16) {
#pragma unroll
        for (int i = 0; i < 4; i++) {
            int e = tid + i * 256;
            int m = e >> 4, kk = e & 15;
            int gm = m0 + m, gk = k0 + kk;
            float v = 0.f;
            if (gm < M && gk < Kd) v = A[(long)gm * lda + gk];
            As[kk][m] = v;
        }
#pragma unroll
        for (int i = 0; i < 4; i++) {
            int e = tid + i * 256;
            int n = e >> 4, kk = e & 15;
            int gn = n0 + n, gk = k0 + kk;
            float v = 0.f;
            if (gn < N && gk < Kd) v = Bm[(long)gn * ldb + gk];
            Bs[kk][n] = v;
        }
        __syncthreads();
#pragma unroll
        for (int kk = 0; kk < 16; kk++) {
            float a[4], b[4];
#pragma unroll
            for (int i = 0; i < 4; i++) a[i] = As[kk][ty + 16 * i];
#pragma unroll
            for (int j = 0; j < 4; j++) b[j] = Bs[kk][tx + 16 * j];
#pragma unroll
            for (int i = 0; i < 4; i++)
#pragma unroll
                for (int j = 0; j < 4; j++)
                    acc[i][j] = fmaf(a[i], b[j], acc[i][j]);
        }
        __syncthreads();
    }
#pragma unroll
    for (int i = 0; i < 4; i++) {
        int m = m0 + ty + 16 * i;
        if (m >= M) continue;
#pragma unroll
        for (int j = 0; j < 4; j++) {
            int n = n0 + tx + 16 * j;
            if (n >= N) continue;
            float v = acc[i][j];
            if (bias) v += bias[n];
            if (RELU) v = fmaxf(v, 0.f);
            C[(long)m * ldc + n] = v;
        }
    }
}

// ---------------- fused fp32: lik = theta_t@beta_t -> -log(lik+1e-6)*bow ----------------
__global__ void gemm_nll_k(const float* __restrict__ bow) {
    __shared__ float As[16][65];
    __shared__ float Bs[16][65];
    __shared__ float red[256];
    const int M = B_, N = V_, Kd = K_;
    int t = blockIdx.z;
    int tid = threadIdx.x;
    int tx = tid & 15, ty = tid >> 4;
    int m0 = blockIdx.y * 64, n0 = blockIdx.x * 64;
    float acc[4][4] = {};
    for (int k0 = 0; k0 < Kd; k0 += 16) {
#pragma unroll
        for (int i = 0; i < 4; i++) {
            int e = tid + i * 256;
            int m = e >> 4, kk = e & 15;
            int gm = m0 + m, gk = k0 + kk;
            float v = 0.f;
            if (gm < M && gk < Kd) v = g_theta_arr[((long)t * B_ + gm) * K_ + gk];
            As[kk][m] = v;
        }
#pragma unroll
        for (int i = 0; i < 4; i++) {
            int e = tid + i * 256;
            int kk = e >> 6, n = e & 63;
            int gk = k0 + kk, gn = n0 + n;
            float v = 0.f;
            if (gk < Kd && gn < N) v = g_beta[((long)t * K_ + gk) * V_ + gn];
            Bs[kk][n] = v;
        }
        __syncthreads();
#pragma unroll
        for (int kk = 0; kk < 16; kk++) {
            float a[4], b[4];
#pragma unroll
            for (int i = 0; i < 4; i++) a[i] = As[kk][ty + 16 * i];
#pragma unroll
            for (int j = 0; j < 4; j++) b[j] = Bs[kk][tx + 16 * j];
#pragma unroll
            for (int i = 0; i < 4; i++)
#pragma unroll
                for (int j = 0; j < 4; j++)
                    acc[i][j] = fmaf(a[i], b[j], acc[i][j]);
        }
        __syncthreads();
    }
    float local = 0.f;
#pragma unroll
    for (int i = 0; i < 4; i++) {
        int b = m0 + ty + 16 * i;
        if (b >= M) continue;
#pragma unroll
        for (int j = 0; j < 4; j++) {
            int v = n0 + tx + 16 * j;
            if (v >= N) continue;
            float w = bow[((long)b * T_ + t) * V_ + v];
            local += -logf(acc[i][j] + 1e-6f) * w;
        }
    }
    float s = block_sum(local, red);
    if (tid == 0)
        g_part_nll[(blockIdx.z * gridDim.y + blockIdx.y) * gridDim.x + blockIdx.x] = s;
}

// ---------------- prep / conversion kernels ----------------
__global__ void init_zero_kernel() {
    int idx = blockIdx.x * blockDim.x + threadIdx.x;
    if (idx < B_ * HE_) { g_hbuf[0][idx] = 0.f; g_cstate[idx] = 0.f; }
    int j = idx - B_ * HE_;
    if (j >= 0 && j < B_ * K_) g_eta_prev[j] = 0.f;
}

__global__ void eps_kernel(unsigned a0, unsigned a1, unsigned e0, unsigned e1,
                           unsigned t0, unsigned t1) {
    int i = blockIdx.x * blockDim.x + threadIdx.x;
    if (i < NA_) {
        g_eps_a[i] = partitionable_normal(a0, a1, (unsigned)i);
    } else if (i < NA_ + NE_) {
        int j = i - NA_;
        g_eps_e[j] = partitionable_normal(e0, e1, (unsigned)j);
    } else if (i < NA_ + 2 * NE_) {
        int j = i - NA_ - NE_;
        g_eps_t[j] = partitionable_normal(t0, t1, (unsigned)j);
    }
}

// generic: dst bf16 [R][ldd] (k-pad zeroed), src f32 [R][lds] cols 0..C-1
__global__ void convbf_k(const float* __restrict__ src, int lds,
                         __nv_bfloat16* __restrict__ dst, int ldd, int R, int C) {
    long idx = (long)blockIdx.x * blockDim.x + threadIdx.x;
    long total = (long)R * ldd;
    if (idx >= total) return;
    int r = (int)(idx / ldd), c = (int)(idx % ldd);
    float v = (c < C) ? src[(long)r * lds + c] : 0.f;
    dst[idx] = __float2bfloat16(v);
}

// transpose fp32 [R][C] -> bf16: dst[n][k] = src[k][n]
__global__ void transpose_bf_k(const float* __restrict__ src,
                               __nv_bfloat16* __restrict__ dst,
                               int R, int C, int ldd) {
    __shared__ float tile[32][33];
    int c0 = blockIdx.x * 32, r0 = blockIdx.y * 32;
#pragma unroll
    for (int i = 0; i < 4; i++) {
        int r = r0 + threadIdx.y + i * 8;
        int c = c0 + threadIdx.x;
        tile[threadIdx.y + i * 8][threadIdx.x] = (r < R && c < C) ? src[(long)r * C + c] : 0.f;
    }
    __syncthreads();
#pragma unroll
    for (int i = 0; i < 4; i++) {
        int orow = c0 + threadIdx.y + i * 8;   // = original col
        int ocol = r0 + threadIdx.x;           // = original row
        if (orow < C)
            dst[(long)orow * ldd + ocol] = __float2bfloat16(tile[threadIdx.x][threadIdx.y + i * 8]);
    }
}

__global__ void prep_lstm_k(const float* __restrict__ Wih, const float* __restrict__ Whh,
                            const float* __restrict__ bih, const float* __restrict__ bhh) {
    int idx = blockIdx.x * blockDim.x + threadIdx.x;
    if (idx < 4 * HE_ * HE_) {
        int row = idx / HE_, k = idx % HE_;
        int j = row >> 2, gate = row & 3;
        g_wih_int[idx] = Wih[((long)(gate * HE_ + j)) * HE_ + k];
        g_whh_int[idx] = Whh[((long)(gate * HE_ + j)) * HE_ + k];
    } else if (idx < 4 * HE_ * HE_ + 4 * HE_) {
        int r = idx - 4 * HE_ * HE_;
        int j = r >> 2, gate = r & 3;
        g_bi_int[r] = bih[gate * HE_ + j] + bhh[gate * HE_ + j];
    }
}

__global__ void prep_wml_k(const float* __restrict__ mutW, const float* __restrict__ mutb,
                           const float* __restrict__ lstW, const float* __restrict__ lstb) {
    int idx = blockIdx.x * blockDim.x + threadIdx.x;
    if (idx < 128 * HT_) {
        int row = idx / HT_, k = idx % HT_;
        float v = 0.f;
        if (row < 50) v = mutW[(long)row * HT_ + k];
        else if (row < 100) v = lstW[(long)(row - 50) * HT_ + k];
        g_wml_bf[idx] = __float2bfloat16(v);
    } else if (idx < 128 * HT_ + 128) {
        int r = idx - 128 * HT_;
        g_wmlb[r] = (r < 50) ? mutb[r] : (r < 100 ? lstb[r - 50] : 0.f);
    }
}

__global__ void alphas_kernel(const float* __restrict__ muq, const float* __restrict__ lsq) {
    int idx = blockIdx.x * blockDim.x + threadIdx.x;
    if (idx >= NA_) return;
    int t = idx / (K_ * RHO_), rem = idx % (K_ * RHO_);
    int k = rem / RHO_, r = rem % RHO_;
    int src = (k * T_ + t) * RHO_ + r;
    float a = muq[src] + g_eps_a[idx] * expf(0.5f * lsq[src]);
    g_alphas[idx] = a;
    int row = t * K_ + k;
    g_alphas_bf[(long)row * KP_RHO + r] = __float2bfloat16(a);
}

__global__ void kld_alpha_kernel(const float* __restrict__ muq, const float* __restrict__ lsq) {
    __shared__ float red[256];
    float acc = 0.f;
    for (int idx = blockIdx.x * blockDim.x + threadIdx.x; idx < NA_;
         idx += gridDim.x * blockDim.x) {
        int t = idx / (K_ * RHO_), rem = idx % (K_ * RHO_);
        int k = rem / RHO_, r = rem % RHO_;
        int src = (k * T_ + t) * RHO_ + r;
        float mu = muq[src];
        float ls = lsq[src];
        float qls = fminf(fmaxf(ls, -100.f), 100.f);
        float pmu = (t == 0) ? 0.f : g_alphas[idx - K_ * RHO_];
        float pls = (t == 0) ? 0.f : LOGD;
        float d = mu - pmu;
        acc += (expf(qls) + d * d) / (expf(pls) + 1e-6f) - 1.f + pls - qls;
    }
    float s = block_sum(acc, red);
    if (threadIdx.x == 0) g_part_a[blockIdx.x] = s;
}

// softmax over rows of g_beta, also writes bf16 copy
__global__ void softmax_rows_kernel() {
    __shared__ float red[256];
    long base = (long)blockIdx.x * V_;
    long basebf = (long)blockIdx.x * KP_V;
    int tid = threadIdx.x;
    float m = -FLT_MAX;
    for (int c = tid; c < V_; c += 256) m = fmaxf(m, g_beta[base + c]);
    m = block_max(m, red);
    float s = 0.f;
    for (int c = tid; c < V_; c += 256) {
        float e = expf(g_beta[base + c] - m);
        g_beta[base + c] = e; s += e;
    }
    s = block_sum(s, red);
    float inv = 1.f / s;
    for (int c = tid; c < V_; c += 256) {
        float b = g_beta[base + c] * inv;
        g_beta[base + c] = b;
        g_beta_bf[basebf + c] = __float2bfloat16(b);
    }
}

// fused LSTM step: gates = gx_t + h_in @ Whh_int^T, then cell update
__global__ void lstm_step_k(const float* __restrict__ hin, float* __restrict__ hout, int t) {
    __shared__ float As[16][65];
    __shared__ float Bs[16][65];
    __shared__ float gsm[64][68];
    const int Kd = HE_;
    int tid = threadIdx.x;
    int tx = tid & 15, ty = tid >> 4;
    int m0 = blockIdx.y * 64, n0 = blockIdx.x * 64;
    float acc[4][4] = {};
    for (int k0 = 0; k0 < Kd; k0 += 16) {
#pragma unroll
        for (int i = 0; i < 4; i++) {
            int e = tid + i * 256;
            int m = e >> 4, kk = e & 15;
            As[kk][m] = hin[(long)(m0 + m) * HE_ + k0 + kk];
        }
#pragma unroll
        for (int i = 0; i < 4; i++) {
            int e = tid + i * 256;
            int n = e >> 4, kk = e & 15;
            Bs[kk][n] = g_whh_int[(long)(n0 + n) * HE_ + k0 + kk];
        }
        __syncthreads();
#pragma unroll
        for (int kk = 0; kk < 16; kk++) {
            float a[4], b[4];
#pragma unroll
            for (int i = 0; i < 4; i++) a[i] = As[kk][ty + 16 * i];
#pragma unroll
            for (int j = 0; j < 4; j++) b[j] = Bs[kk][tx + 16 * j];
#pragma unroll
            for (int i = 0; i < 4; i++)
#pragma unroll
                for (int j = 0; j < 4; j++)
                    acc[i][j] = fmaf(a[i], b[j], acc[i][j]);
        }
        __syncthreads();
    }
#pragma unroll
    for (int i = 0; i < 4; i++) {
        int b = m0 + ty + 16 * i;
#pragma unroll
        for (int j = 0; j < 4; j++) {
            int n = n0 + tx + 16 * j;
            gsm[ty + 16 * i][tx + 16 * j] = acc[i][j] + g_gx[((long)b * T_ + t) * (4 * HE_) + n];
        }
    }
    __syncthreads();
#pragma unroll
    for (int q = 0; q < 4; q++) {
        int idx = tid + q * 256;     // 1024 = 64 b x 16 j
        int bl = idx >> 4, jl = idx & 15;
        float gi = gsm[bl][4 * jl];
        float gf = gsm[bl][4 * jl + 1];
        float gg = gsm[bl][4 * jl + 2];
        float go = gsm[bl][4 * jl + 3];
        int b = m0 + bl;
        int j = blockIdx.x * 16 + jl;
        float si = 1.f / (1.f + expf(-gi));
        float sf = 1.f / (1.f + expf(-gf));
        float so = 1.f / (1.f + expf(-go));
        float c = sf * g_cstate[b * HE_ + j] + si * tanhf(gg);
        float h = so * tanhf(c);
        g_cstate[b * HE_ + j] = c;
        hout[b * HE_ + j] = h;
        g_lstm[((long)t * B_ + b) * HE_ + j] = h;
    }
}

__global__ void eta_step_kernel(const float* __restrict__ mueW, const float* __restrict__ mueb,
                                const float* __restrict__ lseW, const float* __restrict__ lseb,
                                int t) {
    __shared__ float z[HEK_];
    __shared__ float red[64];
    int b = blockIdx.x, tid = threadIdx.x;
    for (int c = tid; c < HE_; c += 64) z[c] = g_lstm[((long)t * B_ + b) * HE_ + c];
    for (int c = tid; c < K_; c += 64) z[HE_ + c] = g_eta_prev[b * K_ + c];
    __syncthreads();
    float kl = 0.f, eta = 0.f;
    if (tid < K_) {
        const float* wm = mueW + tid * HEK_;
        const float* wl = lseW + tid * HEK_;
        float mu = mueb[tid], ls = lseb[tid];
#pragma unroll 2
        for (int c = 0; c < HEK_; c++) {
            float zc = z[c];
            mu = fmaf(zc, wm[c], mu);
            ls = fmaf(zc, wl[c], ls);
        }
        float eps = g_eps_e[((long)t * B_ + b) * K_ + tid];
        eta = mu + eps * expf(0.5f * ls);
        g_etas[((long)t * B_ + b) * K_ + tid] = eta;
        float qls = fminf(fmaxf(ls, -100.f), 100.f);
        float pmu = z[HE_ + tid];
        float pls = (t == 0) ? 0.f : LOGD;
        float d = mu - pmu;
        kl = (expf(qls) + d * d) / (expf(pls) + 1e-6f) - 1.f + pls - qls;
    }
    float s = block_sum((tid < K_) ? kl : 0.f, red);
    if (tid == 0) g_part_ke[t * B_ + b] = s;
    if (tid < K_) g_eta_prev[b * K_ + tid] = eta;
}

// h1 = relu(h1e + h1b) -> bf16
__global__ void combine_h1_kernel() {
    int idx = blockIdx.x * blockDim.x + threadIdx.x;
    if (idx >= T_ * B_ * HT_) return;
    int row = idx / HT_, j = idx % HT_;
    int b = row % B_;
    float v = fmaxf(g_h1e[idx] + g_h1b[b * HT_ + j], 0.f);
    g_h1_bf[idx] = __float2bfloat16(v);
}

__global__ void theta_kernel() {
    __shared__ float red[64];
    int row = blockIdx.x, k = threadIdx.x;
    long base = (long)row * K_;
    long mbase = (long)row * 100;
    bool val = k < K_;
    float mu = 0.f, ls = 0.f, zv = -FLT_MAX;
    if (val) {
        mu = g_mls[mbase + k];
        ls = g_mls[mbase + 50 + k];
        zv = mu + g_eps_t[base + k] * expf(0.5f * ls);
    }
    float mx = block_max(zv, red);
    float e = val ? expf(zv - mx) : 0.f;
    float sum = block_sum(e, red);
    if (val) g_theta_arr[base + k] = e / sum;
    float kl = 0.f;
    if (val) {
        float qls = fminf(fmaxf(ls, -100.f), 100.f);
        float d = mu - g_etas[base + k];
        kl = (expf(qls) + d * d) / (1.f + 1e-6f) - 1.f - qls;
    }
    float s = block_sum(kl, red);
    if (k == 0) g_part_kt[row] = s;
}

__global__ void final_reduce_kernel(float* out, int out_size) {
    __shared__ float red[256];
    int tid = threadIdx.x;
    float v;
    v = 0.f; for (int i = tid; i < RB_NLL;  i += 256) v += g_part_nll[i];
    float nll  = block_sum(v, red) * (10.0f / B_);
    v = 0.f; for (int i = tid; i < T_ * B_; i += 256) v += g_part_kt[i];
    float kt   = block_sum(v, red) * (0.5f / (T_ * B_));
    v = 0.f; for (int i = tid; i < RB_A;    i += 256) v += g_part_a[i];
    float ka   = block_sum(v, red) * (0.5f / (T_ * K_));
    v = 0.f; for (int i = tid; i < T_ * B_; i += 256) v += g_part_ke[i];
    float ke   = block_sum(v, red) * (0.5f / B_);
    v = 0.f; for (int i = tid; i < RB_COND; i += 256) v += g_part_cond[i];
    float cond = block_sum(v, red) * (-0.01f);
    if (tid == 0) {
        if (out_size > 0) out[0] = nll;
        if (out_size > 1) out[1] = kt;
        if (out_size > 2) out[2] = ka;
        if (out_size > 3) out[3] = ke;
        if (out_size > 4) out[4] = cond;
    }
}

// ---------------- host driver ----------------
static inline int ceil_div(long a, long b) { return (int)((a + b - 1) / b); }

extern "C" void kernel_launch(void* const* d_in, const int* in_sizes, int n_in,
                              void* d_out, int out_size) {
    (void)in_sizes; (void)n_in;
    const float* nb   = (const float*)d_in[0];
    const float* bow  = (const float*)d_in[1];
    const float* adj  = (const float*)d_in[2];
    const float* muqa = (const float*)d_in[3];
    const float* lsqa = (const float*)d_in[4];
    const float* rhoW = (const float*)d_in[5];
    const float* rhob = (const float*)d_in[6];
    const float* W1   = (const float*)d_in[7];
    const float* b1   = (const float*)d_in[8];
    const float* W2   = (const float*)d_in[9];
    const float* b2   = (const float*)d_in[10];
    const float* mutW = (const float*)d_in[11];
    const float* mutb = (const float*)d_in[12];
    const float* lstW = (const float*)d_in[13];
    const float* lstb = (const float*)d_in[14];
    const float* qeW  = (const float*)d_in[15];
    const float* qeb  = (const float*)d_in[16];
    const float* Wih  = (const float*)d_in[17];
    const float* Whh  = (const float*)d_in[18];
    const float* bih  = (const float*)d_in[19];
    const float* bhh  = (const float*)d_in[20];
    const float* mueW = (const float*)d_in[21];
    const float* mueb = (const float*)d_in[22];
    const float* lseW = (const float*)d_in[23];
    const float* lseb = (const float*)d_in[24];
    float* out = (float*)d_out;

    // JAX partitionable threefry: split(key(42), 3) -> key_i = tf((0,42), 0, i)
    unsigned ka0, ka1, ke0, ke1, kt0, kt1;
    tf2x32(0u, 42u, 0u, 0u, &ka0, &ka1);
    tf2x32(0u, 42u, 0u, 1u, &ke0, &ke1);
    tf2x32(0u, 42u, 0u, 2u, &kt0, &kt1);

    // device symbol addresses
    float *p_beta, *p_inp, *p_gx, *p_hb0, *p_hb1, *p_etas, *p_h1e, *p_h1b, *p_mls;
    float *p_wih_int, *p_bi_int, *p_part_cond, *p_wmlb;
    __nv_bfloat16 *p_alphas_bf, *p_beta_bf, *p_adjT, *p_bow_bf, *p_qew_bf, *p_nb_bf;
    __nv_bfloat16 *p_w1_bf, *p_rhow_bf, *p_w2_bf, *p_wml_bf, *p_h1_bf, *p_h2_bf;
    cudaGetSymbolAddress((void**)&p_beta,      g_beta);
    cudaGetSymbolAddress((void**)&p_inp,       g_inp);
    cudaGetSymbolAddress((void**)&p_gx,        g_gx);
    cudaGetSymbolAddress((void**)&p_hb0,       g_hbuf);
    p_hb1 = p_hb0 + B_ * HE_;
    cudaGetSymbolAddress((void**)&p_etas,      g_etas);
    cudaGetSymbolAddress((void**)&p_h1e,       g_h1e);
    cudaGetSymbolAddress((void**)&p_h1b,       g_h1b);
    cudaGetSymbolAddress((void**)&p_mls,       g_mls);
    cudaGetSymbolAddress((void**)&p_wih_int,   g_wih_int);
    cudaGetSymbolAddress((void**)&p_bi_int,    g_bi_int);
    cudaGetSymbolAddress((void**)&p_part_cond, g_part_cond);
    cudaGetSymbolAddress((void**)&p_wmlb,      g_wmlb);
    cudaGetSymbolAddress((void**)&p_alphas_bf, g_alphas_bf);
    cudaGetSymbolAddress((void**)&p_beta_bf,   g_beta_bf);
    cudaGetSymbolAddress((void**)&p_adjT,      g_adjT_bf);
    cudaGetSymbolAddress((void**)&p_bow_bf,    g_bow_bf);
    cudaGetSymbolAddress((void**)&p_qew_bf,    g_qew_bf);
    cudaGetSymbolAddress((void**)&p_nb_bf,     g_nb_bf);
    cudaGetSymbolAddress((void**)&p_w1_bf,     g_w1_bf);
    cudaGetSymbolAddress((void**)&p_rhow_bf,   g_rhow_bf);
    cudaGetSymbolAddress((void**)&p_w2_bf,     g_w2_bf);
    cudaGetSymbolAddress((void**)&p_wml_bf,    g_wml_bf);
    cudaGetSymbolAddress((void**)&p_h1_bf,     g_h1_bf);
    cudaGetSymbolAddress((void**)&p_h2_bf,     g_h2_bf);

    // 1. state init
    init_zero_kernel<<<(B_ * HE_ + B_ * K_ + 255) / 256, 256>>>();

    // 2. RNG
    int totalElems = NA_ + 2 * NE_;
    eps_kernel<<<(totalElems + 255) / 256, 256>>>(ka0, ka1, ke0, ke1, kt0, kt1);

    // 3. weight / input conversions
    transpose_bf_k<<<dim3(ceil_div(V_, 32), ceil_div(V_, 32)), dim3(32, 8)>>>(adj, p_adjT, V_, V_, KP_V);
    convbf_k<<<ceil_div((long)B_ * T_ * KP_V, 256), 256>>>(bow, V_, p_bow_bf, KP_V, B_ * T_, V_);
    convbf_k<<<ceil_div((long)HE_ * KP_V, 256), 256>>>(qeW, V_, p_qew_bf, KP_V, HE_, V_);
    convbf_k<<<ceil_div((long)B_ * KP_V, 256), 256>>>(nb, V_, p_nb_bf, KP_V, B_, V_);
    convbf_k<<<ceil_div((long)HT_ * KP_V, 256), 256>>>(W1, VK_, p_w1_bf, KP_V, HT_, V_);
    convbf_k<<<ceil_div((long)V_ * KP_RHO, 256), 256>>>(rhoW, RHO_, p_rhow_bf, KP_RHO, V_, RHO_);
    convbf_k<<<ceil_div((long)HT_ * HT_, 256), 256>>>(W2, HT_, p_w2_bf, HT_, HT_, HT_);
    prep_lstm_k<<<(4 * HE_ * HE_ + 4 * HE_ + 255) / 256, 256>>>(Wih, Whh, bih, bhh);
    prep_wml_k<<<(128 * HT_ + 128 + 255) / 256, 256>>>(mutW, mutb, lstW, lstb);

    // 4. alphas (+bf16) + KL(alpha)
    alphas_kernel<<<(NA_ + 255) / 256, 256>>>(muqa, lsqa);
    kld_alpha_kernel<<<RB_A, 256>>>(muqa, lsqa);

    // 5. beta logits (TC) -> softmax (+bf16)
    tc_gemm_k<true, false, false, false><<<dim3(ceil_div(V_, 128), ceil_div(T_ * K_, 128)), 256>>>(
        p_alphas_bf, KP_RHO, p_rhow_bf, KP_RHO, rhob, p_beta, nullptr, V_,
        nullptr, nullptr, T_ * K_, V_, KP_RHO);
    softmax_rows_kernel<<<T_ * K_, 256>>>();

    // 6. cond: beta_bf @ adjT (TC, fused trace epilogue)
    tc_gemm_k<false, false, false, true><<<dim3(ceil_div(V_, 128), ceil_div(T_ * K_, 128)), 256>>>(
        p_beta_bf, KP_V, p_adjT, KP_V, nullptr, nullptr, nullptr, V_,
        p_beta, p_part_cond, T_ * K_, V_, KP_V);

    // 7. inp = bow @ qeW^T + qeb (TC)
    tc_gemm_k<true, false, false, false><<<dim3(ceil_div(HE_, 128), ceil_div(B_ * T_, 128)), 256>>>(
        p_bow_bf, KP_V, p_qew_bf, KP_V, qeb, p_inp, nullptr, HE_,
        nullptr, nullptr, B_ * T_, HE_, KP_V);

    // 8. gates_x = inp @ Wih_int^T + bi_int (fp32), then fused LSTM steps
    gemm_k<false><<<dim3(16, 48), 256>>>(
        p_inp, HE_, p_wih_int, HE_, p_bi_int, p_gx, 4 * HE_, B_ * T_, 4 * HE_, HE_);
    for (int t = 0; t < T_; t++) {
        float* hin  = (t & 1) ? p_hb1 : p_hb0;
        float* hout = (t & 1) ? p_hb0 : p_hb1;
        lstm_step_k<<<dim3(16, 4), 256>>>(hin, hout, t);
    }

    // 9. eta recurrence
    for (int t = 0; t < T_; t++)
        eta_step_kernel<<<B_, 64>>>(mueW, mueb, lseW, lseb, t);

    // 10. theta encoder
    gemm_k<false><<<dim3(13, 48), 256>>>(
        p_etas, K_, W1 + V_, VK_, b1, p_h1e, HT_, T_ * B_, HT_, K_);
    tc_gemm_k<false, false, false, false><<<dim3(ceil_div(HT_, 128), ceil_div(B_, 128)), 256>>>(
        p_nb_bf, KP_V, p_w1_bf, KP_V, nullptr, p_h1b, nullptr, HT_,
        nullptr, nullptr, B_, HT_, KP_V);
    combine_h1_kernel<<<(T_ * B_ * HT_ + 255) / 256, 256>>>();
    tc_gemm_k<true, true, true, false><<<dim3(ceil_div(HT_, 128), ceil_div(T_ * B_, 128)), 256>>>(
        p_h1_bf, HT_, p_w2_bf, HT_, b2, nullptr, p_h2_bf, HT_,
        nullptr, nullptr, T_ * B_, HT_, HT_);
    tc_gemm_k<true, false, false, false><<<dim3(1, ceil_div(T_ * B_, 128)), 256>>>(
        p_h2_bf, HT_, p_wml_bf, HT_, p_wmlb, p_mls, nullptr, 100,
        nullptr, nullptr, T_ * B_, 100, HT_);

    // 11. theta softmax + KL(theta)
    theta_kernel<<<T_ * B_, 64>>>();

    // 12. decode GEMM fused with NLL (fp32 — keeps log() precision)
    gemm_nll_k<<<dim3(79, 4, 12), 256>>>(bow);

    // 13. final scalars
    final_reduce_kernel<<<1, 256>>>(out, out_size);
}

// round 10
// speedup vs baseline: 2.2042x; 1.2886x over previous
#include <cuda_runtime.h>
#include <cuda_bf16.h>
#include <cstdint>
#include <float.h>
#include <math.h>

// ---------------- problem constants ----------------
#define T_    12
#define K_    50
#define V_    5000
#define B_    256
#define RHO_  300
#define HT_   800
#define HE_   256
#define VK_   (V_ + K_)
#define HEK_  (HE_ + K_)
#define LOGD  (-5.2983173665480363f)

#define NA_   (T_*K_*RHO_)
#define NE_   (T_*B_*K_)

// padded dims (rows -> mult of 128 where used as TC operand rows, K -> mult of 32)
#define KP_V   5024
#define KP_RHO 320
#define NP_V   5120
#define MP_TK  640
#define NP_HT  896

#define INP_SPLIT 4
#define H1B_SPLIT 8

// ---------------- device scratch ----------------
__device__ float g_eps_a[NA_];
__device__ float g_eps_e[NE_];
__device__ float g_eps_t[NE_];
__device__ float g_alphas[NA_];
__device__ __align__(16) __nv_bfloat16 g_alphas_bf[MP_TK*KP_RHO];
__device__ float g_beta[T_*K_*V_];
__device__ __align__(16) __nv_bfloat16 g_beta_bf[MP_TK*KP_V];
__device__ __align__(16) __nv_bfloat16 g_betaT_bf[T_*NP_V*64];
__device__ __align__(16) __nv_bfloat16 g_adjT_bf[NP_V*KP_V];
__device__ __align__(16) __nv_bfloat16 g_bow_bf[B_*T_*KP_V];
__device__ __align__(16) __nv_bfloat16 g_qew_bf[HE_*KP_V];
__device__ __align__(16) __nv_bfloat16 g_nb_bf[B_*KP_V];
__device__ __align__(16) __nv_bfloat16 g_w1_bf[NP_HT*KP_V];
__device__ __align__(16) __nv_bfloat16 g_rhow_bf[NP_V*KP_RHO];
__device__ __align__(16) __nv_bfloat16 g_w2_bf[NP_HT*HT_];
__device__ __align__(16) __nv_bfloat16 g_wml_bf[128*HT_];
__device__ __align__(16) __nv_bfloat16 g_theta_bf[T_*B_*64];
__device__ float g_wmlb[128];
__device__ float g_wih_int[4*HE_*HE_];
__device__ float g_whh_int[4*HE_*HE_];
__device__ float g_bi_int[4*HE_];
__device__ float g_inp[B_*T_*HE_];
__device__ float g_inp_part[INP_SPLIT*B_*T_*HE_];
__device__ float g_gx[B_*T_*4*HE_];
__device__ float g_hbuf[2][B_*HE_];
__device__ float g_cstate[B_*HE_];
__device__ float g_lstm[T_*B_*HE_];
__device__ float g_eta_prev[B_*K_];
__device__ float g_etas[NE_];
__device__ float g_h1e[T_*B_*HT_];
__device__ float g_h1b_part[H1B_SPLIT*B_*HT_];
__device__ __align__(16) __nv_bfloat16 g_h1_bf[T_*B_*HT_];
__device__ __align__(16) __nv_bfloat16 g_h2_bf[T_*B_*HT_];
__device__ float g_mls[T_*B_*100];
__device__ float g_theta_arr[NE_];

#define RB_NLL  (12*2*40)   // 960
#define RB_COND 200
#define RB_A    256
__device__ float g_part_nll[RB_NLL];
__device__ float g_part_cond[RB_COND];
__device__ float g_part_a[RB_A];
__device__ float g_part_kt[T_*B_];
__device__ float g_part_ke[T_*B_];

// ---------------- threefry2x32 (JAX partitionable) ----------------
__host__ __device__ inline void tf2x32(unsigned k0, unsigned k1,
                                       unsigned x0, unsigned x1,
                                       unsigned* o0, unsigned* o1) {
    unsigned ks0 = k0, ks1 = k1, ks2 = k0 ^ k1 ^ 0x1BD11BDAu;
    x0 += ks0; x1 += ks1;
#define TF_R(r) { x0 += x1; x1 = (x1 << (r)) | (x1 >> (32 - (r))); x1 ^= x0; }
    TF_R(13) TF_R(15) TF_R(26) TF_R(6)
    x0 += ks1; x1 += ks2 + 1u;
    TF_R(17) TF_R(29) TF_R(16) TF_R(24)
    x0 += ks2; x1 += ks0 + 2u;
    TF_R(13) TF_R(15) TF_R(26) TF_R(6)
    x0 += ks0; x1 += ks1 + 3u;
    TF_R(17) TF_R(29) TF_R(16) TF_R(24)
    x0 += ks1; x1 += ks2 + 4u;
    TF_R(13) TF_R(15) TF_R(26) TF_R(6)
    x0 += ks2; x1 += ks0 + 5u;
#undef TF_R
    *o0 = x0; *o1 = x1;
}

__device__ __forceinline__ float bits2normal(unsigned bits) {
    float f = __uint_as_float((bits >> 9) | 0x3F800000u) - 1.0f;
    const float lo = -0.99999994f;
    float u = fmaf(f, 2.0f, lo);
    u = fmaxf(lo, u);
    return 1.4142135381698608f * erfinvf(u);
}

__device__ __forceinline__ float partitionable_normal(unsigned k0, unsigned k1, unsigned i) {
    unsigned o0, o1;
    tf2x32(k0, k1, 0u, i, &o0, &o1);
    return bits2normal(o0 ^ o1);
}

// ---------------- block reductions ----------------
__device__ __forceinline__ float block_sum(float v, float* red) {
    int tid = threadIdx.x, n = blockDim.x;
    red[tid] = v; __syncthreads();
    for (int s = n >> 1; s > 0; s >>= 1) {
        if (tid < s) red[tid] += red[tid + s];
        __syncthreads();
    }
    v = red[0]; __syncthreads();
    return v;
}
__device__ __forceinline__ float block_max(float v, float* red) {
    int tid = threadIdx.x, n = blockDim.x;
    red[tid] = v; __syncthreads();
    for (int s = n >> 1; s > 0; s >>= 1) {
        if (tid < s) red[tid] = fmaxf(red[tid], red[tid + s]);
        __syncthreads();
    }
    v = red[0]; __syncthreads();
    return v;
}

// ---------------- mma helper ----------------
__device__ __forceinline__ void mma16816(float* c, const uint32_t* a, uint32_t b0, uint32_t b1) {
    asm volatile(
        "mma.sync.aligned.m16n8k16.row.col.f32.bf16.bf16.f32 "
        "{%0,%1,%2,%3}, {%4,%5,%6,%7}, {%8,%9}, {%0,%1,%2,%3};\n"
        : "+f"(c[0]), "+f"(c[1]), "+f"(c[2]), "+f"(c[3])
        : "r"(a[0]), "r"(a[1]), "r"(a[2]), "r"(a[3]), "r"(b0), "r"(b1));
}

#define CPASYNC16(sp, gp) \
    asm volatile("cp.async.cg.shared.global [%0], [%1], 16;\n" \
        :: "r"((unsigned)__cvta_generic_to_shared(sp)), "l"(gp))
#define CPCOMMIT() asm volatile("cp.async.commit_group;\n")
#define CPWAIT(n)  asm volatile("cp.async.wait_group %0;\n" :: "n"(n))

#define TC_SMEM_BYTES (2 * 3 * 128 * 40 * 2)

// ---------------- pipelined bf16 TC GEMM (NT): C = A[M,Kp] * B[N,Kp]^T ----------------
// 3-stage cp.async pipeline. Split-K via gridDim.z (output z-partials, no bias on split).
template<bool BIAS, bool RELU, bool OUTBF, bool CONDEPI>
__global__ void __launch_bounds__(256) tc_gemm_k(
    const __nv_bfloat16* __restrict__ A, int lda,
    const __nv_bfloat16* __restrict__ B, int ldb,
    const float* __restrict__ bias,
    float* __restrict__ C, __nv_bfloat16* __restrict__ Cbf, int ldc,
    const float* __restrict__ Cf, float* __restrict__ part,
    int M, int N, int Kp) {
    extern __shared__ __nv_bfloat16 smp[];
    __nv_bfloat16* As = smp;                  // [3][128][40]
    __nv_bfloat16* Bs = smp + 3 * 128 * 40;
    __shared__ float red[256];
    int tid = threadIdx.x;
    int lane = tid & 31, wid = tid >> 5;
    int wm = wid & 3, wn = wid >> 2;
    int g = lane >> 2, t4 = lane & 3;
    long m0 = (long)blockIdx.y * 128, n0 = (long)blockIdx.x * 128;
    int arow = tid >> 2;
    int akc = (tid & 3) * 8;
    float acc[2][8][4] = {};

    int nkt = Kp >> 5;
    int per = (nkt + gridDim.z - 1) / gridDim.z;
    int it0 = blockIdx.z * per;
    int itn = nkt - it0; if (itn > per) itn = per; if (itn < 0) itn = 0;

#define TC_ISSUE(IT, S) do {                                                     \
        int _k = ((IT) << 5) + akc;                                              \
        __nv_bfloat16* _as = As + (size_t)(S) * 128 * 40;                        \
        __nv_bfloat16* _bs = Bs + (size_t)(S) * 128 * 40;                        \
        CPASYNC16(&_as[(size_t)arow * 40 + akc],        &A[(m0 + arow) * (long)lda + _k]);        \
        CPASYNC16(&_as[(size_t)(arow + 64) * 40 + akc], &A[(m0 + arow + 64) * (long)lda + _k]);   \
        CPASYNC16(&_bs[(size_t)arow * 40 + akc],        &B[(n0 + arow) * (long)ldb + _k]);        \
        CPASYNC16(&_bs[(size_t)(arow + 64) * 40 + akc], &B[(n0 + arow + 64) * (long)ldb + _k]);   \
        CPCOMMIT();                                                              \
    } while (0)

    if (itn > 0) TC_ISSUE(it0, 0);
    if (itn > 1) TC_ISSUE(it0 + 1, 1);

    for (int ii = 0; ii < itn; ii++) {
        if (ii + 1 < itn) { CPWAIT(1); } else { CPWAIT(0); }
        __syncthreads();
        if (ii + 2 < itn) TC_ISSUE(it0 + ii + 2, (ii + 2) % 3);
        const __nv_bfloat16* Asb = As + (size_t)(ii % 3) * 128 * 40;
        const __nv_bfloat16* Bsb = Bs + (size_t)(ii % 3) * 128 * 40;
#pragma unroll
        for (int ks = 0; ks < 32; ks += 16) {
            uint32_t a[2][4];
#pragma unroll
            for (int i = 0; i < 2; i++) {
                int r = wm * 32 + i * 16 + g;
                a[i][0] = *(const uint32_t*)&Asb[(size_t)r * 40 + ks + 2 * t4];
                a[i][1] = *(const uint32_t*)&Asb[(size_t)(r + 8) * 40 + ks + 2 * t4];
                a[i][2] = *(const uint32_t*)&Asb[(size_t)r * 40 + ks + 2 * t4 + 8];
                a[i][3] = *(const uint32_t*)&Asb[(size_t)(r + 8) * 40 + ks + 2 * t4 + 8];
            }
#pragma unroll
            for (int j = 0; j < 8; j++) {
                int n = wn * 64 + j * 8 + g;
                uint32_t b0 = *(const uint32_t*)&Bsb[(size_t)n * 40 + ks + 2 * t4];
                uint32_t b1 = *(const uint32_t*)&Bsb[(size_t)n * 40 + ks + 2 * t4 + 8];
#pragma unroll
                for (int i = 0; i < 2; i++)
                    mma16816(acc[i][j], a[i], b0, b1);
            }
        }
        __syncthreads();
    }
#undef TC_ISSUE

    if (CONDEPI) {
        float local = 0.f;
#pragma unroll
        for (int i = 0; i < 2; i++) {
#pragma unroll
            for (int j = 0; j < 8; j++) {
                long m = m0 + wm * 32 + i * 16 + g;
                long n = n0 + wn * 64 + j * 8 + 2 * t4;
                if (m < M) {
                    if (n < N)     local += acc[i][j][0] * Cf[m * ldc + n];
                    if (n + 1 < N) local += acc[i][j][1] * Cf[m * ldc + n + 1];
                }
                if (m + 8 < M) {
                    if (n < N)     local += acc[i][j][2] * Cf[(m + 8) * ldc + n];
                    if (n + 1 < N) local += acc[i][j][3] * Cf[(m + 8) * ldc + n + 1];
                }
            }
        }
        float s = block_sum(local, red);
        if (tid == 0) part[blockIdx.y * gridDim.x + blockIdx.x] = s;
    } else {
        float* Cz = C ? C + (long)blockIdx.z * M * ldc : nullptr;
#pragma unroll
        for (int i = 0; i < 2; i++) {
#pragma unroll
            for (int j = 0; j < 8; j++) {
                long m = m0 + wm * 32 + i * 16 + g;
                long n = n0 + wn * 64 + j * 8 + 2 * t4;
#pragma unroll
                for (int q = 0; q < 4; q++) {
                    long mm = m + (q >> 1) * 8;
                    long nn = n + (q & 1);
                    if (mm < M && nn < N) {
                        float v = acc[i][j][q];
                        if (BIAS) v += bias[nn];
                        if (RELU) v = fmaxf(v, 0.f);
                        if (OUTBF) Cbf[mm * ldc + nn] = __float2bfloat16(v);
                        else       Cz[mm * ldc + nn] = v;
                    }
                }
            }
        }
    }
}

// ---------------- TC NLL: lik = theta_t @ betaT_t, epilogue -log(lik+1e-6)*bow ----------------
// grid (40, 2, 12). Kp=64 (2 k-iters), M=256, N=5000.
__global__ void __launch_bounds__(256) tc_nll_k(const float* __restrict__ bow) {
    __shared__ __nv_bfloat16 As[128][40];
    __shared__ __nv_bfloat16 Bs[128][40];
    __shared__ float red[256];
    int t = blockIdx.z;
    const __nv_bfloat16* A = g_theta_bf + (long)t * B_ * 64;
    const __nv_bfloat16* B = g_betaT_bf + (long)t * NP_V * 64;
    int tid = threadIdx.x;
    int lane = tid & 31, wid = tid >> 5;
    int wm = wid & 3, wn = wid >> 2;
    int g = lane >> 2, t4 = lane & 3;
    long m0 = (long)blockIdx.y * 128, n0 = (long)blockIdx.x * 128;
    int arow = tid >> 2;
    int akc = (tid & 3) * 8;
    float acc[2][8][4] = {};
    for (int k0 = 0; k0 < 64; k0 += 32) {
#pragma unroll
        for (int h = 0; h < 2; h++) {
            int r = arow + h * 64;
            *(uint4*)&As[r][akc] = *(const uint4*)&A[(m0 + r) * 64 + k0 + akc];
            *(uint4*)&Bs[r][akc] = *(const uint4*)&B[(n0 + r) * 64 + k0 + akc];
        }
        __syncthreads();
#pragma unroll
        for (int ks = 0; ks < 32; ks += 16) {
            uint32_t a[2][4];
#pragma unroll
            for (int i = 0; i < 2; i++) {
                int r = wm * 32 + i * 16 + g;
                a[i][0] = *(const uint32_t*)&As[r][ks + 2 * t4];
                a[i][1] = *(const uint32_t*)&As[r + 8][ks + 2 * t4];
                a[i][2] = *(const uint32_t*)&As[r][ks + 2 * t4 + 8];
                a[i][3] = *(const uint32_t*)&As[r + 8][ks + 2 * t4 + 8];
            }
#pragma unroll
            for (int j = 0; j < 8; j++) {
                int n = wn * 64 + j * 8 + g;
                uint32_t b0 = *(const uint32_t*)&Bs[n][ks + 2 * t4];
                uint32_t b1 = *(const uint32_t*)&Bs[n][ks + 2 * t4 + 8];
#pragma unroll
                for (int i = 0; i < 2; i++)
                    mma16816(acc[i][j], a[i], b0, b1);
            }
        }
        __syncthreads();
    }
    float local = 0.f;
#pragma unroll
    for (int i = 0; i < 2; i++) {
#pragma unroll
        for (int j = 0; j < 8; j++) {
            long m = m0 + wm * 32 + i * 16 + g;      // batch b (<256 always)
            long n = n0 + wn * 64 + j * 8 + 2 * t4;  // vocab v
#pragma unroll
            for (int q = 0; q < 4; q++) {
                long bb = m + (q >> 1) * 8;
                long vv = n + (q & 1);
                if (vv < V_) {
                    float w = bow[(bb * T_ + t) * (long)V_ + vv];
                    local += -logf(acc[i][j][q] + 1e-6f) * w;
                }
            }
        }
    }
    float s = block_sum(local, red);
    if (tid == 0)
        g_part_nll[(blockIdx.z * 2 + blockIdx.y) * 40 + blockIdx.x] = s;
}

// ---------------- generic tiled fp32 GEMM (NT) ----------------
template<bool RELU>
__global__ void gemm_k(const float* __restrict__ A, int lda,
                       const float* __restrict__ Bm, int ldb,
                       const float* __restrict__ bias,
                       float* __restrict__ C, int ldc,
                       int M, int N, int Kd) {
    __shared__ float As[16][65];
    __shared__ float Bs[16][65];
    int tid = threadIdx.x;
    int tx = tid & 15, ty = tid >> 4;
    int m0 = blockIdx.y * 64, n0 = blockIdx.x * 64;
    float acc[4][4] = {};
    for (int k0 = 0; k0 < Kd; k0 += 16) {
#pragma unroll
        for (int i = 0; i < 4; i++) {
            int e = tid + i * 256;
            int m = e >> 4, kk = e & 15;
            int gm = m0 + m, gk = k0 + kk;
            float v = 0.f;
            if (gm < M && gk < Kd) v = A[(long)gm * lda + gk];
            As[kk][m] = v;
        }
#pragma unroll
        for (int i = 0; i < 4; i++) {
            int e = tid + i * 256;
            int n = e >> 4, kk = e & 15;
            int gn = n0 + n, gk = k0 + kk;
            float v = 0.f;
            if (gn < N && gk < Kd) v = Bm[(long)gn * ldb + gk];
            Bs[kk][n] = v;
        }
        __syncthreads();
#pragma unroll
        for (int kk = 0; kk < 16; kk++) {
            float a[4], b[4];
#pragma unroll
            for (int i = 0; i < 4; i++) a[i] = As[kk][ty + 16 * i];
#pragma unroll
            for (int j = 0; j < 4; j++) b[j] = Bs[kk][tx + 16 * j];
#pragma unroll
            for (int i = 0; i < 4; i++)
#pragma unroll
                for (int j = 0; j < 4; j++)
                    acc[i][j] = fmaf(a[i], b[j], acc[i][j]);
        }
        __syncthreads();
    }
#pragma unroll
    for (int i = 0; i < 4; i++) {
        int m = m0 + ty + 16 * i;
        if (m >= M) continue;
#pragma unroll
        for (int j = 0; j < 4; j++) {
            int n = n0 + tx + 16 * j;
            if (n >= N) continue;
            float v = acc[i][j];
            if (bias) v += bias[n];
            if (RELU) v = fmaxf(v, 0.f);
            C[(long)m * ldc + n] = v;
        }
    }
}

// ---------------- prep / conversion kernels ----------------
__global__ void init_zero_kernel() {
    int idx = blockIdx.x * blockDim.x + threadIdx.x;
    if (idx < B_ * HE_) { g_hbuf[0][idx] = 0.f; g_cstate[idx] = 0.f; }
    int j = idx - B_ * HE_;
    if (j >= 0 && j < B_ * K_) g_eta_prev[j] = 0.f;
}

__global__ void eps_kernel(unsigned a0, unsigned a1, unsigned e0, unsigned e1,
                           unsigned t0, unsigned t1) {
    int i = blockIdx.x * blockDim.x + threadIdx.x;
    if (i < NA_) {
        g_eps_a[i] = partitionable_normal(a0, a1, (unsigned)i);
    } else if (i < NA_ + NE_) {
        int j = i - NA_;
        g_eps_e[j] = partitionable_normal(e0, e1, (unsigned)j);
    } else if (i < NA_ + 2 * NE_) {
        int j = i - NA_ - NE_;
        g_eps_t[j] = partitionable_normal(t0, t1, (unsigned)j);
    }
}

// vectorized conversion: grid (ceil(ldd/8/256), R). Requires 16B-aligned src rows.
__global__ void convbf_vec_k(const float* __restrict__ src, int lds,
                             __nv_bfloat16* __restrict__ dst, int ldd, int C) {
    int c = (blockIdx.x * blockDim.x + threadIdx.x) * 8;
    if (c >= ldd) return;
    int r = blockIdx.y;
    const float* s = src + (long)r * lds;
    __nv_bfloat16 tmp[8];
    if (c + 8 <= C) {
        float4 a = *(const float4*)(s + c);
        float4 b = *(const float4*)(s + c + 4);
        tmp[0] = __float2bfloat16(a.x); tmp[1] = __float2bfloat16(a.y);
        tmp[2] = __float2bfloat16(a.z); tmp[3] = __float2bfloat16(a.w);
        tmp[4] = __float2bfloat16(b.x); tmp[5] = __float2bfloat16(b.y);
        tmp[6] = __float2bfloat16(b.z); tmp[7] = __float2bfloat16(b.w);
    } else {
#pragma unroll
        for (int j = 0; j < 8; j++) {
            int cc = c + j;
            tmp[j] = __float2bfloat16(cc < C ? s[cc] : 0.f);
        }
    }
    *(uint4*)&dst[(long)r * ldd + c] = *(uint4*)tmp;
}

// scalar row conversion (for unaligned src rows, e.g. W1 with lds=5050)
__global__ void convbf_row_k(const float* __restrict__ src, int lds,
                             __nv_bfloat16* __restrict__ dst, int ldd, int C) {
    int c = blockIdx.x * blockDim.x + threadIdx.x;
    if (c >= ldd) return;
    int r = blockIdx.y;
    float v = (c < C) ? src[(long)r * lds + c] : 0.f;
    dst[(long)r * ldd + c] = __float2bfloat16(v);
}

// transpose fp32 [R][C] -> bf16 [C][R pad ldd]
__global__ void transpose_bf_k(const float* __restrict__ src,
                               __nv_bfloat16* __restrict__ dst,
                               int R, int C, int ldd) {
    __shared__ float tile[32][33];
    int c0 = blockIdx.x * 32, r0 = blockIdx.y * 32;
#pragma unroll
    for (int i = 0; i < 4; i++) {
        int r = r0 + threadIdx.y + i * 8;
        int c = c0 + threadIdx.x;
        tile[threadIdx.y + i * 8][threadIdx.x] = (r < R && c < C) ? src[(long)r * C + c] : 0.f;
    }
    __syncthreads();
#pragma unroll
    for (int i = 0; i < 4; i++) {
        int orow = c0 + threadIdx.y + i * 8;
        int ocol = r0 + threadIdx.x;
        if (orow < C)
            dst[(long)orow * ldd + ocol] = __float2bfloat16(tile[threadIdx.x][threadIdx.y + i * 8]);
    }
}

// beta [t][k][v] fp32 -> betaT [t][v][64] bf16 (k padded to 64 with zeros)
__global__ void betaT_k() {
    __shared__ float sm[64][33];
    int t = blockIdx.y;
    int v0 = blockIdx.x * 32;
    int lane = threadIdx.x & 31, w = threadIdx.x >> 5;
    for (int k = w; k < 64; k += 8) {
        int v = v0 + lane;
        sm[k][lane] = (k < K_ && v < V_) ? g_beta[((long)t * K_ + k) * V_ + v] : 0.f;
    }
    __syncthreads();
    int r = threadIdx.x >> 3;
    int c0 = (threadIdx.x & 7) * 8;
    if (v0 + r < V_) {
        __nv_bfloat16 tmp[8];
#pragma unroll
        for (int j = 0; j < 8; j++) tmp[j] = __float2bfloat16(sm[c0 + j][r]);
        *(uint4*)&g_betaT_bf[((long)t * NP_V + v0 + r) * 64 + c0] = *(uint4*)tmp;
    }
}

__global__ void prep_lstm_k(const float* __restrict__ Wih, const float* __restrict__ Whh,
                            const float* __restrict__ bih, const float* __restrict__ bhh) {
    int idx = blockIdx.x * blockDim.x + threadIdx.x;
    if (idx < 4 * HE_ * HE_) {
        int row = idx / HE_, k = idx % HE_;
        int j = row >> 2, gate = row & 3;
        g_wih_int[idx] = Wih[((long)(gate * HE_ + j)) * HE_ + k];
        g_whh_int[idx] = Whh[((long)(gate * HE_ + j)) * HE_ + k];
    } else if (idx < 4 * HE_ * HE_ + 4 * HE_) {
        int r = idx - 4 * HE_ * HE_;
        int j = r >> 2, gate = r & 3;
        g_bi_int[r] = bih[gate * HE_ + j] + bhh[gate * HE_ + j];
    }
}

__global__ void prep_wml_k(const float* __restrict__ mutW, const float* __restrict__ mutb,
                           const float* __restrict__ lstW, const float* __restrict__ lstb) {
    int idx = blockIdx.x * blockDim.x + threadIdx.x;
    if (idx < 128 * HT_) {
        int row = idx / HT_, k = idx % HT_;
        float v = 0.f;
        if (row < 50) v = mutW[(long)row * HT_ + k];
        else if (row < 100) v = lstW[(long)(row - 50) * HT_ + k];
        g_wml_bf[idx] = __float2bfloat16(v);
    } else if (idx < 128 * HT_ + 128) {
        int r = idx - 128 * HT_;
        g_wmlb[r] = (r < 50) ? mutb[r] : (r < 100 ? lstb[r - 50] : 0.f);
    }
}

__global__ void alphas_kernel(const float* __restrict__ muq, const float* __restrict__ lsq) {
    int idx = blockIdx.x * blockDim.x + threadIdx.x;
    if (idx >= NA_) return;
    int t = idx / (K_ * RHO_), rem = idx % (K_ * RHO_);
    int k = rem / RHO_, r = rem % RHO_;
    int src = (k * T_ + t) * RHO_ + r;
    float a = muq[src] + g_eps_a[idx] * expf(0.5f * lsq[src]);
    g_alphas[idx] = a;
    int row = t * K_ + k;
    g_alphas_bf[(long)row * KP_RHO + r] = __float2bfloat16(a);
}

__global__ void kld_alpha_kernel(const float* __restrict__ muq, const float* __restrict__ lsq) {
    __shared__ float red[256];
    float acc = 0.f;
    for (int idx = blockIdx.x * blockDim.x + threadIdx.x; idx < NA_;
         idx += gridDim.x * blockDim.x) {
        int t = idx / (K_ * RHO_), rem = idx % (K_ * RHO_);
        int k = rem / RHO_, r = rem % RHO_;
        int src = (k * T_ + t) * RHO_ + r;
        float mu = muq[src];
        float ls = lsq[src];
        float qls = fminf(fmaxf(ls, -100.f), 100.f);
        float pmu = (t == 0) ? 0.f : g_alphas[idx - K_ * RHO_];
        float pls = (t == 0) ? 0.f : LOGD;
        float d = mu - pmu;
        acc += (expf(qls) + d * d) / (expf(pls) + 1e-6f) - 1.f + pls - qls;
    }
    float s = block_sum(acc, red);
    if (threadIdx.x == 0) g_part_a[blockIdx.x] = s;
}

__global__ void softmax_rows_kernel() {
    __shared__ float red[256];
    long base = (long)blockIdx.x * V_;
    long basebf = (long)blockIdx.x * KP_V;
    int tid = threadIdx.x;
    float m = -FLT_MAX;
    for (int c = tid; c < V_; c += 256) m = fmaxf(m, g_beta[base + c]);
    m = block_max(m, red);
    float s = 0.f;
    for (int c = tid; c < V_; c += 256) {
        float e = expf(g_beta[base + c] - m);
        g_beta[base + c] = e; s += e;
    }
    s = block_sum(s, red);
    float inv = 1.f / s;
    for (int c = tid; c < V_; c += 256) {
        float b = g_beta[base + c] * inv;
        g_beta[base + c] = b;
        g_beta_bf[basebf + c] = __float2bfloat16(b);
    }
}

__global__ void combine_inp_k(const float* __restrict__ qeb) {
    int idx = blockIdx.x * blockDim.x + threadIdx.x;
    if (idx >= B_ * T_ * HE_) return;
    int j = idx & (HE_ - 1);
    float s = qeb[j];
#pragma unroll
    for (int z = 0; z < INP_SPLIT; z++) s += g_inp_part[(long)z * B_ * T_ * HE_ + idx];
    g_inp[idx] = s;
}

// fused LSTM step
__global__ void lstm_step_k(const float* __restrict__ hin, float* __restrict__ hout, int t) {
    __shared__ float As[16][65];
    __shared__ float Bs[16][65];
    __shared__ float gsm[64][68];
    const int Kd = HE_;
    int tid = threadIdx.x;
    int tx = tid & 15, ty = tid >> 4;
    int m0 = blockIdx.y * 64, n0 = blockIdx.x * 64;
    float acc[4][4] = {};
    for (int k0 = 0; k0 < Kd; k0 += 16) {
#pragma unroll
        for (int i = 0; i < 4; i++) {
            int e = tid + i * 256;
            int m = e >> 4, kk = e & 15;
            As[kk][m] = hin[(long)(m0 + m) * HE_ + k0 + kk];
        }
#pragma unroll
        for (int i = 0; i < 4; i++) {
            int e = tid + i * 256;
            int n = e >> 4, kk = e & 15;
            Bs[kk][n] = g_whh_int[(long)(n0 + n) * HE_ + k0 + kk];
        }
        __syncthreads();
#pragma unroll
        for (int kk = 0; kk < 16; kk++) {
            float a[4], b[4];
#pragma unroll
            for (int i = 0; i < 4; i++) a[i] = As[kk][ty + 16 * i];
#pragma unroll
            for (int j = 0; j < 4; j++) b[j] = Bs[kk][tx + 16 * j];
#pragma unroll
            for (int i = 0; i < 4; i++)
#pragma unroll
                for (int j = 0; j < 4; j++)
                    acc[i][j] = fmaf(a[i], b[j], acc[i][j]);
        }
        __syncthreads();
    }
#pragma unroll
    for (int i = 0; i < 4; i++) {
        int b = m0 + ty + 16 * i;
#pragma unroll
        for (int j = 0; j < 4; j++) {
            int n = n0 + tx + 16 * j;
            gsm[ty + 16 * i][tx + 16 * j] = acc[i][j] + g_gx[((long)b * T_ + t) * (4 * HE_) + n];
        }
    }
    __syncthreads();
#pragma unroll
    for (int q = 0; q < 4; q++) {
        int idx = tid + q * 256;
        int bl = idx >> 4, jl = idx & 15;
        float gi = gsm[bl][4 * jl];
        float gf = gsm[bl][4 * jl + 1];
        float gg = gsm[bl][4 * jl + 2];
        float go = gsm[bl][4 * jl + 3];
        int b = m0 + bl;
        int j = blockIdx.x * 16 + jl;
        float si = 1.f / (1.f + expf(-gi));
        float sf = 1.f / (1.f + expf(-gf));
        float so = 1.f / (1.f + expf(-go));
        float c = sf * g_cstate[b * HE_ + j] + si * tanhf(gg);
        float h = so * tanhf(c);
        g_cstate[b * HE_ + j] = c;
        hout[b * HE_ + j] = h;
        g_lstm[((long)t * B_ + b) * HE_ + j] = h;
    }
}

__global__ void eta_step_kernel(const float* __restrict__ mueW, const float* __restrict__ mueb,
                                const float* __restrict__ lseW, const float* __restrict__ lseb,
                                int t) {
    __shared__ float z[HEK_];
    __shared__ float red[64];
    int b = blockIdx.x, tid = threadIdx.x;
    for (int c = tid; c < HE_; c += 64) z[c] = g_lstm[((long)t * B_ + b) * HE_ + c];
    for (int c = tid; c < K_; c += 64) z[HE_ + c] = g_eta_prev[b * K_ + c];
    __syncthreads();
    float kl = 0.f, eta = 0.f;
    if (tid < K_) {
        const float* wm = mueW + tid * HEK_;
        const float* wl = lseW + tid * HEK_;
        float mu = mueb[tid], ls = lseb[tid];
#pragma unroll 2
        for (int c = 0; c < HEK_; c++) {
            float zc = z[c];
            mu = fmaf(zc, wm[c], mu);
            ls = fmaf(zc, wl[c], ls);
        }
        float eps = g_eps_e[((long)t * B_ + b) * K_ + tid];
        eta = mu + eps * expf(0.5f * ls);
        g_etas[((long)t * B_ + b) * K_ + tid] = eta;
        float qls = fminf(fmaxf(ls, -100.f), 100.f);
        float pmu = z[HE_ + tid];
        float pls = (t == 0) ? 0.f : LOGD;
        float d = mu - pmu;
        kl = (expf(qls) + d * d) / (expf(pls) + 1e-6f) - 1.f + pls - qls;
    }
    float s = block_sum((tid < K_) ? kl : 0.f, red);
    if (tid == 0) g_part_ke[t * B_ + b] = s;
    if (tid < K_) g_eta_prev[b * K_ + tid] = eta;
}

// h1 = relu(h1e + sum_z h1b_part) -> bf16 ; grid (4, T_*B_)
__global__ void combine_h1_kernel() {
    int j = blockIdx.x * blockDim.x + threadIdx.x;
    if (j >= HT_) return;
    int row = blockIdx.y;
    int b = row & (B_ - 1);
    float hb = 0.f;
#pragma unroll
    for (int z = 0; z < H1B_SPLIT; z++) hb += g_h1b_part[(long)z * B_ * HT_ + b * HT_ + j];
    long idx = (long)row * HT_ + j;
    float v = fmaxf(g_h1e[idx] + hb, 0.f);
    g_h1_bf[idx] = __float2bfloat16(v);
}

__global__ void theta_kernel() {
    __shared__ float red[64];
    int row = blockIdx.x, k = threadIdx.x;
    long base = (long)row * K_;
    long mbase = (long)row * 100;
    bool val = k < K_;
    float mu = 0.f, ls = 0.f, zv = -FLT_MAX;
    if (val) {
        mu = g_mls[mbase + k];
        ls = g_mls[mbase + 50 + k];
        zv = mu + g_eps_t[base + k] * expf(0.5f * ls);
    }
    float mx = block_max(zv, red);
    float e = val ? expf(zv - mx) : 0.f;
    float sum = block_sum(e, red);
    float th = e / sum;
    if (val) {
        g_theta_arr[base + k] = th;
        g_theta_bf[(long)row * 64 + k] = __float2bfloat16(th);
    }
    float kl = 0.f;
    if (val) {
        float qls = fminf(fmaxf(ls, -100.f), 100.f);
        float d = mu - g_etas[base + k];
        kl = (expf(qls) + d * d) / (1.f + 1e-6f) - 1.f - qls;
    }
    float s = block_sum(kl, red);
    if (k == 0) g_part_kt[row] = s;
}

__global__ void final_reduce_kernel(float* out, int out_size) {
    __shared__ float red[256];
    int tid = threadIdx.x;
    float v;
    v = 0.f; for (int i = tid; i < RB_NLL;  i += 256) v += g_part_nll[i];
    float nll  = block_sum(v, red) * (10.0f / B_);
    v = 0.f; for (int i = tid; i < T_ * B_; i += 256) v += g_part_kt[i];
    float kt   = block_sum(v, red) * (0.5f / (T_ * B_));
    v = 0.f; for (int i = tid; i < RB_A;    i += 256) v += g_part_a[i];
    float ka   = block_sum(v, red) * (0.5f / (T_ * K_));
    v = 0.f; for (int i = tid; i < T_ * B_; i += 256) v += g_part_ke[i];
    float ke   = block_sum(v, red) * (0.5f / B_);
    v = 0.f; for (int i = tid; i < RB_COND; i += 256) v += g_part_cond[i];
    float cond = block_sum(v, red) * (-0.01f);
    if (tid == 0) {
        if (out_size > 0) out[0] = nll;
        if (out_size > 1) out[1] = kt;
        if (out_size > 2) out[2] = ka;
        if (out_size > 3) out[3] = ke;
        if (out_size > 4) out[4] = cond;
    }
}

// ---------------- host driver ----------------
static inline int ceil_div(long a, long b) { return (int)((a + b - 1) / b); }

extern "C" void kernel_launch(void* const* d_in, const int* in_sizes, int n_in,
                              void* d_out, int out_size) {
    (void)in_sizes; (void)n_in;
    const float* nb   = (const float*)d_in[0];
    const float* bow  = (const float*)d_in[1];
    const float* adj  = (const float*)d_in[2];
    const float* muqa = (const float*)d_in[3];
    const float* lsqa = (const float*)d_in[4];
    const float* rhoW = (const float*)d_in[5];
    const float* rhob = (const float*)d_in[6];
    const float* W1   = (const float*)d_in[7];
    const float* b1   = (const float*)d_in[8];
    const float* W2   = (const float*)d_in[9];
    const float* b2   = (const float*)d_in[10];
    const float* mutW = (const float*)d_in[11];
    const float* mutb = (const float*)d_in[12];
    const float* lstW = (const float*)d_in[13];
    const float* lstb = (const float*)d_in[14];
    const float* qeW  = (const float*)d_in[15];
    const float* qeb  = (const float*)d_in[16];
    const float* Wih  = (const float*)d_in[17];
    const float* Whh  = (const float*)d_in[18];
    const float* bih  = (const float*)d_in[19];
    const float* bhh  = (const float*)d_in[20];
    const float* mueW = (const float*)d_in[21];
    const float* mueb = (const float*)d_in[22];
    const float* lseW = (const float*)d_in[23];
    const float* lseb = (const float*)d_in[24];
    float* out = (float*)d_out;

    unsigned ka0, ka1, ke0, ke1, kt0, kt1;
    tf2x32(0u, 42u, 0u, 0u, &ka0, &ka1);
    tf2x32(0u, 42u, 0u, 1u, &ke0, &ke1);
    tf2x32(0u, 42u, 0u, 2u, &kt0, &kt1);

    float *p_beta, *p_inp, *p_inp_part, *p_gx, *p_hb0, *p_hb1, *p_etas, *p_h1e, *p_h1b_part, *p_mls;
    float *p_wih_int, *p_bi_int, *p_part_cond, *p_wmlb;
    __nv_bfloat16 *p_alphas_bf, *p_beta_bf, *p_adjT, *p_bow_bf, *p_qew_bf, *p_nb_bf;
    __nv_bfloat16 *p_w1_bf, *p_rhow_bf, *p_w2_bf, *p_wml_bf, *p_h1_bf, *p_h2_bf;
    cudaGetSymbolAddress((void**)&p_beta,      g_beta);
    cudaGetSymbolAddress((void**)&p_inp,       g_inp);
    cudaGetSymbolAddress((void**)&p_inp_part,  g_inp_part);
    cudaGetSymbolAddress((void**)&p_gx,        g_gx);
    cudaGetSymbolAddress((void**)&p_hb0,       g_hbuf);
    p_hb1 = p_hb0 + B_ * HE_;
    cudaGetSymbolAddress((void**)&p_etas,      g_etas);
    cudaGetSymbolAddress((void**)&p_h1e,       g_h1e);
    cudaGetSymbolAddress((void**)&p_h1b_part,  g_h1b_part);
    cudaGetSymbolAddress((void**)&p_mls,       g_mls);
    cudaGetSymbolAddress((void**)&p_wih_int,   g_wih_int);
    cudaGetSymbolAddress((void**)&p_bi_int,    g_bi_int);
    cudaGetSymbolAddress((void**)&p_part_cond, g_part_cond);
    cudaGetSymbolAddress((void**)&p_wmlb,      g_wmlb);
    cudaGetSymbolAddress((void**)&p_alphas_bf, g_alphas_bf);
    cudaGetSymbolAddress((void**)&p_beta_bf,   g_beta_bf);
    cudaGetSymbolAddress((void**)&p_adjT,      g_adjT_bf);
    cudaGetSymbolAddress((void**)&p_bow_bf,    g_bow_bf);
    cudaGetSymbolAddress((void**)&p_qew_bf,    g_qew_bf);
    cudaGetSymbolAddress((void**)&p_nb_bf,     g_nb_bf);
    cudaGetSymbolAddress((void**)&p_w1_bf,     g_w1_bf);
    cudaGetSymbolAddress((void**)&p_rhow_bf,   g_rhow_bf);
    cudaGetSymbolAddress((void**)&p_w2_bf,     g_w2_bf);
    cudaGetSymbolAddress((void**)&p_wml_bf,    g_wml_bf);
    cudaGetSymbolAddress((void**)&p_h1_bf,     g_h1_bf);
    cudaGetSymbolAddress((void**)&p_h2_bf,     g_h2_bf);

    // raise dynamic smem limit for pipelined TC GEMM instantiations (idempotent)
    cudaFuncSetAttribute(tc_gemm_k<true,  false, false, false>, cudaFuncAttributeMaxDynamicSharedMemorySize, TC_SMEM_BYTES);
    cudaFuncSetAttribute(tc_gemm_k<false, false, false, true >, cudaFuncAttributeMaxDynamicSharedMemorySize, TC_SMEM_BYTES);
    cudaFuncSetAttribute(tc_gemm_k<false, false, false, false>, cudaFuncAttributeMaxDynamicSharedMemorySize, TC_SMEM_BYTES);
    cudaFuncSetAttribute(tc_gemm_k<true,  true,  true,  false>, cudaFuncAttributeMaxDynamicSharedMemorySize, TC_SMEM_BYTES);

    // 1. state init + RNG
    init_zero_kernel<<<(B_ * HE_ + B_ * K_ + 255) / 256, 256>>>();
    int totalElems = NA_ + 2 * NE_;
    eps_kernel<<<(totalElems + 255) / 256, 256>>>(ka0, ka1, ke0, ke1, kt0, kt1);

    // 2. conversions (div-free 2D grids, vectorized where rows are 16B-aligned)
    transpose_bf_k<<<dim3(ceil_div(V_, 32), ceil_div(V_, 32)), dim3(32, 8)>>>(adj, p_adjT, V_, V_, KP_V);
    convbf_vec_k<<<dim3(ceil_div(KP_V / 8, 256), B_ * T_), 256>>>(bow, V_, p_bow_bf, KP_V, V_);
    convbf_vec_k<<<dim3(ceil_div(KP_V / 8, 256), HE_), 256>>>(qeW, V_, p_qew_bf, KP_V, V_);
    convbf_vec_k<<<dim3(ceil_div(KP_V / 8, 256), B_), 256>>>(nb, V_, p_nb_bf, KP_V, V_);
    convbf_row_k<<<dim3(ceil_div(KP_V, 256), HT_), 256>>>(W1, VK_, p_w1_bf, KP_V, V_);
    convbf_vec_k<<<dim3(ceil_div(KP_RHO / 8, 256), V_), 256>>>(rhoW, RHO_, p_rhow_bf, KP_RHO, RHO_);
    convbf_vec_k<<<dim3(ceil_div(HT_ / 8, 256), HT_), 256>>>(W2, HT_, p_w2_bf, HT_, HT_);
    prep_lstm_k<<<(4 * HE_ * HE_ + 4 * HE_ + 255) / 256, 256>>>(Wih, Whh, bih, bhh);
    prep_wml_k<<<(128 * HT_ + 128 + 255) / 256, 256>>>(mutW, mutb, lstW, lstb);

    // 3. alphas + KL(alpha)
    alphas_kernel<<<(NA_ + 255) / 256, 256>>>(muqa, lsqa);
    kld_alpha_kernel<<<RB_A, 256>>>(muqa, lsqa);

    // 4. beta logits -> softmax -> bf16 + betaT
    tc_gemm_k<true, false, false, false><<<dim3(ceil_div(V_, 128), ceil_div(T_ * K_, 128)), 256, TC_SMEM_BYTES>>>(
        p_alphas_bf, KP_RHO, p_rhow_bf, KP_RHO, rhob, p_beta, nullptr, V_,
        nullptr, nullptr, T_ * K_, V_, KP_RHO);
    softmax_rows_kernel<<<T_ * K_, 256>>>();
    betaT_k<<<dim3(ceil_div(V_, 32), T_), 256>>>();

    // 5. cond (fused trace)
    tc_gemm_k<false, false, false, true><<<dim3(ceil_div(V_, 128), ceil_div(T_ * K_, 128)), 256, TC_SMEM_BYTES>>>(
        p_beta_bf, KP_V, p_adjT, KP_V, nullptr, nullptr, nullptr, V_,
        p_beta, p_part_cond, T_ * K_, V_, KP_V);

    // 6. inp = bow @ qeW^T (split-K) + combine with bias
    tc_gemm_k<false, false, false, false><<<dim3(ceil_div(HE_, 128), ceil_div(B_ * T_, 128), INP_SPLIT), 256, TC_SMEM_BYTES>>>(
        p_bow_bf, KP_V, p_qew_bf, KP_V, nullptr, p_inp_part, nullptr, HE_,
        nullptr, nullptr, B_ * T_, HE_, KP_V);
    combine_inp_k<<<ceil_div(B_ * T_ * HE_, 256), 256>>>(qeb);

    // 7. gates_x + fused LSTM steps
    gemm_k<false><<<dim3(16, 48), 256>>>(
        p_inp, HE_, p_wih_int, HE_, p_bi_int, p_gx, 4 * HE_, B_ * T_, 4 * HE_, HE_);
    for (int t = 0; t < T_; t++) {
        float* hin  = (t & 1) ? p_hb1 : p_hb0;
        float* hout = (t & 1) ? p_hb0 : p_hb1;
        lstm_step_k<<<dim3(16, 4), 256>>>(hin, hout, t);
    }

    // 8. eta recurrence
    for (int t = 0; t < T_; t++)
        eta_step_kernel<<<B_, 64>>>(mueW, mueb, lseW, lseb, t);

    // 9. theta encoder
    gemm_k<false><<<dim3(13, 48), 256>>>(
        p_etas, K_, W1 + V_, VK_, b1, p_h1e, HT_, T_ * B_, HT_, K_);
    tc_gemm_k<false, false, false, false><<<dim3(ceil_div(HT_, 128), ceil_div(B_, 128), H1B_SPLIT), 256, TC_SMEM_BYTES>>>(
        p_nb_bf, KP_V, p_w1_bf, KP_V, nullptr, p_h1b_part, nullptr, HT_,
        nullptr, nullptr, B_, HT_, KP_V);
    combine_h1_kernel<<<dim3(ceil_div(HT_, 256), T_ * B_), 256>>>();
    tc_gemm_k<true, true, true, false><<<dim3(ceil_div(HT_, 128), ceil_div(T_ * B_, 128)), 256, TC_SMEM_BYTES>>>(
        p_h1_bf, HT_, p_w2_bf, HT_, b2, nullptr, p_h2_bf, HT_,
        nullptr, nullptr, T_ * B_, HT_, HT_);
    tc_gemm_k<true, false, false, false><<<dim3(1, ceil_div(T_ * B_, 128)), 256, TC_SMEM_BYTES>>>(
        p_h2_bf, HT_, p_wml_bf, HT_, p_wmlb, p_mls, nullptr, 100,
        nullptr, nullptr, T_ * B_, 100, HT_);

    // 10. theta softmax + KL(theta) (+theta bf16)
    theta_kernel<<<T_ * B_, 64>>>();

    // 11. decode TC GEMM fused with NLL
    tc_nll_k<<<dim3(40, 2, T_), 256>>>(bow);

    // 12. final scalars
    final_reduce_kernel<<<1, 256>>>(out, out_size);
}

// round 12
// speedup vs baseline: 4.6173x; 2.0948x over previous
#include <cuda_runtime.h>
#include <cuda_bf16.h>
#include <cstdint>
#include <float.h>
#include <math.h>

// ---------------- problem constants ----------------
#define T_    12
#define K_    50
#define V_    5000
#define B_    256
#define RHO_  300
#define HT_   800
#define HE_   256
#define VK_   (V_ + K_)
#define HEK_  (HE_ + K_)   // 306
#define LOGD  (-5.2983173665480363f)

#define NA_   (T_*K_*RHO_)
#define NE_   (T_*B_*K_)

#define KP_V   5024
#define KP_RHO 320
#define NP_V   5120
#define MP_TK  640

#define INP_SPLIT 4
#define H1B_SPLIT 8

// ---------------- device scratch ----------------
__device__ float g_eps_a[NA_];
__device__ float g_eps_e[NE_];
__device__ float g_eps_t[NE_];
__device__ float g_alphas[NA_];
__device__ __align__(16) __nv_bfloat16 g_alphas_bf[MP_TK*KP_RHO];
__device__ float g_beta[T_*K_*V_];
__device__ __align__(16) __nv_bfloat16 g_beta_bf[MP_TK*KP_V];
__device__ __align__(16) __nv_bfloat16 g_betaT_bf[T_*NP_V*64];
__device__ __align__(16) __nv_bfloat16 g_adjT_bf[NP_V*KP_V];
__device__ __align__(16) __nv_bfloat16 g_bow_bf[B_*T_*KP_V];
__device__ __align__(16) __nv_bfloat16 g_qew_bf[HE_*KP_V];
__device__ __align__(16) __nv_bfloat16 g_nb_bf[B_*KP_V];
__device__ __align__(16) __nv_bfloat16 g_w1_bf[896*KP_V];
__device__ __align__(16) __nv_bfloat16 g_rhow_bf[NP_V*KP_RHO];
__device__ __align__(16) __nv_bfloat16 g_w2_bf[896*HT_];
__device__ __align__(16) __nv_bfloat16 g_wml_bf[128*HT_];
__device__ float g_wmlb[128];
__device__ __align__(16) __nv_bfloat16 g_whhT_bf[HE_*4*HE_];   // [k][1024] interleaved j*4+gate
__device__ __align__(16) __nv_bfloat16 g_wih_bf[4*HE_*HE_];    // [1024 rows j*4+g][k=256]
__device__ float g_bi_int[4*HE_];
__device__ __align__(16) __nv_bfloat16 g_inp_bf[B_*T_*HE_];
__device__ float g_inp_part[INP_SPLIT*B_*T_*HE_];
__device__ float g_gx[B_*T_*4*HE_];
__device__ float g_lstm[T_*B_*HE_];
__device__ float g_etas[NE_];
__device__ float g_h1e[T_*B_*HT_];
__device__ float g_h1b_part[H1B_SPLIT*B_*HT_];
__device__ __align__(16) __nv_bfloat16 g_h1_bf[T_*B_*HT_];
__device__ __align__(16) __nv_bfloat16 g_h2_bf[T_*B_*HT_];
__device__ float g_mls[T_*B_*100];
__device__ float g_theta_arr[NE_];
__device__ __align__(16) __nv_bfloat16 g_theta_bf[T_*B_*64];

#define RB_NLL  (12*2*40)
#define RB_COND 200
#define RB_A    256
__device__ float g_part_nll[RB_NLL];
__device__ float g_part_cond[RB_COND];
__device__ float g_part_a[RB_A];
__device__ float g_part_kt[T_*B_];
__device__ float g_part_ke[T_*B_];

// ---------------- threefry2x32 (JAX partitionable) ----------------
__host__ __device__ inline void tf2x32(unsigned k0, unsigned k1,
                                       unsigned x0, unsigned x1,
                                       unsigned* o0, unsigned* o1) {
    unsigned ks0 = k0, ks1 = k1, ks2 = k0 ^ k1 ^ 0x1BD11BDAu;
    x0 += ks0; x1 += ks1;
#define TF_R(r) { x0 += x1; x1 = (x1 << (r)) | (x1 >> (32 - (r))); x1 ^= x0; }
    TF_R(13) TF_R(15) TF_R(26) TF_R(6)
    x0 += ks1; x1 += ks2 + 1u;
    TF_R(17) TF_R(29) TF_R(16) TF_R(24)
    x0 += ks2; x1 += ks0 + 2u;
    TF_R(13) TF_R(15) TF_R(26) TF_R(6)
    x0 += ks0; x1 += ks1 + 3u;
    TF_R(17) TF_R(29) TF_R(16) TF_R(24)
    x0 += ks1; x1 += ks2 + 4u;
    TF_R(13) TF_R(15) TF_R(26) TF_R(6)
    x0 += ks2; x1 += ks0 + 5u;
#undef TF_R
    *o0 = x0; *o1 = x1;
}

__device__ __forceinline__ float bits2normal(unsigned bits) {
    float f = __uint_as_float((bits >> 9) | 0x3F800000u) - 1.0f;
    const float lo = -0.99999994f;
    float u = fmaf(f, 2.0f, lo);
    u = fmaxf(lo, u);
    return 1.4142135381698608f * erfinvf(u);
}

__device__ __forceinline__ float partitionable_normal(unsigned k0, unsigned k1, unsigned i) {
    unsigned o0, o1;
    tf2x32(k0, k1, 0u, i, &o0, &o1);
    return bits2normal(o0 ^ o1);
}

// ---------------- block reductions ----------------
__device__ __forceinline__ float block_sum(float v, float* red) {
    int tid = threadIdx.x, n = blockDim.x;
    red[tid] = v; __syncthreads();
    for (int s = n >> 1; s > 0; s >>= 1) {
        if (tid < s) red[tid] += red[tid + s];
        __syncthreads();
    }
    v = red[0]; __syncthreads();
    return v;
}
__device__ __forceinline__ float block_max(float v, float* red) {
    int tid = threadIdx.x, n = blockDim.x;
    red[tid] = v; __syncthreads();
    for (int s = n >> 1; s > 0; s >>= 1) {
        if (tid < s) red[tid] = fmaxf(red[tid], red[tid + s]);
        __syncthreads();
    }
    v = red[0]; __syncthreads();
    return v;
}

// ---------------- mma + cp.async helpers ----------------
__device__ __forceinline__ void mma16816(float* c, const uint32_t* a, uint32_t b0, uint32_t b1) {
    asm volatile(
        "mma.sync.aligned.m16n8k16.row.col.f32.bf16.bf16.f32 "
        "{%0,%1,%2,%3}, {%4,%5,%6,%7}, {%8,%9}, {%0,%1,%2,%3};\n"
        : "+f"(c[0]), "+f"(c[1]), "+f"(c[2]), "+f"(c[3])
        : "r"(a[0]), "r"(a[1]), "r"(a[2]), "r"(a[3]), "r"(b0), "r"(b1));
}
#define CPASYNC16(sp, gp) \
    asm volatile("cp.async.cg.shared.global [%0], [%1], 16;\n" \
        :: "r"((unsigned)__cvta_generic_to_shared(sp)), "l"(gp))
#define CPCOMMIT() asm volatile("cp.async.commit_group;\n")
#define CPWAIT(n)  asm volatile("cp.async.wait_group %0;\n" :: "n"(n))

#define TC_SMEM_BYTES (2 * 3 * 128 * 40 * 2)

// ---------------- pipelined bf16 TC GEMM (NT) ----------------
template<bool BIAS, bool RELU, bool OUTBF, bool CONDEPI>
__global__ void __launch_bounds__(256) tc_gemm_k(
    const __nv_bfloat16* __restrict__ A, int lda,
    const __nv_bfloat16* __restrict__ B, int ldb,
    const float* __restrict__ bias,
    float* __restrict__ C, __nv_bfloat16* __restrict__ Cbf, int ldc,
    const float* __restrict__ Cf, float* __restrict__ part,
    int M, int N, int Kp) {
    extern __shared__ __nv_bfloat16 smp[];
    __nv_bfloat16* As = smp;
    __nv_bfloat16* Bs = smp + 3 * 128 * 40;
    __shared__ float red[256];
    int tid = threadIdx.x;
    int lane = tid & 31, wid = tid >> 5;
    int wm = wid & 3, wn = wid >> 2;
    int g = lane >> 2, t4 = lane & 3;
    long m0 = (long)blockIdx.y * 128, n0 = (long)blockIdx.x * 128;
    int arow = tid >> 2;
    int akc = (tid & 3) * 8;
    float acc[2][8][4] = {};

    int nkt = Kp >> 5;
    int per = (nkt + gridDim.z - 1) / gridDim.z;
    int it0 = blockIdx.z * per;
    int itn = nkt - it0; if (itn > per) itn = per; if (itn < 0) itn = 0;

#define TC_ISSUE(IT, S) do {                                                     \
        int _k = ((IT) << 5) + akc;                                              \
        __nv_bfloat16* _as = As + (size_t)(S) * 128 * 40;                        \
        __nv_bfloat16* _bs = Bs + (size_t)(S) * 128 * 40;                        \
        CPASYNC16(&_as[(size_t)arow * 40 + akc],        &A[(m0 + arow) * (long)lda + _k]);        \
        CPASYNC16(&_as[(size_t)(arow + 64) * 40 + akc], &A[(m0 + arow + 64) * (long)lda + _k]);   \
        CPASYNC16(&_bs[(size_t)arow * 40 + akc],        &B[(n0 + arow) * (long)ldb + _k]);        \
        CPASYNC16(&_bs[(size_t)(arow + 64) * 40 + akc], &B[(n0 + arow + 64) * (long)ldb + _k]);   \
        CPCOMMIT();                                                              \
    } while (0)

    if (itn > 0) TC_ISSUE(it0, 0);
    if (itn > 1) TC_ISSUE(it0 + 1, 1);

    for (int ii = 0; ii < itn; ii++) {
        if (ii + 1 < itn) { CPWAIT(1); } else { CPWAIT(0); }
        __syncthreads();
        if (ii + 2 < itn) TC_ISSUE(it0 + ii + 2, (ii + 2) % 3);
        const __nv_bfloat16* Asb = As + (size_t)(ii % 3) * 128 * 40;
        const __nv_bfloat16* Bsb = Bs + (size_t)(ii % 3) * 128 * 40;
#pragma unroll
        for (int ks = 0; ks < 32; ks += 16) {
            uint32_t a[2][4];
#pragma unroll
            for (int i = 0; i < 2; i++) {
                int r = wm * 32 + i * 16 + g;
                a[i][0] = *(const uint32_t*)&Asb[(size_t)r * 40 + ks + 2 * t4];
                a[i][1] = *(const uint32_t*)&Asb[(size_t)(r + 8) * 40 + ks + 2 * t4];
                a[i][2] = *(const uint32_t*)&Asb[(size_t)r * 40 + ks + 2 * t4 + 8];
                a[i][3] = *(const uint32_t*)&Asb[(size_t)(r + 8) * 40 + ks + 2 * t4 + 8];
            }
#pragma unroll
            for (int j = 0; j < 8; j++) {
                int n = wn * 64 + j * 8 + g;
                uint32_t b0 = *(const uint32_t*)&Bsb[(size_t)n * 40 + ks + 2 * t4];
                uint32_t b1 = *(const uint32_t*)&Bsb[(size_t)n * 40 + ks + 2 * t4 + 8];
#pragma unroll
                for (int i = 0; i < 2; i++)
                    mma16816(acc[i][j], a[i], b0, b1);
            }
        }
        __syncthreads();
    }
#undef TC_ISSUE

    if (CONDEPI) {
        float local = 0.f;
#pragma unroll
        for (int i = 0; i < 2; i++) {
#pragma unroll
            for (int j = 0; j < 8; j++) {
                long m = m0 + wm * 32 + i * 16 + g;
                long n = n0 + wn * 64 + j * 8 + 2 * t4;
                if (m < M) {
                    if (n < N)     local += acc[i][j][0] * Cf[m * ldc + n];
                    if (n + 1 < N) local += acc[i][j][1] * Cf[m * ldc + n + 1];
                }
                if (m + 8 < M) {
                    if (n < N)     local += acc[i][j][2] * Cf[(m + 8) * ldc + n];
                    if (n + 1 < N) local += acc[i][j][3] * Cf[(m + 8) * ldc + n + 1];
                }
            }
        }
        float s = block_sum(local, red);
        if (tid == 0) part[blockIdx.y * gridDim.x + blockIdx.x] = s;
    } else {
        float* Cz = C ? C + (long)blockIdx.z * M * ldc : nullptr;
#pragma unroll
        for (int i = 0; i < 2; i++) {
#pragma unroll
            for (int j = 0; j < 8; j++) {
                long m = m0 + wm * 32 + i * 16 + g;
                long n = n0 + wn * 64 + j * 8 + 2 * t4;
#pragma unroll
                for (int q = 0; q < 4; q++) {
                    long mm = m + (q >> 1) * 8;
                    long nn = n + (q & 1);
                    if (mm < M && nn < N) {
                        float v = acc[i][j][q];
                        if (BIAS) v += bias[nn];
                        if (RELU) v = fmaxf(v, 0.f);
                        if (OUTBF) Cbf[mm * ldc + nn] = __float2bfloat16(v);
                        else       Cz[mm * ldc + nn] = v;
                    }
                }
            }
        }
    }
}

// ---------------- TC NLL ----------------
__global__ void __launch_bounds__(256) tc_nll_k(const float* __restrict__ bow) {
    __shared__ __nv_bfloat16 As[128][40];
    __shared__ __nv_bfloat16 Bs[128][40];
    __shared__ float red[256];
    int t = blockIdx.z;
    const __nv_bfloat16* A = g_theta_bf + (long)t * B_ * 64;
    const __nv_bfloat16* B = g_betaT_bf + (long)t * NP_V * 64;
    int tid = threadIdx.x;
    int lane = tid & 31, wid = tid >> 5;
    int wm = wid & 3, wn = wid >> 2;
    int g = lane >> 2, t4 = lane & 3;
    long m0 = (long)blockIdx.y * 128, n0 = (long)blockIdx.x * 128;
    int arow = tid >> 2;
    int akc = (tid & 3) * 8;
    float acc[2][8][4] = {};
    for (int k0 = 0; k0 < 64; k0 += 32) {
#pragma unroll
        for (int h = 0; h < 2; h++) {
            int r = arow + h * 64;
            *(uint4*)&As[r][akc] = *(const uint4*)&A[(m0 + r) * 64 + k0 + akc];
            *(uint4*)&Bs[r][akc] = *(const uint4*)&B[(n0 + r) * 64 + k0 + akc];
        }
        __syncthreads();
#pragma unroll
        for (int ks = 0; ks < 32; ks += 16) {
            uint32_t a[2][4];
#pragma unroll
            for (int i = 0; i < 2; i++) {
                int r = wm * 32 + i * 16 + g;
                a[i][0] = *(const uint32_t*)&As[r][ks + 2 * t4];
                a[i][1] = *(const uint32_t*)&As[r + 8][ks + 2 * t4];
                a[i][2] = *(const uint32_t*)&As[r][ks + 2 * t4 + 8];
                a[i][3] = *(const uint32_t*)&As[r + 8][ks + 2 * t4 + 8];
            }
#pragma unroll
            for (int j = 0; j < 8; j++) {
                int n = wn * 64 + j * 8 + g;
                uint32_t b0 = *(const uint32_t*)&Bs[n][ks + 2 * t4];
                uint32_t b1 = *(const uint32_t*)&Bs[n][ks + 2 * t4 + 8];
#pragma unroll
                for (int i = 0; i < 2; i++)
                    mma16816(acc[i][j], a[i], b0, b1);
            }
        }
        __syncthreads();
    }
    float local = 0.f;
#pragma unroll
    for (int i = 0; i < 2; i++) {
#pragma unroll
        for (int j = 0; j < 8; j++) {
            long m = m0 + wm * 32 + i * 16 + g;
            long n = n0 + wn * 64 + j * 8 + 2 * t4;
#pragma unroll
            for (int q = 0; q < 4; q++) {
                long bb = m + (q >> 1) * 8;
                long vv = n + (q & 1);
                if (vv < V_) {
                    float w = bow[(bb * T_ + t) * (long)V_ + vv];
                    local += -logf(acc[i][j][q] + 1e-6f) * w;
                }
            }
        }
    }
    float s = block_sum(local, red);
    if (tid == 0)
        g_part_nll[(blockIdx.z * 2 + blockIdx.y) * 40 + blockIdx.x] = s;
}

// ---------------- generic tiled fp32 GEMM (NT) ----------------
template<bool RELU>
__global__ void gemm_k(const float* __restrict__ A, int lda,
                       const float* __restrict__ Bm, int ldb,
                       const float* __restrict__ bias,
                       float* __restrict__ C, int ldc,
                       int M, int N, int Kd) {
    __shared__ float As[16][65];
    __shared__ float Bs[16][65];
    int tid = threadIdx.x;
    int tx = tid & 15, ty = tid >> 4;
    int m0 = blockIdx.y * 64, n0 = blockIdx.x * 64;
    float acc[4][4] = {};
    for (int k0 = 0; k0 < Kd; k0 += 16) {
#pragma unroll
        for (int i = 0; i < 4; i++) {
            int e = tid + i * 256;
            int m = e >> 4, kk = e & 15;
            int gm = m0 + m, gk = k0 + kk;
            float v = 0.f;
            if (gm < M && gk < Kd) v = A[(long)gm * lda + gk];
            As[kk][m] = v;
        }
#pragma unroll
        for (int i = 0; i < 4; i++) {
            int e = tid + i * 256;
            int n = e >> 4, kk = e & 15;
            int gn = n0 + n, gk = k0 + kk;
            float v = 0.f;
            if (gn < N && gk < Kd) v = Bm[(long)gn * ldb + gk];
            Bs[kk][n] = v;
        }
        __syncthreads();
#pragma unroll
        for (int kk = 0; kk < 16; kk++) {
            float a[4], b[4];
#pragma unroll
            for (int i = 0; i < 4; i++) a[i] = As[kk][ty + 16 * i];
#pragma unroll
            for (int j = 0; j < 4; j++) b[j] = Bs[kk][tx + 16 * j];
#pragma unroll
            for (int i = 0; i < 4; i++)
#pragma unroll
                for (int j = 0; j < 4; j++)
                    acc[i][j] = fmaf(a[i], b[j], acc[i][j]);
        }
        __syncthreads();
    }
#pragma unroll
    for (int i = 0; i < 4; i++) {
        int m = m0 + ty + 16 * i;
        if (m >= M) continue;
#pragma unroll
        for (int j = 0; j < 4; j++) {
            int n = n0 + tx + 16 * j;
            if (n >= N) continue;
            float v = acc[i][j];
            if (bias) v += bias[n];
            if (RELU) v = fmaxf(v, 0.f);
            C[(long)m * ldc + n] = v;
        }
    }
}

// ---------------- RNG / conversions / prep ----------------
__global__ void eps_kernel(unsigned a0, unsigned a1, unsigned e0, unsigned e1,
                           unsigned t0, unsigned t1) {
    int i = blockIdx.x * blockDim.x + threadIdx.x;
    if (i < NA_) {
        g_eps_a[i] = partitionable_normal(a0, a1, (unsigned)i);
    } else if (i < NA_ + NE_) {
        int j = i - NA_;
        g_eps_e[j] = partitionable_normal(e0, e1, (unsigned)j);
    } else if (i < NA_ + 2 * NE_) {
        int j = i - NA_ - NE_;
        g_eps_t[j] = partitionable_normal(t0, t1, (unsigned)j);
    }
}

__global__ void convbf_vec_k(const float* __restrict__ src, int lds,
                             __nv_bfloat16* __restrict__ dst, int ldd, int C) {
    int c = (blockIdx.x * blockDim.x + threadIdx.x) * 8;
    if (c >= ldd) return;
    int r = blockIdx.y;
    const float* s = src + (long)r * lds;
    __nv_bfloat16 tmp[8];
    if (c + 8 <= C) {
        float4 a = *(const float4*)(s + c);
        float4 b = *(const float4*)(s + c + 4);
        tmp[0] = __float2bfloat16(a.x); tmp[1] = __float2bfloat16(a.y);
        tmp[2] = __float2bfloat16(a.z); tmp[3] = __float2bfloat16(a.w);
        tmp[4] = __float2bfloat16(b.x); tmp[5] = __float2bfloat16(b.y);
        tmp[6] = __float2bfloat16(b.z); tmp[7] = __float2bfloat16(b.w);
    } else {
#pragma unroll
        for (int j = 0; j < 8; j++) {
            int cc = c + j;
            tmp[j] = __float2bfloat16(cc < C ? s[cc] : 0.f);
        }
    }
    *(uint4*)&dst[(long)r * ldd + c] = *(uint4*)tmp;
}

__global__ void convbf_row_k(const float* __restrict__ src, int lds,
                             __nv_bfloat16* __restrict__ dst, int ldd, int C) {
    int c = blockIdx.x * blockDim.x + threadIdx.x;
    if (c >= ldd) return;
    int r = blockIdx.y;
    float v = (c < C) ? src[(long)r * lds + c] : 0.f;
    dst[(long)r * ldd + c] = __float2bfloat16(v);
}

__global__ void transpose_bf_k(const float* __restrict__ src,
                               __nv_bfloat16* __restrict__ dst,
                               int R, int C, int ldd) {
    __shared__ float tile[32][33];
    int c0 = blockIdx.x * 32, r0 = blockIdx.y * 32;
#pragma unroll
    for (int i = 0; i < 4; i++) {
        int r = r0 + threadIdx.y + i * 8;
        int c = c0 + threadIdx.x;
        tile[threadIdx.y + i * 8][threadIdx.x] = (r < R && c < C) ? src[(long)r * C + c] : 0.f;
    }
    __syncthreads();
#pragma unroll
    for (int i = 0; i < 4; i++) {
        int orow = c0 + threadIdx.y + i * 8;
        int ocol = r0 + threadIdx.x;
        if (orow < C)
            dst[(long)orow * ldd + ocol] = __float2bfloat16(tile[threadIdx.x][threadIdx.y + i * 8]);
    }
}

__global__ void betaT_k() {
    __shared__ float sm[64][33];
    int t = blockIdx.y;
    int v0 = blockIdx.x * 32;
    int lane = threadIdx.x & 31, w = threadIdx.x >> 5;
    for (int k = w; k < 64; k += 8) {
        int v = v0 + lane;
        sm[k][lane] = (k < K_ && v < V_) ? g_beta[((long)t * K_ + k) * V_ + v] : 0.f;
    }
    __syncthreads();
    int r = threadIdx.x >> 3;
    int c0 = (threadIdx.x & 7) * 8;
    if (v0 + r < V_) {
        __nv_bfloat16 tmp[8];
#pragma unroll
        for (int j = 0; j < 8; j++) tmp[j] = __float2bfloat16(sm[c0 + j][r]);
        *(uint4*)&g_betaT_bf[((long)t * NP_V + v0 + r) * 64 + c0] = *(uint4*)tmp;
    }
}

// fused prep: whhT/wih bf16 (interleaved), bi, wml
__global__ void prep_fused_k(const float* __restrict__ Wih, const float* __restrict__ Whh,
                             const float* __restrict__ bih, const float* __restrict__ bhh,
                             const float* __restrict__ mutW, const float* __restrict__ mutb,
                             const float* __restrict__ lstW, const float* __restrict__ lstb) {
    int idx = blockIdx.x * blockDim.x + threadIdx.x;
    const int S1 = HE_ * 4 * HE_;          // whhT 262144
    const int S2 = S1 + 4 * HE_ * HE_;     // wih
    const int S3 = S2 + 4 * HE_;           // bi
    const int S4 = S3 + 128 * HT_;         // wml
    const int S5 = S4 + 128;               // wmlb
    if (idx < S1) {
        int k = idx >> 10, r = idx & 1023;
        int j = r >> 2, gate = r & 3;
        g_whhT_bf[idx] = __float2bfloat16(Whh[((long)(gate * HE_ + j)) * HE_ + k]);
    } else if (idx < S2) {
        int i = idx - S1;
        int r = i >> 8, k = i & 255;
        int j = r >> 2, gate = r & 3;
        g_wih_bf[i] = __float2bfloat16(Wih[((long)(gate * HE_ + j)) * HE_ + k]);
    } else if (idx < S3) {
        int r = idx - S2;
        int j = r >> 2, gate = r & 3;
        g_bi_int[r] = bih[gate * HE_ + j] + bhh[gate * HE_ + j];
    } else if (idx < S4) {
        int i = idx - S3;
        int row = i / HT_, k = i % HT_;
        float v = 0.f;
        if (row < 50) v = mutW[(long)row * HT_ + k];
        else if (row < 100) v = lstW[(long)(row - 50) * HT_ + k];
        g_wml_bf[i] = __float2bfloat16(v);
    } else if (idx < S5) {
        int r = idx - S4;
        g_wmlb[r] = (r < 50) ? mutb[r] : (r < 100 ? lstb[r - 50] : 0.f);
    }
}

__global__ void alphas_kernel(const float* __restrict__ muq, const float* __restrict__ lsq) {
    int idx = blockIdx.x * blockDim.x + threadIdx.x;
    if (idx >= NA_) return;
    int t = idx / (K_ * RHO_), rem = idx % (K_ * RHO_);
    int k = rem / RHO_, r = rem % RHO_;
    int src = (k * T_ + t) * RHO_ + r;
    float a = muq[src] + g_eps_a[idx] * expf(0.5f * lsq[src]);
    g_alphas[idx] = a;
    int row = t * K_ + k;
    g_alphas_bf[(long)row * KP_RHO + r] = __float2bfloat16(a);
}

__global__ void kld_alpha_kernel(const float* __restrict__ muq, const float* __restrict__ lsq) {
    __shared__ float red[256];
    float acc = 0.f;
    for (int idx = blockIdx.x * blockDim.x + threadIdx.x; idx < NA_;
         idx += gridDim.x * blockDim.x) {
        int t = idx / (K_ * RHO_), rem = idx % (K_ * RHO_);
        int k = rem / RHO_, r = rem % RHO_;
        int src = (k * T_ + t) * RHO_ + r;
        float mu = muq[src];
        float ls = lsq[src];
        float qls = fminf(fmaxf(ls, -100.f), 100.f);
        float pmu = (t == 0) ? 0.f : g_alphas[idx - K_ * RHO_];
        float pls = (t == 0) ? 0.f : LOGD;
        float d = mu - pmu;
        acc += (expf(qls) + d * d) / (expf(pls) + 1e-6f) - 1.f + pls - qls;
    }
    float s = block_sum(acc, red);
    if (threadIdx.x == 0) g_part_a[blockIdx.x] = s;
}

__global__ void softmax_rows_kernel() {
    __shared__ float red[256];
    long base = (long)blockIdx.x * V_;
    long basebf = (long)blockIdx.x * KP_V;
    int tid = threadIdx.x;
    float m = -FLT_MAX;
    for (int c = tid; c < V_; c += 256) m = fmaxf(m, g_beta[base + c]);
    m = block_max(m, red);
    float s = 0.f;
    for (int c = tid; c < V_; c += 256) {
        float e = expf(g_beta[base + c] - m);
        g_beta[base + c] = e; s += e;
    }
    s = block_sum(s, red);
    float inv = 1.f / s;
    for (int c = tid; c < V_; c += 256) {
        float b = g_beta[base + c] * inv;
        g_beta[base + c] = b;
        g_beta_bf[basebf + c] = __float2bfloat16(b);
    }
}

__global__ void combine_inp_k(const float* __restrict__ qeb) {
    int idx = blockIdx.x * blockDim.x + threadIdx.x;
    if (idx >= B_ * T_ * HE_) return;
    int j = idx & (HE_ - 1);
    float s = qeb[j];
#pragma unroll
    for (int z = 0; z < INP_SPLIT; z++) s += g_inp_part[(long)z * B_ * T_ * HE_ + idx];
    g_inp_bf[idx] = __float2bfloat16(s);
}

// ---------------- single-launch LSTM scan: 128 blocks x 2 batch rows ----------------
__global__ void __launch_bounds__(256) lstm_scan_k() {
    __shared__ float h[2][HE_];
    int j = threadIdx.x;
    int b0 = 2 * blockIdx.x, b1 = b0 + 1;
    float c0 = 0.f, c1 = 0.f;
    h[0][j] = 0.f; h[1][j] = 0.f;
    __syncthreads();
    const uint2* wT = (const uint2*)g_whhT_bf;   // [k][256] uint2 (4 bf16 = gates of j)
    for (int t = 0; t < T_; t++) {
        float a00 = 0.f, a10 = 0.f, a20 = 0.f, a30 = 0.f;
        float a01 = 0.f, a11 = 0.f, a21 = 0.f, a31 = 0.f;
#pragma unroll 4
        for (int k = 0; k < HE_; k++) {
            uint2 w = wT[k * 256 + j];
            float2 w01 = __bfloat1622float2(*(const __nv_bfloat162*)&w.x);
            float2 w23 = __bfloat1622float2(*(const __nv_bfloat162*)&w.y);
            float hb0 = h[0][k], hb1 = h[1][k];
            a00 = fmaf(w01.x, hb0, a00); a10 = fmaf(w01.y, hb0, a10);
            a20 = fmaf(w23.x, hb0, a20); a30 = fmaf(w23.y, hb0, a30);
            a01 = fmaf(w01.x, hb1, a01); a11 = fmaf(w01.y, hb1, a11);
            a21 = fmaf(w23.x, hb1, a21); a31 = fmaf(w23.y, hb1, a31);
        }
        __syncthreads();
        {
            float4 gx4 = *(const float4*)&g_gx[((long)b0 * T_ + t) * (4 * HE_) + 4 * j];
            float gi = gx4.x + a00, gf = gx4.y + a10, gg = gx4.z + a20, go = gx4.w + a30;
            float si = 1.f / (1.f + expf(-gi));
            float sf = 1.f / (1.f + expf(-gf));
            float so = 1.f / (1.f + expf(-go));
            c0 = sf * c0 + si * tanhf(gg);
            float hh = so * tanhf(c0);
            h[0][j] = hh;
            g_lstm[((long)t * B_ + b0) * HE_ + j] = hh;
        }
        {
            float4 gx4 = *(const float4*)&g_gx[((long)b1 * T_ + t) * (4 * HE_) + 4 * j];
            float gi = gx4.x + a01, gf = gx4.y + a11, gg = gx4.z + a21, go = gx4.w + a31;
            float si = 1.f / (1.f + expf(-gi));
            float sf = 1.f / (1.f + expf(-gf));
            float so = 1.f / (1.f + expf(-go));
            c1 = sf * c1 + si * tanhf(gg);
            float hh = so * tanhf(c1);
            h[1][j] = hh;
            g_lstm[((long)t * B_ + b1) * HE_ + j] = hh;
        }
        __syncthreads();
    }
}

// ---------------- single-launch eta scan: 64 blocks x 4 batch rows ----------------
// dyn smem: wsm bf16[100*306] | z f32[4*306] | smu f32[200] | sls f32[200] | skl f32[200]
#define ETA_SMEM (100*306*2 + (4*306 + 200 + 200 + 200) * 4)
__global__ void __launch_bounds__(256) eta_scan_k(
    const float* __restrict__ mueW, const float* __restrict__ mueb,
    const float* __restrict__ lseW, const float* __restrict__ lseb) {
    extern __shared__ char smc[];
    __nv_bfloat16* wsm = (__nv_bfloat16*)smc;
    float* z   = (float*)(smc + 100 * 306 * 2);
    float* smu = z + 4 * 306;
    float* sls = smu + 200;
    float* skl = sls + 200;
    int tid = threadIdx.x, bk = blockIdx.x;
    for (int i = tid; i < 100 * 306; i += 256) {
        int r = i / 306, k = i % 306;
        float v = (r < 50) ? mueW[(long)r * HEK_ + k] : lseW[(long)(r - 50) * HEK_ + k];
        wsm[i] = __float2bfloat16(v);
    }
    if (tid < 200) {
        int q = tid / 50, k = tid % 50;
        z[q * 306 + 256 + k] = 0.f;   // eta_prev = 0
    }
    __syncthreads();
    for (int t = 0; t < T_; t++) {
#pragma unroll
        for (int q = 0; q < 4; q++)
            z[q * 306 + tid] = g_lstm[((long)t * B_ + 4 * bk + q) * HE_ + tid];
        __syncthreads();
#pragma unroll
        for (int rep = 0; rep < 2; rep++) {
            int o = tid + rep * 256;
            if (o < 400) {
                int q = o / 100, r = o % 100;
                float acc = (r < 50) ? mueb[r] : lseb[r - 50];
                const __nv_bfloat16* wr = wsm + r * 306;
                const float* zq = z + q * 306;
#pragma unroll 2
                for (int k = 0; k < HEK_; k++)
                    acc = fmaf(__bfloat162float(wr[k]), zq[k], acc);
                if (r < 50) smu[q * 50 + r] = acc;
                else        sls[q * 50 + (r - 50)] = acc;
            }
        }
        __syncthreads();
        if (tid < 200) {
            int q = tid / 50, k = tid % 50;
            int b = 4 * bk + q;
            float mu = smu[q * 50 + k], ls = sls[q * 50 + k];
            float pmu = z[q * 306 + 256 + k];
            float eps = g_eps_e[((long)t * B_ + b) * K_ + k];
            float eta = mu + eps * expf(0.5f * ls);
            g_etas[((long)t * B_ + b) * K_ + k] = eta;
            float qls = fminf(fmaxf(ls, -100.f), 100.f);
            float pls = (t == 0) ? 0.f : LOGD;
            float d = mu - pmu;
            skl[tid] = (expf(qls) + d * d) / (expf(pls) + 1e-6f) - 1.f + pls - qls;
            z[q * 306 + 256 + k] = eta;
        }
        __syncthreads();
        if (tid < 4) {
            float s = 0.f;
            for (int k = 0; k < 50; k++) s += skl[tid * 50 + k];
            g_part_ke[t * B_ + 4 * bk + tid] = s;
        }
        __syncthreads();
    }
}

// h1 = relu(h1e + sum_z h1b_part) -> bf16
__global__ void combine_h1_kernel() {
    int j = blockIdx.x * blockDim.x + threadIdx.x;
    if (j >= HT_) return;
    int row = blockIdx.y;
    int b = row & (B_ - 1);
    float hb = 0.f;
#pragma unroll
    for (int z = 0; z < H1B_SPLIT; z++) hb += g_h1b_part[(long)z * B_ * HT_ + b * HT_ + j];
    long idx = (long)row * HT_ + j;
    float v = fmaxf(g_h1e[idx] + hb, 0.f);
    g_h1_bf[idx] = __float2bfloat16(v);
}

__global__ void theta_kernel() {
    __shared__ float red[64];
    int row = blockIdx.x, k = threadIdx.x;
    long base = (long)row * K_;
    long mbase = (long)row * 100;
    bool val = k < K_;
    float mu = 0.f, ls = 0.f, zv = -FLT_MAX;
    if (val) {
        mu = g_mls[mbase + k];
        ls = g_mls[mbase + 50 + k];
        zv = mu + g_eps_t[base + k] * expf(0.5f * ls);
    }
    float mx = block_max(zv, red);
    float e = val ? expf(zv - mx) : 0.f;
    float sum = block_sum(e, red);
    float th = e / sum;
    if (val) {
        g_theta_arr[base + k] = th;
        g_theta_bf[(long)row * 64 + k] = __float2bfloat16(th);
    } else if (k < 64) {
        g_theta_bf[(long)row * 64 + k] = __float2bfloat16(0.f);
    }
    float kl = 0.f;
    if (val) {
        float qls = fminf(fmaxf(ls, -100.f), 100.f);
        float d = mu - g_etas[base + k];
        kl = (expf(qls) + d * d) / (1.f + 1e-6f) - 1.f - qls;
    }
    float s = block_sum(kl, red);
    if (k == 0) g_part_kt[row] = s;
}

__global__ void final_reduce_kernel(float* out, int out_size) {
    __shared__ float red[256];
    int tid = threadIdx.x;
    float v;
    v = 0.f; for (int i = tid; i < RB_NLL;  i += 256) v += g_part_nll[i];
    float nll  = block_sum(v, red) * (10.0f / B_);
    v = 0.f; for (int i = tid; i < T_ * B_; i += 256) v += g_part_kt[i];
    float kt   = block_sum(v, red) * (0.5f / (T_ * B_));
    v = 0.f; for (int i = tid; i < RB_A;    i += 256) v += g_part_a[i];
    float ka   = block_sum(v, red) * (0.5f / (T_ * K_));
    v = 0.f; for (int i = tid; i < T_ * B_; i += 256) v += g_part_ke[i];
    float ke   = block_sum(v, red) * (0.5f / B_);
    v = 0.f; for (int i = tid; i < RB_COND; i += 256) v += g_part_cond[i];
    float cond = block_sum(v, red) * (-0.01f);
    if (tid == 0) {
        if (out_size > 0) out[0] = nll;
        if (out_size > 1) out[1] = kt;
        if (out_size > 2) out[2] = ka;
        if (out_size > 3) out[3] = ke;
        if (out_size > 4) out[4] = cond;
    }
}

// ---------------- host driver ----------------
static inline int ceil_div(long a, long b) { return (int)((a + b - 1) / b); }

extern "C" void kernel_launch(void* const* d_in, const int* in_sizes, int n_in,
                              void* d_out, int out_size) {
    (void)in_sizes; (void)n_in;
    const float* nb   = (const float*)d_in[0];
    const float* bow  = (const float*)d_in[1];
    const float* adj  = (const float*)d_in[2];
    const float* muqa = (const float*)d_in[3];
    const float* lsqa = (const float*)d_in[4];
    const float* rhoW = (const float*)d_in[5];
    const float* rhob = (const float*)d_in[6];
    const float* W1   = (const float*)d_in[7];
    const float* b1   = (const float*)d_in[8];
    const float* W2   = (const float*)d_in[9];
    const float* b2   = (const float*)d_in[10];
    const float* mutW = (const float*)d_in[11];
    const float* mutb = (const float*)d_in[12];
    const float* lstW = (const float*)d_in[13];
    const float* lstb = (const float*)d_in[14];
    const float* qeW  = (const float*)d_in[15];
    const float* qeb  = (const float*)d_in[16];
    const float* Wih  = (const float*)d_in[17];
    const float* Whh  = (const float*)d_in[18];
    const float* bih  = (const float*)d_in[19];
    const float* bhh  = (const float*)d_in[20];
    const float* mueW = (const float*)d_in[21];
    const float* mueb = (const float*)d_in[22];
    const float* lseW = (const float*)d_in[23];
    const float* lseb = (const float*)d_in[24];
    float* out = (float*)d_out;

    unsigned ka0, ka1, ke0, ke1, kt0, kt1;
    tf2x32(0u, 42u, 0u, 0u, &ka0, &ka1);
    tf2x32(0u, 42u, 0u, 1u, &ke0, &ke1);
    tf2x32(0u, 42u, 0u, 2u, &kt0, &kt1);

    float *p_beta, *p_inp_part, *p_gx, *p_etas, *p_h1e, *p_h1b_part, *p_mls;
    float *p_bi_int, *p_part_cond, *p_wmlb;
    __nv_bfloat16 *p_alphas_bf, *p_beta_bf, *p_adjT, *p_bow_bf, *p_qew_bf, *p_nb_bf;
    __nv_bfloat16 *p_w1_bf, *p_rhow_bf, *p_w2_bf, *p_wml_bf, *p_h1_bf, *p_h2_bf;
    __nv_bfloat16 *p_inp_bf, *p_wih_bf;
    cudaGetSymbolAddress((void**)&p_beta,      g_beta);
    cudaGetSymbolAddress((void**)&p_inp_part,  g_inp_part);
    cudaGetSymbolAddress((void**)&p_gx,        g_gx);
    cudaGetSymbolAddress((void**)&p_etas,      g_etas);
    cudaGetSymbolAddress((void**)&p_h1e,       g_h1e);
    cudaGetSymbolAddress((void**)&p_h1b_part,  g_h1b_part);
    cudaGetSymbolAddress((void**)&p_mls,       g_mls);
    cudaGetSymbolAddress((void**)&p_bi_int,    g_bi_int);
    cudaGetSymbolAddress((void**)&p_part_cond, g_part_cond);
    cudaGetSymbolAddress((void**)&p_wmlb,      g_wmlb);
    cudaGetSymbolAddress((void**)&p_alphas_bf, g_alphas_bf);
    cudaGetSymbolAddress((void**)&p_beta_bf,   g_beta_bf);
    cudaGetSymbolAddress((void**)&p_adjT,      g_adjT_bf);
    cudaGetSymbolAddress((void**)&p_bow_bf,    g_bow_bf);
    cudaGetSymbolAddress((void**)&p_qew_bf,    g_qew_bf);
    cudaGetSymbolAddress((void**)&p_nb_bf,     g_nb_bf);
    cudaGetSymbolAddress((void**)&p_w1_bf,     g_w1_bf);
    cudaGetSymbolAddress((void**)&p_rhow_bf,   g_rhow_bf);
    cudaGetSymbolAddress((void**)&p_w2_bf,     g_w2_bf);
    cudaGetSymbolAddress((void**)&p_wml_bf,    g_wml_bf);
    cudaGetSymbolAddress((void**)&p_h1_bf,     g_h1_bf);
    cudaGetSymbolAddress((void**)&p_h2_bf,     g_h2_bf);
    cudaGetSymbolAddress((void**)&p_inp_bf,    g_inp_bf);
    cudaGetSymbolAddress((void**)&p_wih_bf,    g_wih_bf);

    cudaFuncSetAttribute(tc_gemm_k<true,  false, false, false>, cudaFuncAttributeMaxDynamicSharedMemorySize, TC_SMEM_BYTES);
    cudaFuncSetAttribute(tc_gemm_k<false, false, false, true >, cudaFuncAttributeMaxDynamicSharedMemorySize, TC_SMEM_BYTES);
    cudaFuncSetAttribute(tc_gemm_k<false, false, false, false>, cudaFuncAttributeMaxDynamicSharedMemorySize, TC_SMEM_BYTES);
    cudaFuncSetAttribute(tc_gemm_k<true,  true,  true,  false>, cudaFuncAttributeMaxDynamicSharedMemorySize, TC_SMEM_BYTES);
    cudaFuncSetAttribute(eta_scan_k, cudaFuncAttributeMaxDynamicSharedMemorySize, ETA_SMEM);

    // ---- alpha/beta chain first (4th launch = pipelined beta TC GEMM, for ncu) ----
    convbf_vec_k<<<dim3(ceil_div(KP_RHO / 8, 256), V_), 256>>>(rhoW, RHO_, p_rhow_bf, KP_RHO, RHO_);
    int totalElems = NA_ + 2 * NE_;
    eps_kernel<<<(totalElems + 255) / 256, 256>>>(ka0, ka1, ke0, ke1, kt0, kt1);
    alphas_kernel<<<(NA_ + 255) / 256, 256>>>(muqa, lsqa);
    tc_gemm_k<true, false, false, false><<<dim3(ceil_div(V_, 128), ceil_div(T_ * K_, 128)), 256, TC_SMEM_BYTES>>>(
        p_alphas_bf, KP_RHO, p_rhow_bf, KP_RHO, rhob, p_beta, nullptr, V_,
        nullptr, nullptr, T_ * K_, V_, KP_RHO);
    kld_alpha_kernel<<<RB_A, 256>>>(muqa, lsqa);
    softmax_rows_kernel<<<T_ * K_, 256>>>();
    betaT_k<<<dim3(ceil_div(V_, 32), T_), 256>>>();
    transpose_bf_k<<<dim3(ceil_div(V_, 32), ceil_div(V_, 32)), dim3(32, 8)>>>(adj, p_adjT, V_, V_, KP_V);
    tc_gemm_k<false, false, false, true><<<dim3(ceil_div(V_, 128), ceil_div(T_ * K_, 128)), 256, TC_SMEM_BYTES>>>(
        p_beta_bf, KP_V, p_adjT, KP_V, nullptr, nullptr, nullptr, V_,
        p_beta, p_part_cond, T_ * K_, V_, KP_V);

    // ---- conversions + prep ----
    convbf_vec_k<<<dim3(ceil_div(KP_V / 8, 256), B_ * T_), 256>>>(bow, V_, p_bow_bf, KP_V, V_);
    convbf_vec_k<<<dim3(ceil_div(KP_V / 8, 256), HE_), 256>>>(qeW, V_, p_qew_bf, KP_V, V_);
    convbf_vec_k<<<dim3(ceil_div(KP_V / 8, 256), B_), 256>>>(nb, V_, p_nb_bf, KP_V, V_);
    convbf_row_k<<<dim3(ceil_div(KP_V, 256), HT_), 256>>>(W1, VK_, p_w1_bf, KP_V, V_);
    convbf_vec_k<<<dim3(ceil_div(HT_ / 8, 256), HT_), 256>>>(W2, HT_, p_w2_bf, HT_, HT_);
    {
        int preptotal = HE_ * 4 * HE_ + 4 * HE_ * HE_ + 4 * HE_ + 128 * HT_ + 128;
        prep_fused_k<<<(preptotal + 255) / 256, 256>>>(Wih, Whh, bih, bhh, mutW, mutb, lstW, lstb);
    }

    // ---- inp (split-K) -> bf16 combine -> gx (TC) -> LSTM scan -> eta scan ----
    tc_gemm_k<false, false, false, false><<<dim3(ceil_div(HE_, 128), ceil_div(B_ * T_, 128), INP_SPLIT), 256, TC_SMEM_BYTES>>>(
        p_bow_bf, KP_V, p_qew_bf, KP_V, nullptr, p_inp_part, nullptr, HE_,
        nullptr, nullptr, B_ * T_, HE_, KP_V);
    combine_inp_k<<<ceil_div(B_ * T_ * HE_, 256), 256>>>(qeb);
    tc_gemm_k<true, false, false, false><<<dim3(8, 24), 256, TC_SMEM_BYTES>>>(
        p_inp_bf, HE_, p_wih_bf, HE_, p_bi_int, p_gx, nullptr, 4 * HE_,
        nullptr, nullptr, B_ * T_, 4 * HE_, HE_);
    lstm_scan_k<<<128, 256>>>();
    eta_scan_k<<<64, 256, ETA_SMEM>>>(mueW, mueb, lseW, lseb);

    // ---- theta encoder ----
    gemm_k<false><<<dim3(13, 48), 256>>>(
        p_etas, K_, W1 + V_, VK_, b1, p_h1e, HT_, T_ * B_, HT_, K_);
    tc_gemm_k<false, false, false, false><<<dim3(ceil_div(HT_, 128), ceil_div(B_, 128), H1B_SPLIT), 256, TC_SMEM_BYTES>>>(
        p_nb_bf, KP_V, p_w1_bf, KP_V, nullptr, p_h1b_part, nullptr, HT_,
        nullptr, nullptr, B_, HT_, KP_V);
    combine_h1_kernel<<<dim3(ceil_div(HT_, 256), T_ * B_), 256>>>();
    tc_gemm_k<true, true, true, false><<<dim3(ceil_div(HT_, 128), ceil_div(T_ * B_, 128)), 256, TC_SMEM_BYTES>>>(
        p_h1_bf, HT_, p_w2_bf, HT_, b2, nullptr, p_h2_bf, HT_,
        nullptr, nullptr, T_ * B_, HT_, HT_);
    tc_gemm_k<true, false, false, false><<<dim3(1, ceil_div(T_ * B_, 128)), 256, TC_SMEM_BYTES>>>(
        p_h2_bf, HT_, p_wml_bf, HT_, p_wmlb, p_mls, nullptr, 100,
        nullptr, nullptr, T_ * B_, 100, HT_);

    // ---- theta + NLL + final ----
    theta_kernel<<<T_ * B_, 64>>>();
    tc_nll_k<<<dim3(40, 2, T_), 256>>>(bow);
    final_reduce_kernel<<<1, 256>>>(out, out_size);
}

// round 13
// speedup vs baseline: 4.7051x; 1.0190x over previous
#include <cuda_runtime.h>
#include <cuda_bf16.h>
#include <cstdint>
#include <float.h>
#include <math.h>

// ---------------- problem constants ----------------
#define T_    12
#define K_    50
#define V_    5000
#define B_    256
#define RHO_  300
#define HT_   800
#define HE_   256
#define VK_   (V_ + K_)
#define HEK_  (HE_ + K_)   // 306
#define LOGD  (-5.2983173665480363f)

#define NA_   (T_*K_*RHO_)
#define NE_   (T_*B_*K_)

#define KP_V   5024
#define KP_RHO 320
#define NP_V   5120
#define MP_TK  640

#define INP_SPLIT 6
#define H1B_SPLIT 12

// ---------------- device scratch ----------------
__device__ float g_eps_a[NA_];
__device__ float g_eps_e[NE_];
__device__ float g_eps_t[NE_];
__device__ float g_alphas[NA_];
__device__ __align__(16) __nv_bfloat16 g_alphas_bf[MP_TK*KP_RHO];
__device__ float g_beta[T_*K_*V_];
__device__ __align__(16) __nv_bfloat16 g_beta_bf[MP_TK*KP_V];
__device__ __align__(16) __nv_bfloat16 g_betaT_bf[T_*NP_V*64];
__device__ __align__(16) __nv_bfloat16 g_adjT_bf[NP_V*KP_V];
__device__ __align__(16) __nv_bfloat16 g_bow_bf[B_*T_*KP_V];
__device__ __align__(16) __nv_bfloat16 g_qew_bf[HE_*KP_V];
__device__ __align__(16) __nv_bfloat16 g_nb_bf[B_*KP_V];
__device__ __align__(16) __nv_bfloat16 g_w1_bf[896*KP_V];
__device__ __align__(16) __nv_bfloat16 g_rhow_bf[NP_V*KP_RHO];
__device__ __align__(16) __nv_bfloat16 g_w2_bf[896*HT_];
__device__ __align__(16) __nv_bfloat16 g_wml_bf[128*HT_];
__device__ float g_wmlb[128];
__device__ __align__(16) __nv_bfloat16 g_whhT_bf[HE_*4*HE_];   // [k][1024] interleaved j*4+gate
__device__ __align__(16) __nv_bfloat16 g_wih_bf[4*HE_*HE_];    // [1024 rows j*4+g][k=256]
__device__ float g_bi_int[4*HE_];
__device__ __align__(16) __nv_bfloat16 g_inp_bf[B_*T_*HE_];
__device__ float g_inp_part[INP_SPLIT*B_*T_*HE_];
__device__ float g_gx[B_*T_*4*HE_];
__device__ float g_lstm[T_*B_*HE_];
__device__ float g_etas[NE_];
__device__ float g_h1e[T_*B_*HT_];
__device__ float g_h1b_part[H1B_SPLIT*B_*HT_];
__device__ __align__(16) __nv_bfloat16 g_h1_bf[T_*B_*HT_];
__device__ __align__(16) __nv_bfloat16 g_h2_bf[T_*B_*HT_];
__device__ float g_mls[T_*B_*100];
__device__ float g_theta_arr[NE_];
__device__ __align__(16) __nv_bfloat16 g_theta_bf[T_*B_*64];

#define RB_NLL  (12*2*40)
#define RB_COND 200
#define RB_A    256
__device__ float g_part_nll[RB_NLL];
__device__ float g_part_cond[RB_COND];
__device__ float g_part_a[RB_A];
__device__ float g_part_kt[T_*B_];
__device__ float g_part_ke[T_*B_];

// ---------------- threefry2x32 (JAX partitionable) ----------------
__host__ __device__ inline void tf2x32(unsigned k0, unsigned k1,
                                       unsigned x0, unsigned x1,
                                       unsigned* o0, unsigned* o1) {
    unsigned ks0 = k0, ks1 = k1, ks2 = k0 ^ k1 ^ 0x1BD11BDAu;
    x0 += ks0; x1 += ks1;
#define TF_R(r) { x0 += x1; x1 = (x1 << (r)) | (x1 >> (32 - (r))); x1 ^= x0; }
    TF_R(13) TF_R(15) TF_R(26) TF_R(6)
    x0 += ks1; x1 += ks2 + 1u;
    TF_R(17) TF_R(29) TF_R(16) TF_R(24)
    x0 += ks2; x1 += ks0 + 2u;
    TF_R(13) TF_R(15) TF_R(26) TF_R(6)
    x0 += ks0; x1 += ks1 + 3u;
    TF_R(17) TF_R(29) TF_R(16) TF_R(24)
    x0 += ks1; x1 += ks2 + 4u;
    TF_R(13) TF_R(15) TF_R(26) TF_R(6)
    x0 += ks2; x1 += ks0 + 5u;
#undef TF_R
    *o0 = x0; *o1 = x1;
}

__device__ __forceinline__ float bits2normal(unsigned bits) {
    float f = __uint_as_float((bits >> 9) | 0x3F800000u) - 1.0f;
    const float lo = -0.99999994f;
    float u = fmaf(f, 2.0f, lo);
    u = fmaxf(lo, u);
    return 1.4142135381698608f * erfinvf(u);
}

__device__ __forceinline__ float partitionable_normal(unsigned k0, unsigned k1, unsigned i) {
    unsigned o0, o1;
    tf2x32(k0, k1, 0u, i, &o0, &o1);
    return bits2normal(o0 ^ o1);
}

// ---------------- block reductions ----------------
__device__ __forceinline__ float block_sum(float v, float* red) {
    int tid = threadIdx.x, n = blockDim.x;
    red[tid] = v; __syncthreads();
    for (int s = n >> 1; s > 0; s >>= 1) {
        if (tid < s) red[tid] += red[tid + s];
        __syncthreads();
    }
    v = red[0]; __syncthreads();
    return v;
}
__device__ __forceinline__ float block_max(float v, float* red) {
    int tid = threadIdx.x, n = blockDim.x;
    red[tid] = v; __syncthreads();
    for (int s = n >> 1; s > 0; s >>= 1) {
        if (tid < s) red[tid] = fmaxf(red[tid], red[tid + s]);
        __syncthreads();
    }
    v = red[0]; __syncthreads();
    return v;
}

// ---------------- mma + cp.async helpers ----------------
__device__ __forceinline__ void mma16816(float* c, const uint32_t* a, uint32_t b0, uint32_t b1) {
    asm volatile(
        "mma.sync.aligned.m16n8k16.row.col.f32.bf16.bf16.f32 "
        "{%0,%1,%2,%3}, {%4,%5,%6,%7}, {%8,%9}, {%0,%1,%2,%3};\n"
        : "+f"(c[0]), "+f"(c[1]), "+f"(c[2]), "+f"(c[3])
        : "r"(a[0]), "r"(a[1]), "r"(a[2]), "r"(a[3]), "r"(b0), "r"(b1));
}
#define CPASYNC16(sp, gp) \
    asm volatile("cp.async.cg.shared.global [%0], [%1], 16;\n" \
        :: "r"((unsigned)__cvta_generic_to_shared(sp)), "l"(gp))
#define CPCOMMIT() asm volatile("cp.async.commit_group;\n")
#define CPWAIT(n)  asm volatile("cp.async.wait_group %0;\n" :: "n"(n))

#define CHUNK_ELEMS (128 * 40)
#define TC_SMEM_BYTES (2 * 4 * CHUNK_ELEMS * 2)   // 4-chunk ring, 2 operands: 81920 B

// ---------------- pipelined bf16 TC GEMM (NT), 2 chunks per barrier epoch ----------------
template<bool BIAS, bool RELU, bool OUTBF, bool CONDEPI>
__global__ void __launch_bounds__(256, 2) tc_gemm_k(
    const __nv_bfloat16* __restrict__ A, int lda,
    const __nv_bfloat16* __restrict__ B, int ldb,
    const float* __restrict__ bias,
    float* __restrict__ C, __nv_bfloat16* __restrict__ Cbf, int ldc,
    const float* __restrict__ Cf, float* __restrict__ part,
    int M, int N, int Kp) {
    extern __shared__ __nv_bfloat16 smp[];
    __nv_bfloat16* As = smp;                      // 4 × [128][40]
    __nv_bfloat16* Bs = smp + 4 * CHUNK_ELEMS;
    __shared__ float red[256];
    int tid = threadIdx.x;
    int lane = tid & 31, wid = tid >> 5;
    int wm = wid & 3, wn = wid >> 2;
    int g = lane >> 2, t4 = lane & 3;
    long m0 = (long)blockIdx.y * 128, n0 = (long)blockIdx.x * 128;
    int arow = tid >> 2;
    int akc = (tid & 3) * 8;
    float acc[2][8][4] = {};

    int nkt = Kp >> 5;
    int per = (nkt + gridDim.z - 1) / gridDim.z;
    int it0 = blockIdx.z * per;
    int itn = nkt - it0; if (itn > per) itn = per; if (itn < 0) itn = 0;

#define TC_ISSUE(IT, S) do {                                                     \
        int _k = ((IT) << 5) + akc;                                              \
        __nv_bfloat16* _as = As + (size_t)(S) * CHUNK_ELEMS;                     \
        __nv_bfloat16* _bs = Bs + (size_t)(S) * CHUNK_ELEMS;                     \
        CPASYNC16(&_as[(size_t)arow * 40 + akc],        &A[(m0 + arow) * (long)lda + _k]);        \
        CPASYNC16(&_as[(size_t)(arow + 64) * 40 + akc], &A[(m0 + arow + 64) * (long)lda + _k]);   \
        CPASYNC16(&_bs[(size_t)arow * 40 + akc],        &B[(n0 + arow) * (long)ldb + _k]);        \
        CPASYNC16(&_bs[(size_t)(arow + 64) * 40 + akc], &B[(n0 + arow + 64) * (long)ldb + _k]);   \
        CPCOMMIT();                                                              \
    } while (0)

    int npre = itn < 4 ? itn : 4;
    for (int p = 0; p < npre; p++) TC_ISSUE(it0 + p, p);

    for (int e = 0; e < itn; e += 2) {
        if (itn - e > 4) { CPWAIT(2); } else { CPWAIT(0); }
        __syncthreads();
#pragma unroll
        for (int u = 0; u < 2; u++) {
            int ce = e + u;
            if (ce < itn) {
                const __nv_bfloat16* Asb = As + (size_t)(ce & 3) * CHUNK_ELEMS;
                const __nv_bfloat16* Bsb = Bs + (size_t)(ce & 3) * CHUNK_ELEMS;
#pragma unroll
                for (int ks = 0; ks < 32; ks += 16) {
                    uint32_t a[2][4];
#pragma unroll
                    for (int i = 0; i < 2; i++) {
                        int r = wm * 32 + i * 16 + g;
                        a[i][0] = *(const uint32_t*)&Asb[(size_t)r * 40 + ks + 2 * t4];
                        a[i][1] = *(const uint32_t*)&Asb[(size_t)(r + 8) * 40 + ks + 2 * t4];
                        a[i][2] = *(const uint32_t*)&Asb[(size_t)r * 40 + ks + 2 * t4 + 8];
                        a[i][3] = *(const uint32_t*)&Asb[(size_t)(r + 8) * 40 + ks + 2 * t4 + 8];
                    }
#pragma unroll
                    for (int j = 0; j < 8; j++) {
                        int n = wn * 64 + j * 8 + g;
                        uint32_t b0 = *(const uint32_t*)&Bsb[(size_t)n * 40 + ks + 2 * t4];
                        uint32_t b1 = *(const uint32_t*)&Bsb[(size_t)n * 40 + ks + 2 * t4 + 8];
#pragma unroll
                        for (int i = 0; i < 2; i++)
                            mma16816(acc[i][j], a[i], b0, b1);
                    }
                }
            }
        }
        __syncthreads();
        if (e + 4 < itn) TC_ISSUE(it0 + e + 4, e & 3);
        if (e + 5 < itn) TC_ISSUE(it0 + e + 5, (e + 1) & 3);
    }
#undef TC_ISSUE

    if (CONDEPI) {
        float local = 0.f;
#pragma unroll
        for (int i = 0; i < 2; i++) {
#pragma unroll
            for (int j = 0; j < 8; j++) {
                long m = m0 + wm * 32 + i * 16 + g;
                long n = n0 + wn * 64 + j * 8 + 2 * t4;
                if (m < M) {
                    if (n < N)     local += acc[i][j][0] * Cf[m * ldc + n];
                    if (n + 1 < N) local += acc[i][j][1] * Cf[m * ldc + n + 1];
                }
                if (m + 8 < M) {
                    if (n < N)     local += acc[i][j][2] * Cf[(m + 8) * ldc + n];
                    if (n + 1 < N) local += acc[i][j][3] * Cf[(m + 8) * ldc + n + 1];
                }
            }
        }
        float s = block_sum(local, red);
        if (tid == 0) part[blockIdx.y * gridDim.x + blockIdx.x] = s;
    } else {
        float* Cz = C ? C + (long)blockIdx.z * M * ldc : nullptr;
#pragma unroll
        for (int i = 0; i < 2; i++) {
#pragma unroll
            for (int j = 0; j < 8; j++) {
                long m = m0 + wm * 32 + i * 16 + g;
                long n = n0 + wn * 64 + j * 8 + 2 * t4;
#pragma unroll
                for (int q = 0; q < 4; q++) {
                    long mm = m + (q >> 1) * 8;
                    long nn = n + (q & 1);
                    if (mm < M && nn < N) {
                        float v = acc[i][j][q];
                        if (BIAS) v += bias[nn];
                        if (RELU) v = fmaxf(v, 0.f);
                        if (OUTBF) Cbf[mm * ldc + nn] = __float2bfloat16(v);
                        else       Cz[mm * ldc + nn] = v;
                    }
                }
            }
        }
    }
}

// ---------------- TC NLL ----------------
__global__ void __launch_bounds__(256) tc_nll_k(const float* __restrict__ bow) {
    __shared__ __nv_bfloat16 As[128][40];
    __shared__ __nv_bfloat16 Bs[128][40];
    __shared__ float red[256];
    int t = blockIdx.z;
    const __nv_bfloat16* A = g_theta_bf + (long)t * B_ * 64;
    const __nv_bfloat16* B = g_betaT_bf + (long)t * NP_V * 64;
    int tid = threadIdx.x;
    int lane = tid & 31, wid = tid >> 5;
    int wm = wid & 3, wn = wid >> 2;
    int g = lane >> 2, t4 = lane & 3;
    long m0 = (long)blockIdx.y * 128, n0 = (long)blockIdx.x * 128;
    int arow = tid >> 2;
    int akc = (tid & 3) * 8;
    float acc[2][8][4] = {};
    for (int k0 = 0; k0 < 64; k0 += 32) {
#pragma unroll
        for (int h = 0; h < 2; h++) {
            int r = arow + h * 64;
            *(uint4*)&As[r][akc] = *(const uint4*)&A[(m0 + r) * 64 + k0 + akc];
            *(uint4*)&Bs[r][akc] = *(const uint4*)&B[(n0 + r) * 64 + k0 + akc];
        }
        __syncthreads();
#pragma unroll
        for (int ks = 0; ks < 32; ks += 16) {
            uint32_t a[2][4];
#pragma unroll
            for (int i = 0; i < 2; i++) {
                int r = wm * 32 + i * 16 + g;
                a[i][0] = *(const uint32_t*)&As[r][ks + 2 * t4];
                a[i][1] = *(const uint32_t*)&As[r + 8][ks + 2 * t4];
                a[i][2] = *(const uint32_t*)&As[r][ks + 2 * t4 + 8];
                a[i][3] = *(const uint32_t*)&As[r + 8][ks + 2 * t4 + 8];
            }
#pragma unroll
            for (int j = 0; j < 8; j++) {
                int n = wn * 64 + j * 8 + g;
                uint32_t b0 = *(const uint32_t*)&Bs[n][ks + 2 * t4];
                uint32_t b1 = *(const uint32_t*)&Bs[n][ks + 2 * t4 + 8];
#pragma unroll
                for (int i = 0; i < 2; i++)
                    mma16816(acc[i][j], a[i], b0, b1);
            }
        }
        __syncthreads();
    }
    float local = 0.f;
#pragma unroll
    for (int i = 0; i < 2; i++) {
#pragma unroll
        for (int j = 0; j < 8; j++) {
            long m = m0 + wm * 32 + i * 16 + g;
            long n = n0 + wn * 64 + j * 8 + 2 * t4;
#pragma unroll
            for (int q = 0; q < 4; q++) {
                long bb = m + (q >> 1) * 8;
                long vv = n + (q & 1);
                if (vv < V_) {
                    float w = bow[(bb * T_ + t) * (long)V_ + vv];
                    local += -logf(acc[i][j][q] + 1e-6f) * w;
                }
            }
        }
    }
    float s = block_sum(local, red);
    if (tid == 0)
        g_part_nll[(blockIdx.z * 2 + blockIdx.y) * 40 + blockIdx.x] = s;
}

// ---------------- generic tiled fp32 GEMM (NT) ----------------
template<bool RELU>
__global__ void gemm_k(const float* __restrict__ A, int lda,
                       const float* __restrict__ Bm, int ldb,
                       const float* __restrict__ bias,
                       float* __restrict__ C, int ldc,
                       int M, int N, int Kd) {
    __shared__ float As[16][65];
    __shared__ float Bs[16][65];
    int tid = threadIdx.x;
    int tx = tid & 15, ty = tid >> 4;
    int m0 = blockIdx.y * 64, n0 = blockIdx.x * 64;
    float acc[4][4] = {};
    for (int k0 = 0; k0 < Kd; k0 += 16) {
#pragma unroll
        for (int i = 0; i < 4; i++) {
            int e = tid + i * 256;
            int m = e >> 4, kk = e & 15;
            int gm = m0 + m, gk = k0 + kk;
            float v = 0.f;
            if (gm < M && gk < Kd) v = A[(long)gm * lda + gk];
            As[kk][m] = v;
        }
#pragma unroll
        for (int i = 0; i < 4; i++) {
            int e = tid + i * 256;
            int n = e >> 4, kk = e & 15;
            int gn = n0 + n, gk = k0 + kk;
            float v = 0.f;
            if (gn < N && gk < Kd) v = Bm[(long)gn * ldb + gk];
            Bs[kk][n] = v;
        }
        __syncthreads();
#pragma unroll
        for (int kk = 0; kk < 16; kk++) {
            float a[4], b[4];
#pragma unroll
            for (int i = 0; i < 4; i++) a[i] = As[kk][ty + 16 * i];
#pragma unroll
            for (int j = 0; j < 4; j++) b[j] = Bs[kk][tx + 16 * j];
#pragma unroll
            for (int i = 0; i < 4; i++)
#pragma unroll
                for (int j = 0; j < 4; j++)
                    acc[i][j] = fmaf(a[i], b[j], acc[i][j]);
        }
        __syncthreads();
    }
#pragma unroll
    for (int i = 0; i < 4; i++) {
        int m = m0 + ty + 16 * i;
        if (m >= M) continue;
#pragma unroll
        for (int j = 0; j < 4; j++) {
            int n = n0 + tx + 16 * j;
            if (n >= N) continue;
            float v = acc[i][j];
            if (bias) v += bias[n];
            if (RELU) v = fmaxf(v, 0.f);
            C[(long)m * ldc + n] = v;
        }
    }
}

// ---------------- RNG / conversions / prep ----------------
__global__ void eps_kernel(unsigned a0, unsigned a1, unsigned e0, unsigned e1,
                           unsigned t0, unsigned t1) {
    int i = blockIdx.x * blockDim.x + threadIdx.x;
    if (i < NA_) {
        g_eps_a[i] = partitionable_normal(a0, a1, (unsigned)i);
    } else if (i < NA_ + NE_) {
        int j = i - NA_;
        g_eps_e[j] = partitionable_normal(e0, e1, (unsigned)j);
    } else if (i < NA_ + 2 * NE_) {
        int j = i - NA_ - NE_;
        g_eps_t[j] = partitionable_normal(t0, t1, (unsigned)j);
    }
}

__global__ void convbf_vec_k(const float* __restrict__ src, int lds,
                             __nv_bfloat16* __restrict__ dst, int ldd, int C) {
    int c = (blockIdx.x * blockDim.x + threadIdx.x) * 8;
    if (c >= ldd) return;
    int r = blockIdx.y;
    const float* s = src + (long)r * lds;
    __nv_bfloat16 tmp[8];
    if (c + 8 <= C) {
        float4 a = *(const float4*)(s + c);
        float4 b = *(const float4*)(s + c + 4);
        tmp[0] = __float2bfloat16(a.x); tmp[1] = __float2bfloat16(a.y);
        tmp[2] = __float2bfloat16(a.z); tmp[3] = __float2bfloat16(a.w);
        tmp[4] = __float2bfloat16(b.x); tmp[5] = __float2bfloat16(b.y);
        tmp[6] = __float2bfloat16(b.z); tmp[7] = __float2bfloat16(b.w);
    } else {
#pragma unroll
        for (int j = 0; j < 8; j++) {
            int cc = c + j;
            tmp[j] = __float2bfloat16(cc < C ? s[cc] : 0.f);
        }
    }
    *(uint4*)&dst[(long)r * ldd + c] = *(uint4*)tmp;
}

__global__ void convbf_row_k(const float* __restrict__ src, int lds,
                             __nv_bfloat16* __restrict__ dst, int ldd, int C) {
    int c = blockIdx.x * blockDim.x + threadIdx.x;
    if (c >= ldd) return;
    int r = blockIdx.y;
    float v = (c < C) ? src[(long)r * lds + c] : 0.f;
    dst[(long)r * ldd + c] = __float2bfloat16(v);
}

__global__ void transpose_bf_k(const float* __restrict__ src,
                               __nv_bfloat16* __restrict__ dst,
                               int R, int C, int ldd) {
    __shared__ float tile[32][33];
    int c0 = blockIdx.x * 32, r0 = blockIdx.y * 32;
#pragma unroll
    for (int i = 0; i < 4; i++) {
        int r = r0 + threadIdx.y + i * 8;
        int c = c0 + threadIdx.x;
        tile[threadIdx.y + i * 8][threadIdx.x] = (r < R && c < C) ? src[(long)r * C + c] : 0.f;
    }
    __syncthreads();
#pragma unroll
    for (int i = 0; i < 4; i++) {
        int orow = c0 + threadIdx.y + i * 8;
        int ocol = r0 + threadIdx.x;
        if (orow < C)
            dst[(long)orow * ldd + ocol] = __float2bfloat16(tile[threadIdx.x][threadIdx.y + i * 8]);
    }
}

__global__ void betaT_k() {
    __shared__ float sm[64][33];
    int t = blockIdx.y;
    int v0 = blockIdx.x * 32;
    int lane = threadIdx.x & 31, w = threadIdx.x >> 5;
    for (int k = w; k < 64; k += 8) {
        int v = v0 + lane;
        sm[k][lane] = (k < K_ && v < V_) ? g_beta[((long)t * K_ + k) * V_ + v] : 0.f;
    }
    __syncthreads();
    int r = threadIdx.x >> 3;
    int c0 = (threadIdx.x & 7) * 8;
    if (v0 + r < V_) {
        __nv_bfloat16 tmp[8];
#pragma unroll
        for (int j = 0; j < 8; j++) tmp[j] = __float2bfloat16(sm[c0 + j][r]);
        *(uint4*)&g_betaT_bf[((long)t * NP_V + v0 + r) * 64 + c0] = *(uint4*)tmp;
    }
}

// fused prep: whhT/wih bf16 (interleaved), bi, wml
__global__ void prep_fused_k(const float* __restrict__ Wih, const float* __restrict__ Whh,
                             const float* __restrict__ bih, const float* __restrict__ bhh,
                             const float* __restrict__ mutW, const float* __restrict__ mutb,
                             const float* __restrict__ lstW, const float* __restrict__ lstb) {
    int idx = blockIdx.x * blockDim.x + threadIdx.x;
    const int S1 = HE_ * 4 * HE_;
    const int S2 = S1 + 4 * HE_ * HE_;
    const int S3 = S2 + 4 * HE_;
    const int S4 = S3 + 128 * HT_;
    const int S5 = S4 + 128;
    if (idx < S1) {
        int k = idx >> 10, r = idx & 1023;
        int j = r >> 2, gate = r & 3;
        g_whhT_bf[idx] = __float2bfloat16(Whh[((long)(gate * HE_ + j)) * HE_ + k]);
    } else if (idx < S2) {
        int i = idx - S1;
        int r = i >> 8, k = i & 255;
        int j = r >> 2, gate = r & 3;
        g_wih_bf[i] = __float2bfloat16(Wih[((long)(gate * HE_ + j)) * HE_ + k]);
    } else if (idx < S3) {
        int r = idx - S2;
        int j = r >> 2, gate = r & 3;
        g_bi_int[r] = bih[gate * HE_ + j] + bhh[gate * HE_ + j];
    } else if (idx < S4) {
        int i = idx - S3;
        int row = i / HT_, k = i % HT_;
        float v = 0.f;
        if (row < 50) v = mutW[(long)row * HT_ + k];
        else if (row < 100) v = lstW[(long)(row - 50) * HT_ + k];
        g_wml_bf[i] = __float2bfloat16(v);
    } else if (idx < S5) {
        int r = idx - S4;
        g_wmlb[r] = (r < 50) ? mutb[r] : (r < 100 ? lstb[r - 50] : 0.f);
    }
}

__global__ void alphas_kernel(const float* __restrict__ muq, const float* __restrict__ lsq) {
    int idx = blockIdx.x * blockDim.x + threadIdx.x;
    if (idx >= NA_) return;
    int t = idx / (K_ * RHO_), rem = idx % (K_ * RHO_);
    int k = rem / RHO_, r = rem % RHO_;
    int src = (k * T_ + t) * RHO_ + r;
    float a = muq[src] + g_eps_a[idx] * expf(0.5f * lsq[src]);
    g_alphas[idx] = a;
    int row = t * K_ + k;
    g_alphas_bf[(long)row * KP_RHO + r] = __float2bfloat16(a);
}

__global__ void kld_alpha_kernel(const float* __restrict__ muq, const float* __restrict__ lsq) {
    __shared__ float red[256];
    float acc = 0.f;
    for (int idx = blockIdx.x * blockDim.x + threadIdx.x; idx < NA_;
         idx += gridDim.x * blockDim.x) {
        int t = idx / (K_ * RHO_), rem = idx % (K_ * RHO_);
        int k = rem / RHO_, r = rem % RHO_;
        int src = (k * T_ + t) * RHO_ + r;
        float mu = muq[src];
        float ls = lsq[src];
        float qls = fminf(fmaxf(ls, -100.f), 100.f);
        float pmu = (t == 0) ? 0.f : g_alphas[idx - K_ * RHO_];
        float pls = (t == 0) ? 0.f : LOGD;
        float d = mu - pmu;
        acc += (expf(qls) + d * d) / (expf(pls) + 1e-6f) - 1.f + pls - qls;
    }
    float s = block_sum(acc, red);
    if (threadIdx.x == 0) g_part_a[blockIdx.x] = s;
}

__global__ void softmax_rows_kernel() {
    __shared__ float red[256];
    long base = (long)blockIdx.x * V_;
    long basebf = (long)blockIdx.x * KP_V;
    int tid = threadIdx.x;
    float m = -FLT_MAX;
    for (int c = tid; c < V_; c += 256) m = fmaxf(m, g_beta[base + c]);
    m = block_max(m, red);
    float s = 0.f;
    for (int c = tid; c < V_; c += 256) {
        float e = expf(g_beta[base + c] - m);
        g_beta[base + c] = e; s += e;
    }
    s = block_sum(s, red);
    float inv = 1.f / s;
    for (int c = tid; c < V_; c += 256) {
        float b = g_beta[base + c] * inv;
        g_beta[base + c] = b;
        g_beta_bf[basebf + c] = __float2bfloat16(b);
    }
}

__global__ void combine_inp_k(const float* __restrict__ qeb) {
    int idx = blockIdx.x * blockDim.x + threadIdx.x;
    if (idx >= B_ * T_ * HE_) return;
    int j = idx & (HE_ - 1);
    float s = qeb[j];
#pragma unroll
    for (int z = 0; z < INP_SPLIT; z++) s += g_inp_part[(long)z * B_ * T_ * HE_ + idx];
    g_inp_bf[idx] = __float2bfloat16(s);
}

// ---------------- single-launch LSTM scan: 128 blocks x 2 batch rows ----------------
__global__ void __launch_bounds__(256) lstm_scan_k() {
    __shared__ float h[2][HE_];
    int j = threadIdx.x;
    int b0 = 2 * blockIdx.x, b1 = b0 + 1;
    float c0 = 0.f, c1 = 0.f;
    h[0][j] = 0.f; h[1][j] = 0.f;
    __syncthreads();
    const uint2* wT = (const uint2*)g_whhT_bf;
    for (int t = 0; t < T_; t++) {
        float a00 = 0.f, a10 = 0.f, a20 = 0.f, a30 = 0.f;
        float a01 = 0.f, a11 = 0.f, a21 = 0.f, a31 = 0.f;
#pragma unroll 4
        for (int k = 0; k < HE_; k++) {
            uint2 w = wT[k * 256 + j];
            float2 w01 = __bfloat1622float2(*(const __nv_bfloat162*)&w.x);
            float2 w23 = __bfloat1622float2(*(const __nv_bfloat162*)&w.y);
            float hb0 = h[0][k], hb1 = h[1][k];
            a00 = fmaf(w01.x, hb0, a00); a10 = fmaf(w01.y, hb0, a10);
            a20 = fmaf(w23.x, hb0, a20); a30 = fmaf(w23.y, hb0, a30);
            a01 = fmaf(w01.x, hb1, a01); a11 = fmaf(w01.y, hb1, a11);
            a21 = fmaf(w23.x, hb1, a21); a31 = fmaf(w23.y, hb1, a31);
        }
        __syncthreads();
        {
            float4 gx4 = *(const float4*)&g_gx[((long)b0 * T_ + t) * (4 * HE_) + 4 * j];
            float gi = gx4.x + a00, gf = gx4.y + a10, gg = gx4.z + a20, go = gx4.w + a30;
            float si = 1.f / (1.f + expf(-gi));
            float sf = 1.f / (1.f + expf(-gf));
            float so = 1.f / (1.f + expf(-go));
            c0 = sf * c0 + si * tanhf(gg);
            float hh = so * tanhf(c0);
            h[0][j] = hh;
            g_lstm[((long)t * B_ + b0) * HE_ + j] = hh;
        }
        {
            float4 gx4 = *(const float4*)&g_gx[((long)b1 * T_ + t) * (4 * HE_) + 4 * j];
            float gi = gx4.x + a01, gf = gx4.y + a11, gg = gx4.z + a21, go = gx4.w + a31;
            float si = 1.f / (1.f + expf(-gi));
            float sf = 1.f / (1.f + expf(-gf));
            float so = 1.f / (1.f + expf(-go));
            c1 = sf * c1 + si * tanhf(gg);
            float hh = so * tanhf(c1);
            h[1][j] = hh;
            g_lstm[((long)t * B_ + b1) * HE_ + j] = hh;
        }
        __syncthreads();
    }
}

// ---------------- single-launch eta scan: 64 blocks x 4 batch rows ----------------
#define ETA_SMEM (100*306*2 + (4*306 + 200 + 200 + 200) * 4)
__global__ void __launch_bounds__(256) eta_scan_k(
    const float* __restrict__ mueW, const float* __restrict__ mueb,
    const float* __restrict__ lseW, const float* __restrict__ lseb) {
    extern __shared__ char smc[];
    __nv_bfloat16* wsm = (__nv_bfloat16*)smc;
    float* z   = (float*)(smc + 100 * 306 * 2);
    float* smu = z + 4 * 306;
    float* sls = smu + 200;
    float* skl = sls + 200;
    int tid = threadIdx.x, bk = blockIdx.x;
    for (int i = tid; i < 100 * 306; i += 256) {
        int r = i / 306, k = i % 306;
        float v = (r < 50) ? mueW[(long)r * HEK_ + k] : lseW[(long)(r - 50) * HEK_ + k];
        wsm[i] = __float2bfloat16(v);
    }
    if (tid < 200) {
        int q = tid / 50, k = tid % 50;
        z[q * 306 + 256 + k] = 0.f;
    }
    __syncthreads();
    for (int t = 0; t < T_; t++) {
#pragma unroll
        for (int q = 0; q < 4; q++)
            z[q * 306 + tid] = g_lstm[((long)t * B_ + 4 * bk + q) * HE_ + tid];
        __syncthreads();
#pragma unroll
        for (int rep = 0; rep < 2; rep++) {
            int o = tid + rep * 256;
            if (o < 400) {
                int q = o / 100, r = o % 100;
                float acc = (r < 50) ? mueb[r] : lseb[r - 50];
                const __nv_bfloat16* wr = wsm + r * 306;
                const float* zq = z + q * 306;
#pragma unroll 2
                for (int k = 0; k < HEK_; k++)
                    acc = fmaf(__bfloat162float(wr[k]), zq[k], acc);
                if (r < 50) smu[q * 50 + r] = acc;
                else        sls[q * 50 + (r - 50)] = acc;
            }
        }
        __syncthreads();
        if (tid < 200) {
            int q = tid / 50, k = tid % 50;
            int b = 4 * bk + q;
            float mu = smu[q * 50 + k], ls = sls[q * 50 + k];
            float pmu = z[q * 306 + 256 + k];
            float eps = g_eps_e[((long)t * B_ + b) * K_ + k];
            float eta = mu + eps * expf(0.5f * ls);
            g_etas[((long)t * B_ + b) * K_ + k] = eta;
            float qls = fminf(fmaxf(ls, -100.f), 100.f);
            float pls = (t == 0) ? 0.f : LOGD;
            float d = mu - pmu;
            skl[tid] = (expf(qls) + d * d) / (expf(pls) + 1e-6f) - 1.f + pls - qls;
            z[q * 306 + 256 + k] = eta;
        }
        __syncthreads();
        if (tid < 4) {
            float s = 0.f;
            for (int k = 0; k < 50; k++) s += skl[tid * 50 + k];
            g_part_ke[t * B_ + 4 * bk + tid] = s;
        }
        __syncthreads();
    }
}

// h1 = relu(h1e + sum_z h1b_part) -> bf16
__global__ void combine_h1_kernel() {
    int j = blockIdx.x * blockDim.x + threadIdx.x;
    if (j >= HT_) return;
    int row = blockIdx.y;
    int b = row & (B_ - 1);
    float hb = 0.f;
#pragma unroll
    for (int z = 0; z < H1B_SPLIT; z++) hb += g_h1b_part[(long)z * B_ * HT_ + b * HT_ + j];
    long idx = (long)row * HT_ + j;
    float v = fmaxf(g_h1e[idx] + hb, 0.f);
    g_h1_bf[idx] = __float2bfloat16(v);
}

__global__ void theta_kernel() {
    __shared__ float red[64];
    int row = blockIdx.x, k = threadIdx.x;
    long base = (long)row * K_;
    long mbase = (long)row * 100;
    bool val = k < K_;
    float mu = 0.f, ls = 0.f, zv = -FLT_MAX;
    if (val) {
        mu = g_mls[mbase + k];
        ls = g_mls[mbase + 50 + k];
        zv = mu + g_eps_t[base + k] * expf(0.5f * ls);
    }
    float mx = block_max(zv, red);
    float e = val ? expf(zv - mx) : 0.f;
    float sum = block_sum(e, red);
    float th = e / sum;
    if (val) {
        g_theta_arr[base + k] = th;
        g_theta_bf[(long)row * 64 + k] = __float2bfloat16(th);
    } else if (k < 64) {
        g_theta_bf[(long)row * 64 + k] = __float2bfloat16(0.f);
    }
    float kl = 0.f;
    if (val) {
        float qls = fminf(fmaxf(ls, -100.f), 100.f);
        float d = mu - g_etas[base + k];
        kl = (expf(qls) + d * d) / (1.f + 1e-6f) - 1.f - qls;
    }
    float s = block_sum(kl, red);
    if (k == 0) g_part_kt[row] = s;
}

__global__ void final_reduce_kernel(float* out, int out_size) {
    __shared__ float red[256];
    int tid = threadIdx.x;
    float v;
    v = 0.f; for (int i = tid; i < RB_NLL;  i += 256) v += g_part_nll[i];
    float nll  = block_sum(v, red) * (10.0f / B_);
    v = 0.f; for (int i = tid; i < T_ * B_; i += 256) v += g_part_kt[i];
    float kt   = block_sum(v, red) * (0.5f / (T_ * B_));
    v = 0.f; for (int i = tid; i < RB_A;    i += 256) v += g_part_a[i];
    float ka   = block_sum(v, red) * (0.5f / (T_ * K_));
    v = 0.f; for (int i = tid; i < T_ * B_; i += 256) v += g_part_ke[i];
    float ke   = block_sum(v, red) * (0.5f / B_);
    v = 0.f; for (int i = tid; i < RB_COND; i += 256) v += g_part_cond[i];
    float cond = block_sum(v, red) * (-0.01f);
    if (tid == 0) {
        if (out_size > 0) out[0] = nll;
        if (out_size > 1) out[1] = kt;
        if (out_size > 2) out[2] = ka;
        if (out_size > 3) out[3] = ke;
        if (out_size > 4) out[4] = cond;
    }
}

// ---------------- host driver ----------------
static inline int ceil_div(long a, long b) { return (int)((a + b - 1) / b); }

extern "C" void kernel_launch(void* const* d_in, const int* in_sizes, int n_in,
                              void* d_out, int out_size) {
    (void)in_sizes; (void)n_in;
    const float* nb   = (const float*)d_in[0];
    const float* bow  = (const float*)d_in[1];
    const float* adj  = (const float*)d_in[2];
    const float* muqa = (const float*)d_in[3];
    const float* lsqa = (const float*)d_in[4];
    const float* rhoW = (const float*)d_in[5];
    const float* rhob = (const float*)d_in[6];
    const float* W1   = (const float*)d_in[7];
    const float* b1   = (const float*)d_in[8];
    const float* W2   = (const float*)d_in[9];
    const float* b2   = (const float*)d_in[10];
    const float* mutW = (const float*)d_in[11];
    const float* mutb = (const float*)d_in[12];
    const float* lstW = (const float*)d_in[13];
    const float* lstb = (const float*)d_in[14];
    const float* qeW  = (const float*)d_in[15];
    const float* qeb  = (const float*)d_in[16];
    const float* Wih  = (const float*)d_in[17];
    const float* Whh  = (const float*)d_in[18];
    const float* bih  = (const float*)d_in[19];
    const float* bhh  = (const float*)d_in[20];
    const float* mueW = (const float*)d_in[21];
    const float* mueb = (const float*)d_in[22];
    const float* lseW = (const float*)d_in[23];
    const float* lseb = (const float*)d_in[24];
    float* out = (float*)d_out;

    unsigned ka0, ka1, ke0, ke1, kt0, kt1;
    tf2x32(0u, 42u, 0u, 0u, &ka0, &ka1);
    tf2x32(0u, 42u, 0u, 1u, &ke0, &ke1);
    tf2x32(0u, 42u, 0u, 2u, &kt0, &kt1);

    float *p_beta, *p_inp_part, *p_gx, *p_etas, *p_h1e, *p_h1b_part, *p_mls;
    float *p_bi_int, *p_part_cond, *p_wmlb;
    __nv_bfloat16 *p_alphas_bf, *p_beta_bf, *p_adjT, *p_bow_bf, *p_qew_bf, *p_nb_bf;
    __nv_bfloat16 *p_w1_bf, *p_rhow_bf, *p_w2_bf, *p_wml_bf, *p_h1_bf, *p_h2_bf;
    __nv_bfloat16 *p_inp_bf, *p_wih_bf;
    cudaGetSymbolAddress((void**)&p_beta,      g_beta);
    cudaGetSymbolAddress((void**)&p_inp_part,  g_inp_part);
    cudaGetSymbolAddress((void**)&p_gx,        g_gx);
    cudaGetSymbolAddress((void**)&p_etas,      g_etas);
    cudaGetSymbolAddress((void**)&p_h1e,       g_h1e);
    cudaGetSymbolAddress((void**)&p_h1b_part,  g_h1b_part);
    cudaGetSymbolAddress((void**)&p_mls,       g_mls);
    cudaGetSymbolAddress((void**)&p_bi_int,    g_bi_int);
    cudaGetSymbolAddress((void**)&p_part_cond, g_part_cond);
    cudaGetSymbolAddress((void**)&p_wmlb,      g_wmlb);
    cudaGetSymbolAddress((void**)&p_alphas_bf, g_alphas_bf);
    cudaGetSymbolAddress((void**)&p_beta_bf,   g_beta_bf);
    cudaGetSymbolAddress((void**)&p_adjT,      g_adjT_bf);
    cudaGetSymbolAddress((void**)&p_bow_bf,    g_bow_bf);
    cudaGetSymbolAddress((void**)&p_qew_bf,    g_qew_bf);
    cudaGetSymbolAddress((void**)&p_nb_bf,     g_nb_bf);
    cudaGetSymbolAddress((void**)&p_w1_bf,     g_w1_bf);
    cudaGetSymbolAddress((void**)&p_rhow_bf,   g_rhow_bf);
    cudaGetSymbolAddress((void**)&p_w2_bf,     g_w2_bf);
    cudaGetSymbolAddress((void**)&p_wml_bf,    g_wml_bf);
    cudaGetSymbolAddress((void**)&p_h1_bf,     g_h1_bf);
    cudaGetSymbolAddress((void**)&p_h2_bf,     g_h2_bf);
    cudaGetSymbolAddress((void**)&p_inp_bf,    g_inp_bf);
    cudaGetSymbolAddress((void**)&p_wih_bf,    g_wih_bf);

    cudaFuncSetAttribute(tc_gemm_k<true,  false, false, false>, cudaFuncAttributeMaxDynamicSharedMemorySize, TC_SMEM_BYTES);
    cudaFuncSetAttribute(tc_gemm_k<false, false, false, true >, cudaFuncAttributeMaxDynamicSharedMemorySize, TC_SMEM_BYTES);
    cudaFuncSetAttribute(tc_gemm_k<false, false, false, false>, cudaFuncAttributeMaxDynamicSharedMemorySize, TC_SMEM_BYTES);
    cudaFuncSetAttribute(tc_gemm_k<true,  true,  true,  false>, cudaFuncAttributeMaxDynamicSharedMemorySize, TC_SMEM_BYTES);
    cudaFuncSetAttribute(eta_scan_k, cudaFuncAttributeMaxDynamicSharedMemorySize, ETA_SMEM);

    // ---- alpha/beta chain first (4th launch = pipelined beta TC GEMM, A/B vs R12) ----
    convbf_vec_k<<<dim3(ceil_div(KP_RHO / 8, 256), V_), 256>>>(rhoW, RHO_, p_rhow_bf, KP_RHO, RHO_);
    int totalElems = NA_ + 2 * NE_;
    eps_kernel<<<(totalElems + 255) / 256, 256>>>(ka0, ka1, ke0, ke1, kt0, kt1);
    alphas_kernel<<<(NA_ + 255) / 256, 256>>>(muqa, lsqa);
    tc_gemm_k<true, false, false, false><<<dim3(ceil_div(V_, 128), ceil_div(T_ * K_, 128)), 256, TC_SMEM_BYTES>>>(
        p_alphas_bf, KP_RHO, p_rhow_bf, KP_RHO, rhob, p_beta, nullptr, V_,
        nullptr, nullptr, T_ * K_, V_, KP_RHO);
    kld_alpha_kernel<<<RB_A, 256>>>(muqa, lsqa);
    softmax_rows_kernel<<<T_ * K_, 256>>>();
    betaT_k<<<dim3(ceil_div(V_, 32), T_), 256>>>();
    transpose_bf_k<<<dim3(ceil_div(V_, 32), ceil_div(V_, 32)), dim3(32, 8)>>>(adj, p_adjT, V_, V_, KP_V);
    tc_gemm_k<false, false, false, true><<<dim3(ceil_div(V_, 128), ceil_div(T_ * K_, 128)), 256, TC_SMEM_BYTES>>>(
        p_beta_bf, KP_V, p_adjT, KP_V, nullptr, nullptr, nullptr, V_,
        p_beta, p_part_cond, T_ * K_, V_, KP_V);

    // ---- conversions + prep ----
    convbf_vec_k<<<dim3(ceil_div(KP_V / 8, 256), B_ * T_), 256>>>(bow, V_, p_bow_bf, KP_V, V_);
    convbf_vec_k<<<dim3(ceil_div(KP_V / 8, 256), HE_), 256>>>(qeW, V_, p_qew_bf, KP_V, V_);
    convbf_vec_k<<<dim3(ceil_div(KP_V / 8, 256), B_), 256>>>(nb, V_, p_nb_bf, KP_V, V_);
    convbf_row_k<<<dim3(ceil_div(KP_V, 256), HT_), 256>>>(W1, VK_, p_w1_bf, KP_V, V_);
    convbf_vec_k<<<dim3(ceil_div(HT_ / 8, 256), HT_), 256>>>(W2, HT_, p_w2_bf, HT_, HT_);
    {
        int preptotal = HE_ * 4 * HE_ + 4 * HE_ * HE_ + 4 * HE_ + 128 * HT_ + 128;
        prep_fused_k<<<(preptotal + 255) / 256, 256>>>(Wih, Whh, bih, bhh, mutW, mutb, lstW, lstb);
    }

    // ---- inp (split-K) -> bf16 combine -> gx (TC) -> LSTM scan -> eta scan ----
    tc_gemm_k<false, false, false, false><<<dim3(ceil_div(HE_, 128), ceil_div(B_ * T_, 128), INP_SPLIT), 256, TC_SMEM_BYTES>>>(
        p_bow_bf, KP_V, p_qew_bf, KP_V, nullptr, p_inp_part, nullptr, HE_,
        nullptr, nullptr, B_ * T_, HE_, KP_V);
    combine_inp_k<<<ceil_div(B_ * T_ * HE_, 256), 256>>>(qeb);
    tc_gemm_k<true, false, false, false><<<dim3(8, 24), 256, TC_SMEM_BYTES>>>(
        p_inp_bf, HE_, p_wih_bf, HE_, p_bi_int, p_gx, nullptr, 4 * HE_,
        nullptr, nullptr, B_ * T_, 4 * HE_, HE_);
    lstm_scan_k<<<128, 256>>>();
    eta_scan_k<<<64, 256, ETA_SMEM>>>(mueW, mueb, lseW, lseb);

    // ---- theta encoder ----
    gemm_k<false><<<dim3(13, 48), 256>>>(
        p_etas, K_, W1 + V_, VK_, b1, p_h1e, HT_, T_ * B_, HT_, K_);
    tc_gemm_k<false, false, false, false><<<dim3(ceil_div(HT_, 128), ceil_div(B_, 128), H1B_SPLIT), 256, TC_SMEM_BYTES>>>(
        p_nb_bf, KP_V, p_w1_bf, KP_V, nullptr, p_h1b_part, nullptr, HT_,
        nullptr, nullptr, B_, HT_, KP_V);
    combine_h1_kernel<<<dim3(ceil_div(HT_, 256), T_ * B_), 256>>>();
    tc_gemm_k<true, true, true, false><<<dim3(ceil_div(HT_, 128), ceil_div(T_ * B_, 128)), 256, TC_SMEM_BYTES>>>(
        p_h1_bf, HT_, p_w2_bf, HT_, b2, nullptr, p_h2_bf, HT_,
        nullptr, nullptr, T_ * B_, HT_, HT_);
    tc_gemm_k<true, false, false, false><<<dim3(1, ceil_div(T_ * B_, 128)), 256, TC_SMEM_BYTES>>>(
        p_h2_bf, HT_, p_wml_bf, HT_, p_wmlb, p_mls, nullptr, 100,
        nullptr, nullptr, T_ * B_, 100, HT_);

    // ---- theta + NLL + final ----
    theta_kernel<<<T_ * B_, 64>>>();
    tc_nll_k<<<dim3(40, 2, T_), 256>>>(bow);
    final_reduce_kernel<<<1, 256>>>(out, out_size);
}

// round 14
// speedup vs baseline: 4.7147x; 1.0021x over previous
#include <cuda_runtime.h>
#include <cuda_bf16.h>
#include <cstdint>
#include <float.h>
#include <math.h>

// ---------------- problem constants ----------------
#define T_    12
#define K_    50
#define V_    5000
#define B_    256
#define RHO_  300
#define HT_   800
#define HE_   256
#define VK_   (V_ + K_)
#define HEK_  (HE_ + K_)   // 306
#define LOGD  (-5.2983173665480363f)

#define NA_   (T_*K_*RHO_)
#define NE_   (T_*B_*K_)

#define KP_V   5024
#define KP_RHO 320
#define NP_V   5120
#define MP_TK  640

#define INP_SPLIT 6
#define H1B_SPLIT 12

// ---------------- device scratch ----------------
__device__ float g_eps_a[NA_];
__device__ float g_eps_e[NE_];
__device__ float g_eps_t[NE_];
__device__ float g_alphas[NA_];
__device__ __align__(16) __nv_bfloat16 g_alphas_bf[MP_TK*KP_RHO];
__device__ float g_beta[T_*K_*V_];
__device__ __align__(16) __nv_bfloat16 g_beta_bf[MP_TK*KP_V];
__device__ __align__(16) __nv_bfloat16 g_betaT_bf[T_*NP_V*64];
__device__ __align__(16) __nv_bfloat16 g_adjT_bf[NP_V*KP_V];
__device__ __align__(16) __nv_bfloat16 g_bow_bf[B_*T_*KP_V];
__device__ __align__(16) __nv_bfloat16 g_qew_bf[HE_*KP_V];
__device__ __align__(16) __nv_bfloat16 g_nb_bf[B_*KP_V];
__device__ __align__(16) __nv_bfloat16 g_w1_bf[896*KP_V];
__device__ __align__(16) __nv_bfloat16 g_rhow_bf[NP_V*KP_RHO];
__device__ __align__(16) __nv_bfloat16 g_w2_bf[896*HT_];
__device__ __align__(16) __nv_bfloat16 g_wml_bf[128*HT_];
__device__ float g_wmlb[128];
__device__ __align__(16) __nv_bfloat16 g_whhT_bf[HE_*4*HE_];   // [k][1024] interleaved j*4+gate
__device__ __align__(16) __nv_bfloat16 g_wih_bf[4*HE_*HE_];    // [1024 rows j*4+g][k=256]
__device__ float g_bi_int[4*HE_];
__device__ __align__(16) __nv_bfloat16 g_inp_bf[B_*T_*HE_];
__device__ float g_inp_part[INP_SPLIT*B_*T_*HE_];
__device__ float g_gx[B_*T_*4*HE_];
__device__ float g_lstm[T_*B_*HE_];
__device__ float g_etas[NE_];
__device__ float g_h1e[T_*B_*HT_];
__device__ float g_h1b_part[H1B_SPLIT*B_*HT_];
__device__ __align__(16) __nv_bfloat16 g_h1_bf[T_*B_*HT_];
__device__ __align__(16) __nv_bfloat16 g_h2_bf[T_*B_*HT_];
__device__ float g_mls[T_*B_*100];
__device__ float g_theta_arr[NE_];
__device__ __align__(16) __nv_bfloat16 g_theta_bf[T_*B_*64];

#define RB_NLL  (12*2*40)
#define RB_COND 200
#define RB_A    256
__device__ float g_part_nll[RB_NLL];
__device__ float g_part_cond[RB_COND];
__device__ float g_part_a[RB_A];
__device__ float g_part_kt[T_*B_];
__device__ float g_part_ke[T_*B_];

// ---------------- threefry2x32 (JAX partitionable) ----------------
__host__ __device__ inline void tf2x32(unsigned k0, unsigned k1,
                                       unsigned x0, unsigned x1,
                                       unsigned* o0, unsigned* o1) {
    unsigned ks0 = k0, ks1 = k1, ks2 = k0 ^ k1 ^ 0x1BD11BDAu;
    x0 += ks0; x1 += ks1;
#define TF_R(r) { x0 += x1; x1 = (x1 << (r)) | (x1 >> (32 - (r))); x1 ^= x0; }
    TF_R(13) TF_R(15) TF_R(26) TF_R(6)
    x0 += ks1; x1 += ks2 + 1u;
    TF_R(17) TF_R(29) TF_R(16) TF_R(24)
    x0 += ks2; x1 += ks0 + 2u;
    TF_R(13) TF_R(15) TF_R(26) TF_R(6)
    x0 += ks0; x1 += ks1 + 3u;
    TF_R(17) TF_R(29) TF_R(16) TF_R(24)
    x0 += ks1; x1 += ks2 + 4u;
    TF_R(13) TF_R(15) TF_R(26) TF_R(6)
    x0 += ks2; x1 += ks0 + 5u;
#undef TF_R
    *o0 = x0; *o1 = x1;
}

__device__ __forceinline__ float bits2normal(unsigned bits) {
    float f = __uint_as_float((bits >> 9) | 0x3F800000u) - 1.0f;
    const float lo = -0.99999994f;
    float u = fmaf(f, 2.0f, lo);
    u = fmaxf(lo, u);
    return 1.4142135381698608f * erfinvf(u);
}

__device__ __forceinline__ float partitionable_normal(unsigned k0, unsigned k1, unsigned i) {
    unsigned o0, o1;
    tf2x32(k0, k1, 0u, i, &o0, &o1);
    return bits2normal(o0 ^ o1);
}

// ---------------- block reductions ----------------
__device__ __forceinline__ float block_sum(float v, float* red) {
    int tid = threadIdx.x, n = blockDim.x;
    red[tid] = v; __syncthreads();
    for (int s = n >> 1; s > 0; s >>= 1) {
        if (tid < s) red[tid] += red[tid + s];
        __syncthreads();
    }
    v = red[0]; __syncthreads();
    return v;
}
__device__ __forceinline__ float block_max(float v, float* red) {
    int tid = threadIdx.x, n = blockDim.x;
    red[tid] = v; __syncthreads();
    for (int s = n >> 1; s > 0; s >>= 1) {
        if (tid < s) red[tid] = fmaxf(red[tid], red[tid + s]);
        __syncthreads();
    }
    v = red[0]; __syncthreads();
    return v;
}

// ---------------- mma / ldmatrix / cp.async helpers ----------------
__device__ __forceinline__ void mma16816(float* c, const uint32_t* a, uint32_t b0, uint32_t b1) {
    asm volatile(
        "mma.sync.aligned.m16n8k16.row.col.f32.bf16.bf16.f32 "
        "{%0,%1,%2,%3}, {%4,%5,%6,%7}, {%8,%9}, {%0,%1,%2,%3};\n"
        : "+f"(c[0]), "+f"(c[1]), "+f"(c[2]), "+f"(c[3])
        : "r"(a[0]), "r"(a[1]), "r"(a[2]), "r"(a[3]), "r"(b0), "r"(b1));
}
__device__ __forceinline__ void ldsm_x4(uint32_t* d, uint32_t smaddr) {
    asm volatile("ldmatrix.sync.aligned.m8n8.x4.shared.b16 {%0,%1,%2,%3}, [%4];\n"
        : "=r"(d[0]), "=r"(d[1]), "=r"(d[2]), "=r"(d[3]) : "r"(smaddr));
}
#define CPASYNC16(sp, gp) \
    asm volatile("cp.async.cg.shared.global [%0], [%1], 16;\n" \
        :: "r"((unsigned)__cvta_generic_to_shared(sp)), "l"(gp))
#define CPCOMMIT() asm volatile("cp.async.commit_group;\n")
#define CPWAIT(n)  asm volatile("cp.async.wait_group %0;\n" :: "n"(n))

#define CHUNK_ELEMS (128 * 40)
#define TC_SMEM_BYTES (2 * 4 * CHUNK_ELEMS * 2)   // 4-chunk ring, 2 operands: 81920 B

// ---------------- pipelined bf16 TC GEMM (NT), ldmatrix fragment loads ----------------
template<bool BIAS, bool RELU, bool OUTBF, bool CONDEPI>
__global__ void __launch_bounds__(256) tc_gemm_k(
    const __nv_bfloat16* __restrict__ A, int lda,
    const __nv_bfloat16* __restrict__ B, int ldb,
    const float* __restrict__ bias,
    float* __restrict__ C, __nv_bfloat16* __restrict__ Cbf, int ldc,
    const float* __restrict__ Cf, float* __restrict__ part,
    int M, int N, int Kp) {
    extern __shared__ __nv_bfloat16 smp[];
    __nv_bfloat16* As = smp;                      // 4 × [128][40]
    __nv_bfloat16* Bs = smp + 4 * CHUNK_ELEMS;
    __shared__ float red[256];
    int tid = threadIdx.x;
    int lane = tid & 31, wid = tid >> 5;
    int wm = wid & 3, wn = wid >> 2;
    int g = lane >> 2, t4 = lane & 3;
    long m0 = (long)blockIdx.y * 128, n0 = (long)blockIdx.x * 128;
    int arow = tid >> 2;
    int akc = (tid & 3) * 8;
    float acc[2][8][4] = {};

    // ldmatrix per-lane address components (elements)
    int a_row_off = wm * 32 + (lane & 7) + 8 * ((lane >> 3) & 1);  // + i*16
    int a_col_off = 8 * (lane >> 4);                               // + ks
    int b_row_off = wn * 64 + (lane & 7) + 8 * (lane >> 4);        // + j2*16
    int b_col_off = 8 * ((lane >> 3) & 1);                         // + ks
    uint32_t as_base = (uint32_t)__cvta_generic_to_shared(As);
    uint32_t bs_base = (uint32_t)__cvta_generic_to_shared(Bs);

    int nkt = Kp >> 5;
    int per = (nkt + gridDim.z - 1) / gridDim.z;
    int it0 = blockIdx.z * per;
    int itn = nkt - it0; if (itn > per) itn = per; if (itn < 0) itn = 0;

#define TC_ISSUE(IT, S) do {                                                     \
        int _k = ((IT) << 5) + akc;                                              \
        __nv_bfloat16* _as = As + (size_t)(S) * CHUNK_ELEMS;                     \
        __nv_bfloat16* _bs = Bs + (size_t)(S) * CHUNK_ELEMS;                     \
        CPASYNC16(&_as[(size_t)arow * 40 + akc],        &A[(m0 + arow) * (long)lda + _k]);        \
        CPASYNC16(&_as[(size_t)(arow + 64) * 40 + akc], &A[(m0 + arow + 64) * (long)lda + _k]);   \
        CPASYNC16(&_bs[(size_t)arow * 40 + akc],        &B[(n0 + arow) * (long)ldb + _k]);        \
        CPASYNC16(&_bs[(size_t)(arow + 64) * 40 + akc], &B[(n0 + arow + 64) * (long)ldb + _k]);   \
        CPCOMMIT();                                                              \
    } while (0)

    int npre = itn < 4 ? itn : 4;
    for (int p = 0; p < npre; p++) TC_ISSUE(it0 + p, p);

    for (int e = 0; e < itn; e += 2) {
        if (itn - e > 4) { CPWAIT(2); } else { CPWAIT(0); }
        __syncthreads();
#pragma unroll
        for (int u = 0; u < 2; u++) {
            int ce = e + u;
            if (ce < itn) {
                uint32_t asb = as_base + (uint32_t)((ce & 3) * CHUNK_ELEMS) * 2u;
                uint32_t bsb = bs_base + (uint32_t)((ce & 3) * CHUNK_ELEMS) * 2u;
#pragma unroll
                for (int ks = 0; ks < 32; ks += 16) {
                    uint32_t a[2][4], b[4][4];
#pragma unroll
                    for (int i = 0; i < 2; i++)
                        ldsm_x4(a[i], asb + (uint32_t)((a_row_off + i * 16) * 40 + ks + a_col_off) * 2u);
#pragma unroll
                    for (int j2 = 0; j2 < 4; j2++)
                        ldsm_x4(b[j2], bsb + (uint32_t)((b_row_off + j2 * 16) * 40 + ks + b_col_off) * 2u);
#pragma unroll
                    for (int j2 = 0; j2 < 4; j2++) {
#pragma unroll
                        for (int i = 0; i < 2; i++) {
                            mma16816(acc[i][2 * j2],     a[i], b[j2][0], b[j2][1]);
                            mma16816(acc[i][2 * j2 + 1], a[i], b[j2][2], b[j2][3]);
                        }
                    }
                }
            }
        }
        __syncthreads();
        if (e + 4 < itn) TC_ISSUE(it0 + e + 4, e & 3);
        if (e + 5 < itn) TC_ISSUE(it0 + e + 5, (e + 1) & 3);
    }
#undef TC_ISSUE

    if (CONDEPI) {
        float local = 0.f;
#pragma unroll
        for (int i = 0; i < 2; i++) {
#pragma unroll
            for (int j = 0; j < 8; j++) {
                long m = m0 + wm * 32 + i * 16 + g;
                long n = n0 + wn * 64 + j * 8 + 2 * t4;
                if (m < M) {
                    if (n < N)     local += acc[i][j][0] * Cf[m * ldc + n];
                    if (n + 1 < N) local += acc[i][j][1] * Cf[m * ldc + n + 1];
                }
                if (m + 8 < M) {
                    if (n < N)     local += acc[i][j][2] * Cf[(m + 8) * ldc + n];
                    if (n + 1 < N) local += acc[i][j][3] * Cf[(m + 8) * ldc + n + 1];
                }
            }
        }
        float s = block_sum(local, red);
        if (tid == 0) part[blockIdx.y * gridDim.x + blockIdx.x] = s;
    } else {
        float* Cz = C ? C + (long)blockIdx.z * M * ldc : nullptr;
#pragma unroll
        for (int i = 0; i < 2; i++) {
#pragma unroll
            for (int j = 0; j < 8; j++) {
                long m = m0 + wm * 32 + i * 16 + g;
                long n = n0 + wn * 64 + j * 8 + 2 * t4;
#pragma unroll
                for (int q = 0; q < 4; q++) {
                    long mm = m + (q >> 1) * 8;
                    long nn = n + (q & 1);
                    if (mm < M && nn < N) {
                        float v = acc[i][j][q];
                        if (BIAS) v += bias[nn];
                        if (RELU) v = fmaxf(v, 0.f);
                        if (OUTBF) Cbf[mm * ldc + nn] = __float2bfloat16(v);
                        else       Cz[mm * ldc + nn] = v;
                    }
                }
            }
        }
    }
}

// ---------------- TC NLL ----------------
__global__ void __launch_bounds__(256) tc_nll_k(const float* __restrict__ bow) {
    __shared__ __nv_bfloat16 As[128][40];
    __shared__ __nv_bfloat16 Bs[128][40];
    __shared__ float red[256];
    int t = blockIdx.z;
    const __nv_bfloat16* A = g_theta_bf + (long)t * B_ * 64;
    const __nv_bfloat16* B = g_betaT_bf + (long)t * NP_V * 64;
    int tid = threadIdx.x;
    int lane = tid & 31, wid = tid >> 5;
    int wm = wid & 3, wn = wid >> 2;
    int g = lane >> 2, t4 = lane & 3;
    long m0 = (long)blockIdx.y * 128, n0 = (long)blockIdx.x * 128;
    int arow = tid >> 2;
    int akc = (tid & 3) * 8;
    float acc[2][8][4] = {};
    for (int k0 = 0; k0 < 64; k0 += 32) {
#pragma unroll
        for (int h = 0; h < 2; h++) {
            int r = arow + h * 64;
            *(uint4*)&As[r][akc] = *(const uint4*)&A[(m0 + r) * 64 + k0 + akc];
            *(uint4*)&Bs[r][akc] = *(const uint4*)&B[(n0 + r) * 64 + k0 + akc];
        }
        __syncthreads();
#pragma unroll
        for (int ks = 0; ks < 32; ks += 16) {
            uint32_t a[2][4];
#pragma unroll
            for (int i = 0; i < 2; i++) {
                int r = wm * 32 + i * 16 + g;
                a[i][0] = *(const uint32_t*)&As[r][ks + 2 * t4];
                a[i][1] = *(const uint32_t*)&As[r + 8][ks + 2 * t4];
                a[i][2] = *(const uint32_t*)&As[r][ks + 2 * t4 + 8];
                a[i][3] = *(const uint32_t*)&As[r + 8][ks + 2 * t4 + 8];
            }
#pragma unroll
            for (int j = 0; j < 8; j++) {
                int n = wn * 64 + j * 8 + g;
                uint32_t b0 = *(const uint32_t*)&Bs[n][ks + 2 * t4];
                uint32_t b1 = *(const uint32_t*)&Bs[n][ks + 2 * t4 + 8];
#pragma unroll
                for (int i = 0; i < 2; i++)
                    mma16816(acc[i][j], a[i], b0, b1);
            }
        }
        __syncthreads();
    }
    float local = 0.f;
#pragma unroll
    for (int i = 0; i < 2; i++) {
#pragma unroll
        for (int j = 0; j < 8; j++) {
            long m = m0 + wm * 32 + i * 16 + g;
            long n = n0 + wn * 64 + j * 8 + 2 * t4;
#pragma unroll
            for (int q = 0; q < 4; q++) {
                long bb = m + (q >> 1) * 8;
                long vv = n + (q & 1);
                if (vv < V_) {
                    float w = bow[(bb * T_ + t) * (long)V_ + vv];
                    local += -logf(acc[i][j][q] + 1e-6f) * w;
                }
            }
        }
    }
    float s = block_sum(local, red);
    if (tid == 0)
        g_part_nll[(blockIdx.z * 2 + blockIdx.y) * 40 + blockIdx.x] = s;
}

// ---------------- generic tiled fp32 GEMM (NT) ----------------
template<bool RELU>
__global__ void gemm_k(const float* __restrict__ A, int lda,
                       const float* __restrict__ Bm, int ldb,
                       const float* __restrict__ bias,
                       float* __restrict__ C, int ldc,
                       int M, int N, int Kd) {
    __shared__ float As[16][65];
    __shared__ float Bs[16][65];
    int tid = threadIdx.x;
    int tx = tid & 15, ty = tid >> 4;
    int m0 = blockIdx.y * 64, n0 = blockIdx.x * 64;
    float acc[4][4] = {};
    for (int k0 = 0; k0 < Kd; k0 += 16) {
#pragma unroll
        for (int i = 0; i < 4; i++) {
            int e = tid + i * 256;
            int m = e >> 4, kk = e & 15;
            int gm = m0 + m, gk = k0 + kk;
            float v = 0.f;
            if (gm < M && gk < Kd) v = A[(long)gm * lda + gk];
            As[kk][m] = v;
        }
#pragma unroll
        for (int i = 0; i < 4; i++) {
            int e = tid + i * 256;
            int n = e >> 4, kk = e & 15;
            int gn = n0 + n, gk = k0 + kk;
            float v = 0.f;
            if (gn < N && gk < Kd) v = Bm[(long)gn * ldb + gk];
            Bs[kk][n] = v;
        }
        __syncthreads();
#pragma unroll
        for (int kk = 0; kk < 16; kk++) {
            float a[4], b[4];
#pragma unroll
            for (int i = 0; i < 4; i++) a[i] = As[kk][ty + 16 * i];
#pragma unroll
            for (int j = 0; j < 4; j++) b[j] = Bs[kk][tx + 16 * j];
#pragma unroll
            for (int i = 0; i < 4; i++)
#pragma unroll
                for (int j = 0; j < 4; j++)
                    acc[i][j] = fmaf(a[i], b[j], acc[i][j]);
        }
        __syncthreads();
    }
#pragma unroll
    for (int i = 0; i < 4; i++) {
        int m = m0 + ty + 16 * i;
        if (m >= M) continue;
#pragma unroll
        for (int j = 0; j < 4; j++) {
            int n = n0 + tx + 16 * j;
            if (n >= N) continue;
            float v = acc[i][j];
            if (bias) v += bias[n];
            if (RELU) v = fmaxf(v, 0.f);
            C[(long)m * ldc + n] = v;
        }
    }
}

// ---------------- RNG / conversions / prep ----------------
__global__ void eps_kernel(unsigned a0, unsigned a1, unsigned e0, unsigned e1,
                           unsigned t0, unsigned t1) {
    int i = blockIdx.x * blockDim.x + threadIdx.x;
    if (i < NA_) {
        g_eps_a[i] = partitionable_normal(a0, a1, (unsigned)i);
    } else if (i < NA_ + NE_) {
        int j = i - NA_;
        g_eps_e[j] = partitionable_normal(e0, e1, (unsigned)j);
    } else if (i < NA_ + 2 * NE_) {
        int j = i - NA_ - NE_;
        g_eps_t[j] = partitionable_normal(t0, t1, (unsigned)j);
    }
}

__global__ void convbf_vec_k(const float* __restrict__ src, int lds,
                             __nv_bfloat16* __restrict__ dst, int ldd, int C) {
    int c = (blockIdx.x * blockDim.x + threadIdx.x) * 8;
    if (c >= ldd) return;
    int r = blockIdx.y;
    const float* s = src + (long)r * lds;
    __nv_bfloat16 tmp[8];
    if (c + 8 <= C) {
        float4 a = *(const float4*)(s + c);
        float4 b = *(const float4*)(s + c + 4);
        tmp[0] = __float2bfloat16(a.x); tmp[1] = __float2bfloat16(a.y);
        tmp[2] = __float2bfloat16(a.z); tmp[3] = __float2bfloat16(a.w);
        tmp[4] = __float2bfloat16(b.x); tmp[5] = __float2bfloat16(b.y);
        tmp[6] = __float2bfloat16(b.z); tmp[7] = __float2bfloat16(b.w);
    } else {
#pragma unroll
        for (int j = 0; j < 8; j++) {
            int cc = c + j;
            tmp[j] = __float2bfloat16(cc < C ? s[cc] : 0.f);
        }
    }
    *(uint4*)&dst[(long)r * ldd + c] = *(uint4*)tmp;
}

__global__ void convbf_row_k(const float* __restrict__ src, int lds,
                             __nv_bfloat16* __restrict__ dst, int ldd, int C) {
    int c = blockIdx.x * blockDim.x + threadIdx.x;
    if (c >= ldd) return;
    int r = blockIdx.y;
    float v = (c < C) ? src[(long)r * lds + c] : 0.f;
    dst[(long)r * ldd + c] = __float2bfloat16(v);
}

__global__ void transpose_bf_k(const float* __restrict__ src,
                               __nv_bfloat16* __restrict__ dst,
                               int R, int C, int ldd) {
    __shared__ float tile[32][33];
    int c0 = blockIdx.x * 32, r0 = blockIdx.y * 32;
#pragma unroll
    for (int i = 0; i < 4; i++) {
        int r = r0 + threadIdx.y + i * 8;
        int c = c0 + threadIdx.x;
        tile[threadIdx.y + i * 8][threadIdx.x] = (r < R && c < C) ? src[(long)r * C + c] : 0.f;
    }
    __syncthreads();
#pragma unroll
    for (int i = 0; i < 4; i++) {
        int orow = c0 + threadIdx.y + i * 8;
        int ocol = r0 + threadIdx.x;
        if (orow < C)
            dst[(long)orow * ldd + ocol] = __float2bfloat16(tile[threadIdx.x][threadIdx.y + i * 8]);
    }
}

__global__ void betaT_k() {
    __shared__ float sm[64][33];
    int t = blockIdx.y;
    int v0 = blockIdx.x * 32;
    int lane = threadIdx.x & 31, w = threadIdx.x >> 5;
    for (int k = w; k < 64; k += 8) {
        int v = v0 + lane;
        sm[k][lane] = (k < K_ && v < V_) ? g_beta[((long)t * K_ + k) * V_ + v] : 0.f;
    }
    __syncthreads();
    int r = threadIdx.x >> 3;
    int c0 = (threadIdx.x & 7) * 8;
    if (v0 + r < V_) {
        __nv_bfloat16 tmp[8];
#pragma unroll
        for (int j = 0; j < 8; j++) tmp[j] = __float2bfloat16(sm[c0 + j][r]);
        *(uint4*)&g_betaT_bf[((long)t * NP_V + v0 + r) * 64 + c0] = *(uint4*)tmp;
    }
}

// fused prep: whhT/wih bf16 (interleaved), bi, wml
__global__ void prep_fused_k(const float* __restrict__ Wih, const float* __restrict__ Whh,
                             const float* __restrict__ bih, const float* __restrict__ bhh,
                             const float* __restrict__ mutW, const float* __restrict__ mutb,
                             const float* __restrict__ lstW, const float* __restrict__ lstb) {
    int idx = blockIdx.x * blockDim.x + threadIdx.x;
    const int S1 = HE_ * 4 * HE_;
    const int S2 = S1 + 4 * HE_ * HE_;
    const int S3 = S2 + 4 * HE_;
    const int S4 = S3 + 128 * HT_;
    const int S5 = S4 + 128;
    if (idx < S1) {
        int k = idx >> 10, r = idx & 1023;
        int j = r >> 2, gate = r & 3;
        g_whhT_bf[idx] = __float2bfloat16(Whh[((long)(gate * HE_ + j)) * HE_ + k]);
    } else if (idx < S2) {
        int i = idx - S1;
        int r = i >> 8, k = i & 255;
        int j = r >> 2, gate = r & 3;
        g_wih_bf[i] = __float2bfloat16(Wih[((long)(gate * HE_ + j)) * HE_ + k]);
    } else if (idx < S3) {
        int r = idx - S2;
        int j = r >> 2, gate = r & 3;
        g_bi_int[r] = bih[gate * HE_ + j] + bhh[gate * HE_ + j];
    } else if (idx < S4) {
        int i = idx - S3;
        int row = i / HT_, k = i % HT_;
        float v = 0.f;
        if (row < 50) v = mutW[(long)row * HT_ + k];
        else if (row < 100) v = lstW[(long)(row - 50) * HT_ + k];
        g_wml_bf[i] = __float2bfloat16(v);
    } else if (idx < S5) {
        int r = idx - S4;
        g_wmlb[r] = (r < 50) ? mutb[r] : (r < 100 ? lstb[r - 50] : 0.f);
    }
}

__global__ void alphas_kernel(const float* __restrict__ muq, const float* __restrict__ lsq) {
    int idx = blockIdx.x * blockDim.x + threadIdx.x;
    if (idx >= NA_) return;
    int t = idx / (K_ * RHO_), rem = idx % (K_ * RHO_);
    int k = rem / RHO_, r = rem % RHO_;
    int src = (k * T_ + t) * RHO_ + r;
    float a = muq[src] + g_eps_a[idx] * expf(0.5f * lsq[src]);
    g_alphas[idx] = a;
    int row = t * K_ + k;
    g_alphas_bf[(long)row * KP_RHO + r] = __float2bfloat16(a);
}

__global__ void kld_alpha_kernel(const float* __restrict__ muq, const float* __restrict__ lsq) {
    __shared__ float red[256];
    float acc = 0.f;
    for (int idx = blockIdx.x * blockDim.x + threadIdx.x; idx < NA_;
         idx += gridDim.x * blockDim.x) {
        int t = idx / (K_ * RHO_), rem = idx % (K_ * RHO_);
        int k = rem / RHO_, r = rem % RHO_;
        int src = (k * T_ + t) * RHO_ + r;
        float mu = muq[src];
        float ls = lsq[src];
        float qls = fminf(fmaxf(ls, -100.f), 100.f);
        float pmu = (t == 0) ? 0.f : g_alphas[idx - K_ * RHO_];
        float pls = (t == 0) ? 0.f : LOGD;
        float d = mu - pmu;
        acc += (expf(qls) + d * d) / (expf(pls) + 1e-6f) - 1.f + pls - qls;
    }
    float s = block_sum(acc, red);
    if (threadIdx.x == 0) g_part_a[blockIdx.x] = s;
}

__global__ void softmax_rows_kernel() {
    __shared__ float red[256];
    long base = (long)blockIdx.x * V_;
    long basebf = (long)blockIdx.x * KP_V;
    int tid = threadIdx.x;
    float m = -FLT_MAX;
    for (int c = tid; c < V_; c += 256) m = fmaxf(m, g_beta[base + c]);
    m = block_max(m, red);
    float s = 0.f;
    for (int c = tid; c < V_; c += 256) {
        float e = expf(g_beta[base + c] - m);
        g_beta[base + c] = e; s += e;
    }
    s = block_sum(s, red);
    float inv = 1.f / s;
    for (int c = tid; c < V_; c += 256) {
        float b = g_beta[base + c] * inv;
        g_beta[base + c] = b;
        g_beta_bf[basebf + c] = __float2bfloat16(b);
    }
}

__global__ void combine_inp_k(const float* __restrict__ qeb) {
    int idx = blockIdx.x * blockDim.x + threadIdx.x;
    if (idx >= B_ * T_ * HE_) return;
    int j = idx & (HE_ - 1);
    float s = qeb[j];
#pragma unroll
    for (int z = 0; z < INP_SPLIT; z++) s += g_inp_part[(long)z * B_ * T_ * HE_ + idx];
    g_inp_bf[idx] = __float2bfloat16(s);
}

// ---------------- single-launch LSTM scan: 128 blocks x 2 batch rows ----------------
__global__ void __launch_bounds__(256) lstm_scan_k() {
    __shared__ float h[2][HE_];
    int j = threadIdx.x;
    int b0 = 2 * blockIdx.x, b1 = b0 + 1;
    float c0 = 0.f, c1 = 0.f;
    h[0][j] = 0.f; h[1][j] = 0.f;
    __syncthreads();
    const uint2* wT = (const uint2*)g_whhT_bf;
    for (int t = 0; t < T_; t++) {
        float a00 = 0.f, a10 = 0.f, a20 = 0.f, a30 = 0.f;
        float a01 = 0.f, a11 = 0.f, a21 = 0.f, a31 = 0.f;
#pragma unroll 4
        for (int k = 0; k < HE_; k++) {
            uint2 w = wT[k * 256 + j];
            float2 w01 = __bfloat1622float2(*(const __nv_bfloat162*)&w.x);
            float2 w23 = __bfloat1622float2(*(const __nv_bfloat162*)&w.y);
            float hb0 = h[0][k], hb1 = h[1][k];
            a00 = fmaf(w01.x, hb0, a00); a10 = fmaf(w01.y, hb0, a10);
            a20 = fmaf(w23.x, hb0, a20); a30 = fmaf(w23.y, hb0, a30);
            a01 = fmaf(w01.x, hb1, a01); a11 = fmaf(w01.y, hb1, a11);
            a21 = fmaf(w23.x, hb1, a21); a31 = fmaf(w23.y, hb1, a31);
        }
        __syncthreads();
        {
            float4 gx4 = *(const float4*)&g_gx[((long)b0 * T_ + t) * (4 * HE_) + 4 * j];
            float gi = gx4.x + a00, gf = gx4.y + a10, gg = gx4.z + a20, go = gx4.w + a30;
            float si = 1.f / (1.f + expf(-gi));
            float sf = 1.f / (1.f + expf(-gf));
            float so = 1.f / (1.f + expf(-go));
            c0 = sf * c0 + si * tanhf(gg);
            float hh = so * tanhf(c0);
            h[0][j] = hh;
            g_lstm[((long)t * B_ + b0) * HE_ + j] = hh;
        }
        {
            float4 gx4 = *(const float4*)&g_gx[((long)b1 * T_ + t) * (4 * HE_) + 4 * j];
            float gi = gx4.x + a01, gf = gx4.y + a11, gg = gx4.z + a21, go = gx4.w + a31;
            float si = 1.f / (1.f + expf(-gi));
            float sf = 1.f / (1.f + expf(-gf));
            float so = 1.f / (1.f + expf(-go));
            c1 = sf * c1 + si * tanhf(gg);
            float hh = so * tanhf(c1);
            h[1][j] = hh;
            g_lstm[((long)t * B_ + b1) * HE_ + j] = hh;
        }
        __syncthreads();
    }
}

// ---------------- single-launch eta scan: 64 blocks x 4 batch rows ----------------
#define ETA_SMEM (100*306*2 + (4*306 + 200 + 200 + 200) * 4)
__global__ void __launch_bounds__(256) eta_scan_k(
    const float* __restrict__ mueW, const float* __restrict__ mueb,
    const float* __restrict__ lseW, const float* __restrict__ lseb) {
    extern __shared__ char smc[];
    __nv_bfloat16* wsm = (__nv_bfloat16*)smc;
    float* z   = (float*)(smc + 100 * 306 * 2);
    float* smu = z + 4 * 306;
    float* sls = smu + 200;
    float* skl = sls + 200;
    int tid = threadIdx.x, bk = blockIdx.x;
    for (int i = tid; i < 100 * 306; i += 256) {
        int r = i / 306, k = i % 306;
        float v = (r < 50) ? mueW[(long)r * HEK_ + k] : lseW[(long)(r - 50) * HEK_ + k];
        wsm[i] = __float2bfloat16(v);
    }
    if (tid < 200) {
        int q = tid / 50, k = tid % 50;
        z[q * 306 + 256 + k] = 0.f;
    }
    __syncthreads();
    for (int t = 0; t < T_; t++) {
#pragma unroll
        for (int q = 0; q < 4; q++)
            z[q * 306 + tid] = g_lstm[((long)t * B_ + 4 * bk + q) * HE_ + tid];
        __syncthreads();
#pragma unroll
        for (int rep = 0; rep < 2; rep++) {
            int o = tid + rep * 256;
            if (o < 400) {
                int q = o / 100, r = o % 100;
                float acc = (r < 50) ? mueb[r] : lseb[r - 50];
                const __nv_bfloat16* wr = wsm + r * 306;
                const float* zq = z + q * 306;
#pragma unroll 2
                for (int k = 0; k < HEK_; k++)
                    acc = fmaf(__bfloat162float(wr[k]), zq[k], acc);
                if (r < 50) smu[q * 50 + r] = acc;
                else        sls[q * 50 + (r - 50)] = acc;
            }
        }
        __syncthreads();
        if (tid < 200) {
            int q = tid / 50, k = tid % 50;
            int b = 4 * bk + q;
            float mu = smu[q * 50 + k], ls = sls[q * 50 + k];
            float pmu = z[q * 306 + 256 + k];
            float eps = g_eps_e[((long)t * B_ + b) * K_ + k];
            float eta = mu + eps * expf(0.5f * ls);
            g_etas[((long)t * B_ + b) * K_ + k] = eta;
            float qls = fminf(fmaxf(ls, -100.f), 100.f);
            float pls = (t == 0) ? 0.f : LOGD;
            float d = mu - pmu;
            skl[tid] = (expf(qls) + d * d) / (expf(pls) + 1e-6f) - 1.f + pls - qls;
            z[q * 306 + 256 + k] = eta;
        }
        __syncthreads();
        if (tid < 4) {
            float s = 0.f;
            for (int k = 0; k < 50; k++) s += skl[tid * 50 + k];
            g_part_ke[t * B_ + 4 * bk + tid] = s;
        }
        __syncthreads();
    }
}

// h1 = relu(h1e + sum_z h1b_part) -> bf16
__global__ void combine_h1_kernel() {
    int j = blockIdx.x * blockDim.x + threadIdx.x;
    if (j >= HT_) return;
    int row = blockIdx.y;
    int b = row & (B_ - 1);
    float hb = 0.f;
#pragma unroll
    for (int z = 0; z < H1B_SPLIT; z++) hb += g_h1b_part[(long)z * B_ * HT_ + b * HT_ + j];
    long idx = (long)row * HT_ + j;
    float v = fmaxf(g_h1e[idx] + hb, 0.f);
    g_h1_bf[idx] = __float2bfloat16(v);
}

__global__ void theta_kernel() {
    __shared__ float red[64];
    int row = blockIdx.x, k = threadIdx.x;
    long base = (long)row * K_;
    long mbase = (long)row * 100;
    bool val = k < K_;
    float mu = 0.f, ls = 0.f, zv = -FLT_MAX;
    if (val) {
        mu = g_mls[mbase + k];
        ls = g_mls[mbase + 50 + k];
        zv = mu + g_eps_t[base + k] * expf(0.5f * ls);
    }
    float mx = block_max(zv, red);
    float e = val ? expf(zv - mx) : 0.f;
    float sum = block_sum(e, red);
    float th = e / sum;
    if (val) {
        g_theta_arr[base + k] = th;
        g_theta_bf[(long)row * 64 + k] = __float2bfloat16(th);
    } else if (k < 64) {
        g_theta_bf[(long)row * 64 + k] = __float2bfloat16(0.f);
    }
    float kl = 0.f;
    if (val) {
        float qls = fminf(fmaxf(ls, -100.f), 100.f);
        float d = mu - g_etas[base + k];
        kl = (expf(qls) + d * d) / (1.f + 1e-6f) - 1.f - qls;
    }
    float s = block_sum(kl, red);
    if (k == 0) g_part_kt[row] = s;
}

__global__ void final_reduce_kernel(float* out, int out_size) {
    __shared__ float red[256];
    int tid = threadIdx.x;
    float v;
    v = 0.f; for (int i = tid; i < RB_NLL;  i += 256) v += g_part_nll[i];
    float nll  = block_sum(v, red) * (10.0f / B_);
    v = 0.f; for (int i = tid; i < T_ * B_; i += 256) v += g_part_kt[i];
    float kt   = block_sum(v, red) * (0.5f / (T_ * B_));
    v = 0.f; for (int i = tid; i < RB_A;    i += 256) v += g_part_a[i];
    float ka   = block_sum(v, red) * (0.5f / (T_ * K_));
    v = 0.f; for (int i = tid; i < T_ * B_; i += 256) v += g_part_ke[i];
    float ke   = block_sum(v, red) * (0.5f / B_);
    v = 0.f; for (int i = tid; i < RB_COND; i += 256) v += g_part_cond[i];
    float cond = block_sum(v, red) * (-0.01f);
    if (tid == 0) {
        if (out_size > 0) out[0] = nll;
        if (out_size > 1) out[1] = kt;
        if (out_size > 2) out[2] = ka;
        if (out_size > 3) out[3] = ke;
        if (out_size > 4) out[4] = cond;
    }
}

// ---------------- host driver ----------------
static inline int ceil_div(long a, long b) { return (int)((a + b - 1) / b); }

extern "C" void kernel_launch(void* const* d_in, const int* in_sizes, int n_in,
                              void* d_out, int out_size) {
    (void)in_sizes; (void)n_in;
    const float* nb   = (const float*)d_in[0];
    const float* bow  = (const float*)d_in[1];
    const float* adj  = (const float*)d_in[2];
    const float* muqa = (const float*)d_in[3];
    const float* lsqa = (const float*)d_in[4];
    const float* rhoW = (const float*)d_in[5];
    const float* rhob = (const float*)d_in[6];
    const float* W1   = (const float*)d_in[7];
    const float* b1   = (const float*)d_in[8];
    const float* W2   = (const float*)d_in[9];
    const float* b2   = (const float*)d_in[10];
    const float* mutW = (const float*)d_in[11];
    const float* mutb = (const float*)d_in[12];
    const float* lstW = (const float*)d_in[13];
    const float* lstb = (const float*)d_in[14];
    const float* qeW  = (const float*)d_in[15];
    const float* qeb  = (const float*)d_in[16];
    const float* Wih  = (const float*)d_in[17];
    const float* Whh  = (const float*)d_in[18];
    const float* bih  = (const float*)d_in[19];
    const float* bhh  = (const float*)d_in[20];
    const float* mueW = (const float*)d_in[21];
    const float* mueb = (const float*)d_in[22];
    const float* lseW = (const float*)d_in[23];
    const float* lseb = (const float*)d_in[24];
    float* out = (float*)d_out;

    unsigned ka0, ka1, ke0, ke1, kt0, kt1;
    tf2x32(0u, 42u, 0u, 0u, &ka0, &ka1);
    tf2x32(0u, 42u, 0u, 1u, &ke0, &ke1);
    tf2x32(0u, 42u, 0u, 2u, &kt0, &kt1);

    float *p_beta, *p_inp_part, *p_gx, *p_etas, *p_h1e, *p_h1b_part, *p_mls;
    float *p_bi_int, *p_part_cond, *p_wmlb;
    __nv_bfloat16 *p_alphas_bf, *p_beta_bf, *p_adjT, *p_bow_bf, *p_qew_bf, *p_nb_bf;
    __nv_bfloat16 *p_w1_bf, *p_rhow_bf, *p_w2_bf, *p_wml_bf, *p_h1_bf, *p_h2_bf;
    __nv_bfloat16 *p_inp_bf, *p_wih_bf;
    cudaGetSymbolAddress((void**)&p_beta,      g_beta);
    cudaGetSymbolAddress((void**)&p_inp_part,  g_inp_part);
    cudaGetSymbolAddress((void**)&p_gx,        g_gx);
    cudaGetSymbolAddress((void**)&p_etas,      g_etas);
    cudaGetSymbolAddress((void**)&p_h1e,       g_h1e);
    cudaGetSymbolAddress((void**)&p_h1b_part,  g_h1b_part);
    cudaGetSymbolAddress((void**)&p_mls,       g_mls);
    cudaGetSymbolAddress((void**)&p_bi_int,    g_bi_int);
    cudaGetSymbolAddress((void**)&p_part_cond, g_part_cond);
    cudaGetSymbolAddress((void**)&p_wmlb,      g_wmlb);
    cudaGetSymbolAddress((void**)&p_alphas_bf, g_alphas_bf);
    cudaGetSymbolAddress((void**)&p_beta_bf,   g_beta_bf);
    cudaGetSymbolAddress((void**)&p_adjT,      g_adjT_bf);
    cudaGetSymbolAddress((void**)&p_bow_bf,    g_bow_bf);
    cudaGetSymbolAddress((void**)&p_qew_bf,    g_qew_bf);
    cudaGetSymbolAddress((void**)&p_nb_bf,     g_nb_bf);
    cudaGetSymbolAddress((void**)&p_w1_bf,     g_w1_bf);
    cudaGetSymbolAddress((void**)&p_rhow_bf,   g_rhow_bf);
    cudaGetSymbolAddress((void**)&p_w2_bf,     g_w2_bf);
    cudaGetSymbolAddress((void**)&p_wml_bf,    g_wml_bf);
    cudaGetSymbolAddress((void**)&p_h1_bf,     g_h1_bf);
    cudaGetSymbolAddress((void**)&p_h2_bf,     g_h2_bf);
    cudaGetSymbolAddress((void**)&p_inp_bf,    g_inp_bf);
    cudaGetSymbolAddress((void**)&p_wih_bf,    g_wih_bf);

    cudaFuncSetAttribute(tc_gemm_k<true,  false, false, false>, cudaFuncAttributeMaxDynamicSharedMemorySize, TC_SMEM_BYTES);
    cudaFuncSetAttribute(tc_gemm_k<false, false, false, true >, cudaFuncAttributeMaxDynamicSharedMemorySize, TC_SMEM_BYTES);
    cudaFuncSetAttribute(tc_gemm_k<false, false, false, false>, cudaFuncAttributeMaxDynamicSharedMemorySize, TC_SMEM_BYTES);
    cudaFuncSetAttribute(tc_gemm_k<true,  true,  true,  false>, cudaFuncAttributeMaxDynamicSharedMemorySize, TC_SMEM_BYTES);
    cudaFuncSetAttribute(eta_scan_k, cudaFuncAttributeMaxDynamicSharedMemorySize, ETA_SMEM);

    // ---- alpha/beta chain first (4th launch = pipelined beta TC GEMM, A/B vs R13) ----
    convbf_vec_k<<<dim3(ceil_div(KP_RHO / 8, 256), V_), 256>>>(rhoW, RHO_, p_rhow_bf, KP_RHO, RHO_);
    int totalElems = NA_ + 2 * NE_;
    eps_kernel<<<(totalElems + 255) / 256, 256>>>(ka0, ka1, ke0, ke1, kt0, kt1);
    alphas_kernel<<<(NA_ + 255) / 256, 256>>>(muqa, lsqa);
    tc_gemm_k<true, false, false, false><<<dim3(ceil_div(V_, 128), ceil_div(T_ * K_, 128)), 256, TC_SMEM_BYTES>>>(
        p_alphas_bf, KP_RHO, p_rhow_bf, KP_RHO, rhob, p_beta, nullptr, V_,
        nullptr, nullptr, T_ * K_, V_, KP_RHO);
    kld_alpha_kernel<<<RB_A, 256>>>(muqa, lsqa);
    softmax_rows_kernel<<<T_ * K_, 256>>>();
    betaT_k<<<dim3(ceil_div(V_, 32), T_), 256>>>();
    transpose_bf_k<<<dim3(ceil_div(V_, 32), ceil_div(V_, 32)), dim3(32, 8)>>>(adj, p_adjT, V_, V_, KP_V);
    tc_gemm_k<false, false, false, true><<<dim3(ceil_div(V_, 128), ceil_div(T_ * K_, 128)), 256, TC_SMEM_BYTES>>>(
        p_beta_bf, KP_V, p_adjT, KP_V, nullptr, nullptr, nullptr, V_,
        p_beta, p_part_cond, T_ * K_, V_, KP_V);

    // ---- conversions + prep ----
    convbf_vec_k<<<dim3(ceil_div(KP_V / 8, 256), B_ * T_), 256>>>(bow, V_, p_bow_bf, KP_V, V_);
    convbf_vec_k<<<dim3(ceil_div(KP_V / 8, 256), HE_), 256>>>(qeW, V_, p_qew_bf, KP_V, V_);
    convbf_vec_k<<<dim3(ceil_div(KP_V / 8, 256), B_), 256>>>(nb, V_, p_nb_bf, KP_V, V_);
    convbf_row_k<<<dim3(ceil_div(KP_V, 256), HT_), 256>>>(W1, VK_, p_w1_bf, KP_V, V_);
    convbf_vec_k<<<dim3(ceil_div(HT_ / 8, 256), HT_), 256>>>(W2, HT_, p_w2_bf, HT_, HT_);
    {
        int preptotal = HE_ * 4 * HE_ + 4 * HE_ * HE_ + 4 * HE_ + 128 * HT_ + 128;
        prep_fused_k<<<(preptotal + 255) / 256, 256>>>(Wih, Whh, bih, bhh, mutW, mutb, lstW, lstb);
    }

    // ---- inp (split-K) -> bf16 combine -> gx (TC) -> LSTM scan -> eta scan ----
    tc_gemm_k<false, false, false, false><<<dim3(ceil_div(HE_, 128), ceil_div(B_ * T_, 128), INP_SPLIT), 256, TC_SMEM_BYTES>>>(
        p_bow_bf, KP_V, p_qew_bf, KP_V, nullptr, p_inp_part, nullptr, HE_,
        nullptr, nullptr, B_ * T_, HE_, KP_V);
    combine_inp_k<<<ceil_div(B_ * T_ * HE_, 256), 256>>>(qeb);
    tc_gemm_k<true, false, false, false><<<dim3(8, 24), 256, TC_SMEM_BYTES>>>(
        p_inp_bf, HE_, p_wih_bf, HE_, p_bi_int, p_gx, nullptr, 4 * HE_,
        nullptr, nullptr, B_ * T_, 4 * HE_, HE_);
    lstm_scan_k<<<128, 256>>>();
    eta_scan_k<<<64, 256, ETA_SMEM>>>(mueW, mueb, lseW, lseb);

    // ---- theta encoder ----
    gemm_k<false><<<dim3(13, 48), 256>>>(
        p_etas, K_, W1 + V_, VK_, b1, p_h1e, HT_, T_ * B_, HT_, K_);
    tc_gemm_k<false, false, false, false><<<dim3(ceil_div(HT_, 128), ceil_div(B_, 128), H1B_SPLIT), 256, TC_SMEM_BYTES>>>(
        p_nb_bf, KP_V, p_w1_bf, KP_V, nullptr, p_h1b_part, nullptr, HT_,
        nullptr, nullptr, B_, HT_, KP_V);
    combine_h1_kernel<<<dim3(ceil_div(HT_, 256), T_ * B_), 256>>>();
    tc_gemm_k<true, true, true, false><<<dim3(ceil_div(HT_, 128), ceil_div(T_ * B_, 128)), 256, TC_SMEM_BYTES>>>(
        p_h1_bf, HT_, p_w2_bf, HT_, b2, nullptr, p_h2_bf, HT_,
        nullptr, nullptr, T_ * B_, HT_, HT_);
    tc_gemm_k<true, false, false, false><<<dim3(1, ceil_div(T_ * B_, 128)), 256, TC_SMEM_BYTES>>>(
        p_h2_bf, HT_, p_wml_bf, HT_, p_wmlb, p_mls, nullptr, 100,
        nullptr, nullptr, T_ * B_, 100, HT_);

    // ---- theta + NLL + final ----
    theta_kernel<<<T_ * B_, 64>>>();
    tc_nll_k<<<dim3(40, 2, T_), 256>>>(bow);
    final_reduce_kernel<<<1, 256>>>(out, out_size);
}

// round 15
// speedup vs baseline: 5.0892x; 1.0794x over previous
#include <cuda_runtime.h>
#include <cuda_bf16.h>
#include <cstdint>
#include <float.h>
#include <math.h>

// ---------------- problem constants ----------------
#define T_    12
#define K_    50
#define V_    5000
#define B_    256
#define RHO_  300
#define HT_   800
#define HE_   256
#define VK_   (V_ + K_)
#define HEK_  (HE_ + K_)   // 306
#define LOGD  (-5.2983173665480363f)

#define NA_   (T_*K_*RHO_)
#define NE_   (T_*B_*K_)

#define KP_V   5024
#define KP_RHO 320
#define NP_V   5120
#define MP_TK  640

#define INP_SPLIT 6
#define H1B_SPLIT 12

// ---------------- device scratch ----------------
__device__ float g_eps_a[NA_];
__device__ float g_eps_e[NE_];
__device__ float g_eps_t[NE_];
__device__ float g_alphas[NA_];
__device__ __align__(16) __nv_bfloat16 g_alphas_bf[MP_TK*KP_RHO];
__device__ float g_beta[T_*K_*V_];
__device__ __align__(16) __nv_bfloat16 g_beta_bf[MP_TK*KP_V];
__device__ __align__(16) __nv_bfloat16 g_betaT_bf[T_*NP_V*64];
__device__ __align__(16) __nv_bfloat16 g_adjT_bf[NP_V*KP_V];
__device__ __align__(16) __nv_bfloat16 g_bow_bf[B_*T_*KP_V];
__device__ __align__(16) __nv_bfloat16 g_qew_bf[HE_*KP_V];
__device__ __align__(16) __nv_bfloat16 g_nb_bf[B_*KP_V];
__device__ __align__(16) __nv_bfloat16 g_w1_bf[896*KP_V];
__device__ __align__(16) __nv_bfloat16 g_rhow_bf[NP_V*KP_RHO];
__device__ __align__(16) __nv_bfloat16 g_w2_bf[896*HT_];
__device__ __align__(16) __nv_bfloat16 g_wml_bf[128*HT_];
__device__ float g_wmlb[128];
__device__ __align__(16) __nv_bfloat16 g_whhT_bf[HE_*4*HE_];   // [k][1024] interleaved j*4+gate
__device__ __align__(16) __nv_bfloat16 g_wih_bf[4*HE_*HE_];    // [1024 rows j*4+g][k=256]
__device__ float g_bi_int[4*HE_];
__device__ __align__(16) __nv_bfloat16 g_inp_bf[B_*T_*HE_];
__device__ float g_inp_part[INP_SPLIT*B_*T_*HE_];
__device__ float g_gx[B_*T_*4*HE_];
__device__ float g_lstm[T_*B_*HE_];
__device__ float g_etas[NE_];
__device__ float g_h1e[T_*B_*HT_];
__device__ float g_h1b_part[H1B_SPLIT*B_*HT_];
__device__ __align__(16) __nv_bfloat16 g_h1_bf[T_*B_*HT_];
__device__ __align__(16) __nv_bfloat16 g_h2_bf[T_*B_*HT_];
__device__ float g_mls[T_*B_*100];
__device__ float g_theta_arr[NE_];
__device__ __align__(16) __nv_bfloat16 g_theta_bf[T_*B_*64];

#define RB_NLL  (12*2*40)
#define RB_COND 400          // 40 x 10 blocks
#define RB_A    256
__device__ float g_part_nll[RB_NLL];
__device__ float g_part_cond[RB_COND];
__device__ float g_part_a[RB_A];
__device__ float g_part_kt[T_*B_];
__device__ float g_part_ke[T_*B_];

// ---------------- threefry2x32 (JAX partitionable) ----------------
__host__ __device__ inline void tf2x32(unsigned k0, unsigned k1,
                                       unsigned x0, unsigned x1,
                                       unsigned* o0, unsigned* o1) {
    unsigned ks0 = k0, ks1 = k1, ks2 = k0 ^ k1 ^ 0x1BD11BDAu;
    x0 += ks0; x1 += ks1;
#define TF_R(r) { x0 += x1; x1 = (x1 << (r)) | (x1 >> (32 - (r))); x1 ^= x0; }
    TF_R(13) TF_R(15) TF_R(26) TF_R(6)
    x0 += ks1; x1 += ks2 + 1u;
    TF_R(17) TF_R(29) TF_R(16) TF_R(24)
    x0 += ks2; x1 += ks0 + 2u;
    TF_R(13) TF_R(15) TF_R(26) TF_R(6)
    x0 += ks0; x1 += ks1 + 3u;
    TF_R(17) TF_R(29) TF_R(16) TF_R(24)
    x0 += ks1; x1 += ks2 + 4u;
    TF_R(13) TF_R(15) TF_R(26) TF_R(6)
    x0 += ks2; x1 += ks0 + 5u;
#undef TF_R
    *o0 = x0; *o1 = x1;
}

__device__ __forceinline__ float bits2normal(unsigned bits) {
    float f = __uint_as_float((bits >> 9) | 0x3F800000u) - 1.0f;
    const float lo = -0.99999994f;
    float u = fmaf(f, 2.0f, lo);
    u = fmaxf(lo, u);
    return 1.4142135381698608f * erfinvf(u);
}

__device__ __forceinline__ float partitionable_normal(unsigned k0, unsigned k1, unsigned i) {
    unsigned o0, o1;
    tf2x32(k0, k1, 0u, i, &o0, &o1);
    return bits2normal(o0 ^ o1);
}

// ---------------- block reductions ----------------
__device__ __forceinline__ float block_sum(float v, float* red) {
    int tid = threadIdx.x, n = blockDim.x;
    red[tid] = v; __syncthreads();
    for (int s = n >> 1; s > 0; s >>= 1) {
        if (tid < s) red[tid] += red[tid + s];
        __syncthreads();
    }
    v = red[0]; __syncthreads();
    return v;
}
__device__ __forceinline__ float block_max(float v, float* red) {
    int tid = threadIdx.x, n = blockDim.x;
    red[tid] = v; __syncthreads();
    for (int s = n >> 1; s > 0; s >>= 1) {
        if (tid < s) red[tid] = fmaxf(red[tid], red[tid + s]);
        __syncthreads();
    }
    v = red[0]; __syncthreads();
    return v;
}

// ---------------- mma / ldmatrix / cp.async helpers ----------------
__device__ __forceinline__ void mma16816(float* c, const uint32_t* a, uint32_t b0, uint32_t b1) {
    asm volatile(
        "mma.sync.aligned.m16n8k16.row.col.f32.bf16.bf16.f32 "
        "{%0,%1,%2,%3}, {%4,%5,%6,%7}, {%8,%9}, {%0,%1,%2,%3};\n"
        : "+f"(c[0]), "+f"(c[1]), "+f"(c[2]), "+f"(c[3])
        : "r"(a[0]), "r"(a[1]), "r"(a[2]), "r"(a[3]), "r"(b0), "r"(b1));
}
__device__ __forceinline__ void ldsm_x4(uint32_t* d, uint32_t smaddr) {
    asm volatile("ldmatrix.sync.aligned.m8n8.x4.shared.b16 {%0,%1,%2,%3}, [%4];\n"
        : "=r"(d[0]), "=r"(d[1]), "=r"(d[2]), "=r"(d[3]) : "r"(smaddr));
}
#define CPASYNC16(sp, gp) \
    asm volatile("cp.async.cg.shared.global [%0], [%1], 16;\n" \
        :: "r"((unsigned)__cvta_generic_to_shared(sp)), "l"(gp))
#define CPCOMMIT() asm volatile("cp.async.commit_group;\n")
#define CPWAIT(n)  asm volatile("cp.async.wait_group %0;\n" :: "n"(n))

#define A_CH (64 * 40)
#define B_CH (128 * 40)
#define TC_SMEM_BYTES (3 * (A_CH + B_CH) * 2)   // 3-stage ring: 46080 B -> 3 blocks/SM

// ---------------- pipelined bf16 TC GEMM (NT), tile 64x128, 3 blocks/SM ----------------
template<bool BIAS, bool RELU, bool OUTBF, bool CONDEPI>
__global__ void __launch_bounds__(256, 3) tc_gemm_k(
    const __nv_bfloat16* __restrict__ A, int lda,
    const __nv_bfloat16* __restrict__ B, int ldb,
    const float* __restrict__ bias,
    float* __restrict__ C, __nv_bfloat16* __restrict__ Cbf, int ldc,
    const float* __restrict__ Cf, float* __restrict__ part,
    int M, int N, int Kp) {
    extern __shared__ __nv_bfloat16 smp[];
    __nv_bfloat16* As = smp;                 // 3 × [64][40]
    __nv_bfloat16* Bs = smp + 3 * A_CH;      // 3 × [128][40]
    __shared__ float red[256];
    int tid = threadIdx.x;
    int lane = tid & 31, wid = tid >> 5;
    int wm = wid & 1, wn = wid >> 1;         // 2 m-warps x 4 n-warps
    int g = lane >> 2, t4 = lane & 3;
    long m0 = (long)blockIdx.y * 64, n0 = (long)blockIdx.x * 128;
    int arow = tid >> 2;                     // 0..63
    int akc = (tid & 3) * 8;
    float acc[2][4][4] = {};

    // ldmatrix per-lane address components (elements)
    int a_row_off = wm * 32 + (lane & 7) + 8 * ((lane >> 3) & 1);  // + i*16
    int a_col_off = 8 * (lane >> 4);                               // + ks
    int b_row_off = wn * 32 + (lane & 7) + 8 * (lane >> 4);        // + j2*16
    int b_col_off = 8 * ((lane >> 3) & 1);                         // + ks
    uint32_t as_base = (uint32_t)__cvta_generic_to_shared(As);
    uint32_t bs_base = (uint32_t)__cvta_generic_to_shared(Bs);

    int nkt = Kp >> 5;
    int per = (nkt + gridDim.z - 1) / gridDim.z;
    int it0 = blockIdx.z * per;
    int itn = nkt - it0; if (itn > per) itn = per; if (itn < 0) itn = 0;

#define TC_ISSUE(IT, S) do {                                                     \
        int _k = ((IT) << 5) + akc;                                              \
        __nv_bfloat16* _as = As + (size_t)(S) * A_CH;                            \
        __nv_bfloat16* _bs = Bs + (size_t)(S) * B_CH;                            \
        CPASYNC16(&_as[(size_t)arow * 40 + akc],        &A[(m0 + arow) * (long)lda + _k]);        \
        CPASYNC16(&_bs[(size_t)arow * 40 + akc],        &B[(n0 + arow) * (long)ldb + _k]);        \
        CPASYNC16(&_bs[(size_t)(arow + 64) * 40 + akc], &B[(n0 + arow + 64) * (long)ldb + _k]);   \
        CPCOMMIT();                                                              \
    } while (0)

    if (itn > 0) TC_ISSUE(it0, 0);
    if (itn > 1) TC_ISSUE(it0 + 1, 1);

    for (int ii = 0; ii < itn; ii++) {
        if (ii + 1 < itn) { CPWAIT(1); } else { CPWAIT(0); }
        __syncthreads();
        if (ii + 2 < itn) TC_ISSUE(it0 + ii + 2, (ii + 2) % 3);
        uint32_t asb = as_base + (uint32_t)((ii % 3) * A_CH) * 2u;
        uint32_t bsb = bs_base + (uint32_t)((ii % 3) * B_CH) * 2u;
#pragma unroll
        for (int ks = 0; ks < 32; ks += 16) {
            uint32_t a[2][4], b[2][4];
#pragma unroll
            for (int i = 0; i < 2; i++)
                ldsm_x4(a[i], asb + (uint32_t)((a_row_off + i * 16) * 40 + ks + a_col_off) * 2u);
#pragma unroll
            for (int j2 = 0; j2 < 2; j2++)
                ldsm_x4(b[j2], bsb + (uint32_t)((b_row_off + j2 * 16) * 40 + ks + b_col_off) * 2u);
#pragma unroll
            for (int j2 = 0; j2 < 2; j2++) {
#pragma unroll
                for (int i = 0; i < 2; i++) {
                    mma16816(acc[i][2 * j2],     a[i], b[j2][0], b[j2][1]);
                    mma16816(acc[i][2 * j2 + 1], a[i], b[j2][2], b[j2][3]);
                }
            }
        }
        __syncthreads();
    }
#undef TC_ISSUE

    if (CONDEPI) {
        float local = 0.f;
#pragma unroll
        for (int i = 0; i < 2; i++) {
#pragma unroll
            for (int j = 0; j < 4; j++) {
                long m = m0 + wm * 32 + i * 16 + g;
                long n = n0 + wn * 32 + j * 8 + 2 * t4;
                if (m < M) {
                    if (n < N)     local += acc[i][j][0] * Cf[m * ldc + n];
                    if (n + 1 < N) local += acc[i][j][1] * Cf[m * ldc + n + 1];
                }
                if (m + 8 < M) {
                    if (n < N)     local += acc[i][j][2] * Cf[(m + 8) * ldc + n];
                    if (n + 1 < N) local += acc[i][j][3] * Cf[(m + 8) * ldc + n + 1];
                }
            }
        }
        float s = block_sum(local, red);
        if (tid == 0)
            part[((long)blockIdx.z * gridDim.y + blockIdx.y) * gridDim.x + blockIdx.x] = s;
    } else {
        float* Cz = C ? C + (long)blockIdx.z * M * ldc : nullptr;
#pragma unroll
        for (int i = 0; i < 2; i++) {
#pragma unroll
            for (int j = 0; j < 4; j++) {
                long m = m0 + wm * 32 + i * 16 + g;
                long n = n0 + wn * 32 + j * 8 + 2 * t4;
#pragma unroll
                for (int q = 0; q < 4; q++) {
                    long mm = m + (q >> 1) * 8;
                    long nn = n + (q & 1);
                    if (mm < M && nn < N) {
                        float v = acc[i][j][q];
                        if (BIAS) v += bias[nn];
                        if (RELU) v = fmaxf(v, 0.f);
                        if (OUTBF) Cbf[mm * ldc + nn] = __float2bfloat16(v);
                        else       Cz[mm * ldc + nn] = v;
                    }
                }
            }
        }
    }
}

// ---------------- TC NLL ----------------
__global__ void __launch_bounds__(256) tc_nll_k(const float* __restrict__ bow) {
    __shared__ __nv_bfloat16 As[128][40];
    __shared__ __nv_bfloat16 Bs[128][40];
    __shared__ float red[256];
    int t = blockIdx.z;
    const __nv_bfloat16* A = g_theta_bf + (long)t * B_ * 64;
    const __nv_bfloat16* B = g_betaT_bf + (long)t * NP_V * 64;
    int tid = threadIdx.x;
    int lane = tid & 31, wid = tid >> 5;
    int wm = wid & 3, wn = wid >> 2;
    int g = lane >> 2, t4 = lane & 3;
    long m0 = (long)blockIdx.y * 128, n0 = (long)blockIdx.x * 128;
    int arow = tid >> 2;
    int akc = (tid & 3) * 8;
    float acc[2][8][4] = {};
    for (int k0 = 0; k0 < 64; k0 += 32) {
#pragma unroll
        for (int h = 0; h < 2; h++) {
            int r = arow + h * 64;
            *(uint4*)&As[r][akc] = *(const uint4*)&A[(m0 + r) * 64 + k0 + akc];
            *(uint4*)&Bs[r][akc] = *(const uint4*)&B[(n0 + r) * 64 + k0 + akc];
        }
        __syncthreads();
#pragma unroll
        for (int ks = 0; ks < 32; ks += 16) {
            uint32_t a[2][4];
#pragma unroll
            for (int i = 0; i < 2; i++) {
                int r = wm * 32 + i * 16 + g;
                a[i][0] = *(const uint32_t*)&As[r][ks + 2 * t4];
                a[i][1] = *(const uint32_t*)&As[r + 8][ks + 2 * t4];
                a[i][2] = *(const uint32_t*)&As[r][ks + 2 * t4 + 8];
                a[i][3] = *(const uint32_t*)&As[r + 8][ks + 2 * t4 + 8];
            }
#pragma unroll
            for (int j = 0; j < 8; j++) {
                int n = wn * 64 + j * 8 + g;
                uint32_t b0 = *(const uint32_t*)&Bs[n][ks + 2 * t4];
                uint32_t b1 = *(const uint32_t*)&Bs[n][ks + 2 * t4 + 8];
#pragma unroll
                for (int i = 0; i < 2; i++)
                    mma16816(acc[i][j], a[i], b0, b1);
            }
        }
        __syncthreads();
    }
    float local = 0.f;
#pragma unroll
    for (int i = 0; i < 2; i++) {
#pragma unroll
        for (int j = 0; j < 8; j++) {
            long m = m0 + wm * 32 + i * 16 + g;
            long n = n0 + wn * 64 + j * 8 + 2 * t4;
#pragma unroll
            for (int q = 0; q < 4; q++) {
                long bb = m + (q >> 1) * 8;
                long vv = n + (q & 1);
                if (vv < V_) {
                    float w = bow[(bb * T_ + t) * (long)V_ + vv];
                    local += -logf(acc[i][j][q] + 1e-6f) * w;
                }
            }
        }
    }
    float s = block_sum(local, red);
    if (tid == 0)
        g_part_nll[(blockIdx.z * 2 + blockIdx.y) * 40 + blockIdx.x] = s;
}

// ---------------- generic tiled fp32 GEMM (NT) ----------------
template<bool RELU>
__global__ void gemm_k(const float* __restrict__ A, int lda,
                       const float* __restrict__ Bm, int ldb,
                       const float* __restrict__ bias,
                       float* __restrict__ C, int ldc,
                       int M, int N, int Kd) {
    __shared__ float As[16][65];
    __shared__ float Bs[16][65];
    int tid = threadIdx.x;
    int tx = tid & 15, ty = tid >> 4;
    int m0 = blockIdx.y * 64, n0 = blockIdx.x * 64;
    float acc[4][4] = {};
    for (int k0 = 0; k0 < Kd; k0 += 16) {
#pragma unroll
        for (int i = 0; i < 4; i++) {
            int e = tid + i * 256;
            int m = e >> 4, kk = e & 15;
            int gm = m0 + m, gk = k0 + kk;
            float v = 0.f;
            if (gm < M && gk < Kd) v = A[(long)gm * lda + gk];
            As[kk][m] = v;
        }
#pragma unroll
        for (int i = 0; i < 4; i++) {
            int e = tid + i * 256;
            int n = e >> 4, kk = e & 15;
            int gn = n0 + n, gk = k0 + kk;
            float v = 0.f;
            if (gn < N && gk < Kd) v = Bm[(long)gn * ldb + gk];
            Bs[kk][n] = v;
        }
        __syncthreads();
#pragma unroll
        for (int kk = 0; kk < 16; kk++) {
            float a[4], b[4];
#pragma unroll
            for (int i = 0; i < 4; i++) a[i] = As[kk][ty + 16 * i];
#pragma unroll
            for (int j = 0; j < 4; j++) b[j] = Bs[kk][tx + 16 * j];
#pragma unroll
            for (int i = 0; i < 4; i++)
#pragma unroll
                for (int j = 0; j < 4; j++)
                    acc[i][j] = fmaf(a[i], b[j], acc[i][j]);
        }
        __syncthreads();
    }
#pragma unroll
    for (int i = 0; i < 4; i++) {
        int m = m0 + ty + 16 * i;
        if (m >= M) continue;
#pragma unroll
        for (int j = 0; j < 4; j++) {
            int n = n0 + tx + 16 * j;
            if (n >= N) continue;
            float v = acc[i][j];
            if (bias) v += bias[n];
            if (RELU) v = fmaxf(v, 0.f);
            C[(long)m * ldc + n] = v;
        }
    }
}

// ---------------- RNG / conversions / prep ----------------
__global__ void eps_kernel(unsigned a0, unsigned a1, unsigned e0, unsigned e1,
                           unsigned t0, unsigned t1) {
    int i = blockIdx.x * blockDim.x + threadIdx.x;
    if (i < NA_) {
        g_eps_a[i] = partitionable_normal(a0, a1, (unsigned)i);
    } else if (i < NA_ + NE_) {
        int j = i - NA_;
        g_eps_e[j] = partitionable_normal(e0, e1, (unsigned)j);
    } else if (i < NA_ + 2 * NE_) {
        int j = i - NA_ - NE_;
        g_eps_t[j] = partitionable_normal(t0, t1, (unsigned)j);
    }
}

__global__ void convbf_vec_k(const float* __restrict__ src, int lds,
                             __nv_bfloat16* __restrict__ dst, int ldd, int C) {
    int c = (blockIdx.x * blockDim.x + threadIdx.x) * 8;
    if (c >= ldd) return;
    int r = blockIdx.y;
    const float* s = src + (long)r * lds;
    __nv_bfloat16 tmp[8];
    if (c + 8 <= C) {
        float4 a = *(const float4*)(s + c);
        float4 b = *(const float4*)(s + c + 4);
        tmp[0] = __float2bfloat16(a.x); tmp[1] = __float2bfloat16(a.y);
        tmp[2] = __float2bfloat16(a.z); tmp[3] = __float2bfloat16(a.w);
        tmp[4] = __float2bfloat16(b.x); tmp[5] = __float2bfloat16(b.y);
        tmp[6] = __float2bfloat16(b.z); tmp[7] = __float2bfloat16(b.w);
    } else {
#pragma unroll
        for (int j = 0; j < 8; j++) {
            int cc = c + j;
            tmp[j] = __float2bfloat16(cc < C ? s[cc] : 0.f);
        }
    }
    *(uint4*)&dst[(long)r * ldd + c] = *(uint4*)tmp;
}

__global__ void convbf_row_k(const float* __restrict__ src, int lds,
                             __nv_bfloat16* __restrict__ dst, int ldd, int C) {
    int c = blockIdx.x * blockDim.x + threadIdx.x;
    if (c >= ldd) return;
    int r = blockIdx.y;
    float v = (c < C) ? src[(long)r * lds + c] : 0.f;
    dst[(long)r * ldd + c] = __float2bfloat16(v);
}

__global__ void transpose_bf_k(const float* __restrict__ src,
                               __nv_bfloat16* __restrict__ dst,
                               int R, int C, int ldd) {
    __shared__ float tile[32][33];
    int c0 = blockIdx.x * 32, r0 = blockIdx.y * 32;
#pragma unroll
    for (int i = 0; i < 4; i++) {
        int r = r0 + threadIdx.y + i * 8;
        int c = c0 + threadIdx.x;
        tile[threadIdx.y + i * 8][threadIdx.x] = (r < R && c < C) ? src[(long)r * C + c] : 0.f;
    }
    __syncthreads();
#pragma unroll
    for (int i = 0; i < 4; i++) {
        int orow = c0 + threadIdx.y + i * 8;
        int ocol = r0 + threadIdx.x;
        if (orow < C)
            dst[(long)orow * ldd + ocol] = __float2bfloat16(tile[threadIdx.x][threadIdx.y + i * 8]);
    }
}

__global__ void betaT_k() {
    __shared__ float sm[64][33];
    int t = blockIdx.y;
    int v0 = blockIdx.x * 32;
    int lane = threadIdx.x & 31, w = threadIdx.x >> 5;
    for (int k = w; k < 64; k += 8) {
        int v = v0 + lane;
        sm[k][lane] = (k < K_ && v < V_) ? g_beta[((long)t * K_ + k) * V_ + v] : 0.f;
    }
    __syncthreads();
    int r = threadIdx.x >> 3;
    int c0 = (threadIdx.x & 7) * 8;
    if (v0 + r < V_) {
        __nv_bfloat16 tmp[8];
#pragma unroll
        for (int j = 0; j < 8; j++) tmp[j] = __float2bfloat16(sm[c0 + j][r]);
        *(uint4*)&g_betaT_bf[((long)t * NP_V + v0 + r) * 64 + c0] = *(uint4*)tmp;
    }
}

// fused prep: whhT/wih bf16 (interleaved), bi, wml
__global__ void prep_fused_k(const float* __restrict__ Wih, const float* __restrict__ Whh,
                             const float* __restrict__ bih, const float* __restrict__ bhh,
                             const float* __restrict__ mutW, const float* __restrict__ mutb,
                             const float* __restrict__ lstW, const float* __restrict__ lstb) {
    int idx = blockIdx.x * blockDim.x + threadIdx.x;
    const int S1 = HE_ * 4 * HE_;
    const int S2 = S1 + 4 * HE_ * HE_;
    const int S3 = S2 + 4 * HE_;
    const int S4 = S3 + 128 * HT_;
    const int S5 = S4 + 128;
    if (idx < S1) {
        int k = idx >> 10, r = idx & 1023;
        int j = r >> 2, gate = r & 3;
        g_whhT_bf[idx] = __float2bfloat16(Whh[((long)(gate * HE_ + j)) * HE_ + k]);
    } else if (idx < S2) {
        int i = idx - S1;
        int r = i >> 8, k = i & 255;
        int j = r >> 2, gate = r & 3;
        g_wih_bf[i] = __float2bfloat16(Wih[((long)(gate * HE_ + j)) * HE_ + k]);
    } else if (idx < S3) {
        int r = idx - S2;
        int j = r >> 2, gate = r & 3;
        g_bi_int[r] = bih[gate * HE_ + j] + bhh[gate * HE_ + j];
    } else if (idx < S4) {
        int i = idx - S3;
        int row = i / HT_, k = i % HT_;
        float v = 0.f;
        if (row < 50) v = mutW[(long)row * HT_ + k];
        else if (row < 100) v = lstW[(long)(row - 50) * HT_ + k];
        g_wml_bf[i] = __float2bfloat16(v);
    } else if (idx < S5) {
        int r = idx - S4;
        g_wmlb[r] = (r < 50) ? mutb[r] : (r < 100 ? lstb[r - 50] : 0.f);
    }
}

__global__ void alphas_kernel(const float* __restrict__ muq, const float* __restrict__ lsq) {
    int idx = blockIdx.x * blockDim.x + threadIdx.x;
    if (idx >= NA_) return;
    int t = idx / (K_ * RHO_), rem = idx % (K_ * RHO_);
    int k = rem / RHO_, r = rem % RHO_;
    int src = (k * T_ + t) * RHO_ + r;
    float a = muq[src] + g_eps_a[idx] * expf(0.5f * lsq[src]);
    g_alphas[idx] = a;
    int row = t * K_ + k;
    g_alphas_bf[(long)row * KP_RHO + r] = __float2bfloat16(a);
}

__global__ void kld_alpha_kernel(const float* __restrict__ muq, const float* __restrict__ lsq) {
    __shared__ float red[256];
    float acc = 0.f;
    for (int idx = blockIdx.x * blockDim.x + threadIdx.x; idx < NA_;
         idx += gridDim.x * blockDim.x) {
        int t = idx / (K_ * RHO_), rem = idx % (K_ * RHO_);
        int k = rem / RHO_, r = rem % RHO_;
        int src = (k * T_ + t) * RHO_ + r;
        float mu = muq[src];
        float ls = lsq[src];
        float qls = fminf(fmaxf(ls, -100.f), 100.f);
        float pmu = (t == 0) ? 0.f : g_alphas[idx - K_ * RHO_];
        float pls = (t == 0) ? 0.f : LOGD;
        float d = mu - pmu;
        acc += (expf(qls) + d * d) / (expf(pls) + 1e-6f) - 1.f + pls - qls;
    }
    float s = block_sum(acc, red);
    if (threadIdx.x == 0) g_part_a[blockIdx.x] = s;
}

__global__ void softmax_rows_kernel() {
    __shared__ float red[256];
    long base = (long)blockIdx.x * V_;
    long basebf = (long)blockIdx.x * KP_V;
    int tid = threadIdx.x;
    float m = -FLT_MAX;
    for (int c = tid; c < V_; c += 256) m = fmaxf(m, g_beta[base + c]);
    m = block_max(m, red);
    float s = 0.f;
    for (int c = tid; c < V_; c += 256) {
        float e = expf(g_beta[base + c] - m);
        g_beta[base + c] = e; s += e;
    }
    s = block_sum(s, red);
    float inv = 1.f / s;
    for (int c = tid; c < V_; c += 256) {
        float b = g_beta[base + c] * inv;
        g_beta[base + c] = b;
        g_beta_bf[basebf + c] = __float2bfloat16(b);
    }
}

__global__ void combine_inp_k(const float* __restrict__ qeb) {
    int idx = blockIdx.x * blockDim.x + threadIdx.x;
    if (idx >= B_ * T_ * HE_) return;
    int j = idx & (HE_ - 1);
    float s = qeb[j];
#pragma unroll
    for (int z = 0; z < INP_SPLIT; z++) s += g_inp_part[(long)z * B_ * T_ * HE_ + idx];
    g_inp_bf[idx] = __float2bfloat16(s);
}

// ---------------- single-launch LSTM scan: 128 blocks x 2 batch rows ----------------
__global__ void __launch_bounds__(256) lstm_scan_k() {
    __shared__ float h[2][HE_];
    int j = threadIdx.x;
    int b0 = 2 * blockIdx.x, b1 = b0 + 1;
    float c0 = 0.f, c1 = 0.f;
    h[0][j] = 0.f; h[1][j] = 0.f;
    __syncthreads();
    const uint2* wT = (const uint2*)g_whhT_bf;
    for (int t = 0; t < T_; t++) {
        float a00 = 0.f, a10 = 0.f, a20 = 0.f, a30 = 0.f;
        float a01 = 0.f, a11 = 0.f, a21 = 0.f, a31 = 0.f;
#pragma unroll 4
        for (int k = 0; k < HE_; k++) {
            uint2 w = wT[k * 256 + j];
            float2 w01 = __bfloat1622float2(*(const __nv_bfloat162*)&w.x);
            float2 w23 = __bfloat1622float2(*(const __nv_bfloat162*)&w.y);
            float hb0 = h[0][k], hb1 = h[1][k];
            a00 = fmaf(w01.x, hb0, a00); a10 = fmaf(w01.y, hb0, a10);
            a20 = fmaf(w23.x, hb0, a20); a30 = fmaf(w23.y, hb0, a30);
            a01 = fmaf(w01.x, hb1, a01); a11 = fmaf(w01.y, hb1, a11);
            a21 = fmaf(w23.x, hb1, a21); a31 = fmaf(w23.y, hb1, a31);
        }
        __syncthreads();
        {
            float4 gx4 = *(const float4*)&g_gx[((long)b0 * T_ + t) * (4 * HE_) + 4 * j];
            float gi = gx4.x + a00, gf = gx4.y + a10, gg = gx4.z + a20, go = gx4.w + a30;
            float si = 1.f / (1.f + expf(-gi));
            float sf = 1.f / (1.f + expf(-gf));
            float so = 1.f / (1.f + expf(-go));
            c0 = sf * c0 + si * tanhf(gg);
            float hh = so * tanhf(c0);
            h[0][j] = hh;
            g_lstm[((long)t * B_ + b0) * HE_ + j] = hh;
        }
        {
            float4 gx4 = *(const float4*)&g_gx[((long)b1 * T_ + t) * (4 * HE_) + 4 * j];
            float gi = gx4.x + a01, gf = gx4.y + a11, gg = gx4.z + a21, go = gx4.w + a31;
            float si = 1.f / (1.f + expf(-gi));
            float sf = 1.f / (1.f + expf(-gf));
            float so = 1.f / (1.f + expf(-go));
            c1 = sf * c1 + si * tanhf(gg);
            float hh = so * tanhf(c1);
            h[1][j] = hh;
            g_lstm[((long)t * B_ + b1) * HE_ + j] = hh;
        }
        __syncthreads();
    }
}

// ---------------- single-launch eta scan: 64 blocks x 4 batch rows ----------------
#define ETA_SMEM (100*306*2 + (4*306 + 200 + 200 + 200) * 4)
__global__ void __launch_bounds__(256) eta_scan_k(
    const float* __restrict__ mueW, const float* __restrict__ mueb,
    const float* __restrict__ lseW, const float* __restrict__ lseb) {
    extern __shared__ char smc[];
    __nv_bfloat16* wsm = (__nv_bfloat16*)smc;
    float* z   = (float*)(smc + 100 * 306 * 2);
    float* smu = z + 4 * 306;
    float* sls = smu + 200;
    float* skl = sls + 200;
    int tid = threadIdx.x, bk = blockIdx.x;
    for (int i = tid; i < 100 * 306; i += 256) {
        int r = i / 306, k = i % 306;
        float v = (r < 50) ? mueW[(long)r * HEK_ + k] : lseW[(long)(r - 50) * HEK_ + k];
        wsm[i] = __float2bfloat16(v);
    }
    if (tid < 200) {
        int q = tid / 50, k = tid % 50;
        z[q * 306 + 256 + k] = 0.f;
    }
    __syncthreads();
    for (int t = 0; t < T_; t++) {
#pragma unroll
        for (int q = 0; q < 4; q++)
            z[q * 306 + tid] = g_lstm[((long)t * B_ + 4 * bk + q) * HE_ + tid];
        __syncthreads();
#pragma unroll
        for (int rep = 0; rep < 2; rep++) {
            int o = tid + rep * 256;
            if (o < 400) {
                int q = o / 100, r = o % 100;
                float acc = (r < 50) ? mueb[r] : lseb[r - 50];
                const __nv_bfloat16* wr = wsm + r * 306;
                const float* zq = z + q * 306;
#pragma unroll 2
                for (int k = 0; k < HEK_; k++)
                    acc = fmaf(__bfloat162float(wr[k]), zq[k], acc);
                if (r < 50) smu[q * 50 + r] = acc;
                else        sls[q * 50 + (r - 50)] = acc;
            }
        }
        __syncthreads();
        if (tid < 200) {
            int q = tid / 50, k = tid % 50;
            int b = 4 * bk + q;
            float mu = smu[q * 50 + k], ls = sls[q * 50 + k];
            float pmu = z[q * 306 + 256 + k];
            float eps = g_eps_e[((long)t * B_ + b) * K_ + k];
            float eta = mu + eps * expf(0.5f * ls);
            g_etas[((long)t * B_ + b) * K_ + k] = eta;
            float qls = fminf(fmaxf(ls, -100.f), 100.f);
            float pls = (t == 0) ? 0.f : LOGD;
            float d = mu - pmu;
            skl[tid] = (expf(qls) + d * d) / (expf(pls) + 1e-6f) - 1.f + pls - qls;
            z[q * 306 + 256 + k] = eta;
        }
        __syncthreads();
        if (tid < 4) {
            float s = 0.f;
            for (int k = 0; k < 50; k++) s += skl[tid * 50 + k];
            g_part_ke[t * B_ + 4 * bk + tid] = s;
        }
        __syncthreads();
    }
}

// h1 = relu(h1e + sum_z h1b_part) -> bf16
__global__ void combine_h1_kernel() {
    int j = blockIdx.x * blockDim.x + threadIdx.x;
    if (j >= HT_) return;
    int row = blockIdx.y;
    int b = row & (B_ - 1);
    float hb = 0.f;
#pragma unroll
    for (int z = 0; z < H1B_SPLIT; z++) hb += g_h1b_part[(long)z * B_ * HT_ + b * HT_ + j];
    long idx = (long)row * HT_ + j;
    float v = fmaxf(g_h1e[idx] + hb, 0.f);
    g_h1_bf[idx] = __float2bfloat16(v);
}

__global__ void theta_kernel() {
    __shared__ float red[64];
    int row = blockIdx.x, k = threadIdx.x;
    long base = (long)row * K_;
    long mbase = (long)row * 100;
    bool val = k < K_;
    float mu = 0.f, ls = 0.f, zv = -FLT_MAX;
    if (val) {
        mu = g_mls[mbase + k];
        ls = g_mls[mbase + 50 + k];
        zv = mu + g_eps_t[base + k] * expf(0.5f * ls);
    }
    float mx = block_max(zv, red);
    float e = val ? expf(zv - mx) : 0.f;
    float sum = block_sum(e, red);
    float th = e / sum;
    if (val) {
        g_theta_arr[base + k] = th;
        g_theta_bf[(long)row * 64 + k] = __float2bfloat16(th);
    } else if (k < 64) {
        g_theta_bf[(long)row * 64 + k] = __float2bfloat16(0.f);
    }
    float kl = 0.f;
    if (val) {
        float qls = fminf(fmaxf(ls, -100.f), 100.f);
        float d = mu - g_etas[base + k];
        kl = (expf(qls) + d * d) / (1.f + 1e-6f) - 1.f - qls;
    }
    float s = block_sum(kl, red);
    if (k == 0) g_part_kt[row] = s;
}

__global__ void final_reduce_kernel(float* out, int out_size) {
    __shared__ float red[256];
    int tid = threadIdx.x;
    float v;
    v = 0.f; for (int i = tid; i < RB_NLL;  i += 256) v += g_part_nll[i];
    float nll  = block_sum(v, red) * (10.0f / B_);
    v = 0.f; for (int i = tid; i < T_ * B_; i += 256) v += g_part_kt[i];
    float kt   = block_sum(v, red) * (0.5f / (T_ * B_));
    v = 0.f; for (int i = tid; i < RB_A;    i += 256) v += g_part_a[i];
    float ka   = block_sum(v, red) * (0.5f / (T_ * K_));
    v = 0.f; for (int i = tid; i < T_ * B_; i += 256) v += g_part_ke[i];
    float ke   = block_sum(v, red) * (0.5f / B_);
    v = 0.f; for (int i = tid; i < RB_COND; i += 256) v += g_part_cond[i];
    float cond = block_sum(v, red) * (-0.01f);
    if (tid == 0) {
        if (out_size > 0) out[0] = nll;
        if (out_size > 1) out[1] = kt;
        if (out_size > 2) out[2] = ka;
        if (out_size > 3) out[3] = ke;
        if (out_size > 4) out[4] = cond;
    }
}

// ---------------- host driver ----------------
static inline int ceil_div(long a, long b) { return (int)((a + b - 1) / b); }

extern "C" void kernel_launch(void* const* d_in, const int* in_sizes, int n_in,
                              void* d_out, int out_size) {
    (void)in_sizes; (void)n_in;
    const float* nb   = (const float*)d_in[0];
    const float* bow  = (const float*)d_in[1];
    const float* adj  = (const float*)d_in[2];
    const float* muqa = (const float*)d_in[3];
    const float* lsqa = (const float*)d_in[4];
    const float* rhoW = (const float*)d_in[5];
    const float* rhob = (const float*)d_in[6];
    const float* W1   = (const float*)d_in[7];
    const float* b1   = (const float*)d_in[8];
    const float* W2   = (const float*)d_in[9];
    const float* b2   = (const float*)d_in[10];
    const float* mutW = (const float*)d_in[11];
    const float* mutb = (const float*)d_in[12];
    const float* lstW = (const float*)d_in[13];
    const float* lstb = (const float*)d_in[14];
    const float* qeW  = (const float*)d_in[15];
    const float* qeb  = (const float*)d_in[16];
    const float* Wih  = (const float*)d_in[17];
    const float* Whh  = (const float*)d_in[18];
    const float* bih  = (const float*)d_in[19];
    const float* bhh  = (const float*)d_in[20];
    const float* mueW = (const float*)d_in[21];
    const float* mueb = (const float*)d_in[22];
    const float* lseW = (const float*)d_in[23];
    const float* lseb = (const float*)d_in[24];
    float* out = (float*)d_out;

    unsigned ka0, ka1, ke0, ke1, kt0, kt1;
    tf2x32(0u, 42u, 0u, 0u, &ka0, &ka1);
    tf2x32(0u, 42u, 0u, 1u, &ke0, &ke1);
    tf2x32(0u, 42u, 0u, 2u, &kt0, &kt1);

    float *p_beta, *p_inp_part, *p_gx, *p_etas, *p_h1e, *p_h1b_part, *p_mls;
    float *p_bi_int, *p_part_cond, *p_wmlb;
    __nv_bfloat16 *p_alphas_bf, *p_beta_bf, *p_adjT, *p_bow_bf, *p_qew_bf, *p_nb_bf;
    __nv_bfloat16 *p_w1_bf, *p_rhow_bf, *p_w2_bf, *p_wml_bf, *p_h1_bf, *p_h2_bf;
    __nv_bfloat16 *p_inp_bf, *p_wih_bf;
    cudaGetSymbolAddress((void**)&p_beta,      g_beta);
    cudaGetSymbolAddress((void**)&p_inp_part,  g_inp_part);
    cudaGetSymbolAddress((void**)&p_gx,        g_gx);
    cudaGetSymbolAddress((void**)&p_etas,      g_etas);
    cudaGetSymbolAddress((void**)&p_h1e,       g_h1e);
    cudaGetSymbolAddress((void**)&p_h1b_part,  g_h1b_part);
    cudaGetSymbolAddress((void**)&p_mls,       g_mls);
    cudaGetSymbolAddress((void**)&p_bi_int,    g_bi_int);
    cudaGetSymbolAddress((void**)&p_part_cond, g_part_cond);
    cudaGetSymbolAddress((void**)&p_wmlb,      g_wmlb);
    cudaGetSymbolAddress((void**)&p_alphas_bf, g_alphas_bf);
    cudaGetSymbolAddress((void**)&p_beta_bf,   g_beta_bf);
    cudaGetSymbolAddress((void**)&p_adjT,      g_adjT_bf);
    cudaGetSymbolAddress((void**)&p_bow_bf,    g_bow_bf);
    cudaGetSymbolAddress((void**)&p_qew_bf,    g_qew_bf);
    cudaGetSymbolAddress((void**)&p_nb_bf,     g_nb_bf);
    cudaGetSymbolAddress((void**)&p_w1_bf,     g_w1_bf);
    cudaGetSymbolAddress((void**)&p_rhow_bf,   g_rhow_bf);
    cudaGetSymbolAddress((void**)&p_w2_bf,     g_w2_bf);
    cudaGetSymbolAddress((void**)&p_wml_bf,    g_wml_bf);
    cudaGetSymbolAddress((void**)&p_h1_bf,     g_h1_bf);
    cudaGetSymbolAddress((void**)&p_h2_bf,     g_h2_bf);
    cudaGetSymbolAddress((void**)&p_inp_bf,    g_inp_bf);
    cudaGetSymbolAddress((void**)&p_wih_bf,    g_wih_bf);

    cudaFuncSetAttribute(tc_gemm_k<true,  false, false, false>, cudaFuncAttributeMaxDynamicSharedMemorySize, TC_SMEM_BYTES);
    cudaFuncSetAttribute(tc_gemm_k<false, false, false, true >, cudaFuncAttributeMaxDynamicSharedMemorySize, TC_SMEM_BYTES);
    cudaFuncSetAttribute(tc_gemm_k<false, false, false, false>, cudaFuncAttributeMaxDynamicSharedMemorySize, TC_SMEM_BYTES);
    cudaFuncSetAttribute(tc_gemm_k<true,  true,  true,  false>, cudaFuncAttributeMaxDynamicSharedMemorySize, TC_SMEM_BYTES);
    cudaFuncSetAttribute(eta_scan_k, cudaFuncAttributeMaxDynamicSharedMemorySize, ETA_SMEM);

    // ---- alpha/beta chain first (4th launch = beta TC GEMM, A/B vs R14) ----
    convbf_vec_k<<<dim3(ceil_div(KP_RHO / 8, 256), V_), 256>>>(rhoW, RHO_, p_rhow_bf, KP_RHO, RHO_);
    int totalElems = NA_ + 2 * NE_;
    eps_kernel<<<(totalElems + 255) / 256, 256>>>(ka0, ka1, ke0, ke1, kt0, kt1);
    alphas_kernel<<<(NA_ + 255) / 256, 256>>>(muqa, lsqa);
    tc_gemm_k<true, false, false, false><<<dim3(40, 10), 256, TC_SMEM_BYTES>>>(
        p_alphas_bf, KP_RHO, p_rhow_bf, KP_RHO, rhob, p_beta, nullptr, V_,
        nullptr, nullptr, T_ * K_, V_, KP_RHO);
    kld_alpha_kernel<<<RB_A, 256>>>(muqa, lsqa);
    softmax_rows_kernel<<<T_ * K_, 256>>>();
    betaT_k<<<dim3(ceil_div(V_, 32), T_), 256>>>();
    transpose_bf_k<<<dim3(ceil_div(V_, 32), ceil_div(V_, 32)), dim3(32, 8)>>>(adj, p_adjT, V_, V_, KP_V);
    tc_gemm_k<false, false, false, true><<<dim3(40, 10), 256, TC_SMEM_BYTES>>>(
        p_beta_bf, KP_V, p_adjT, KP_V, nullptr, nullptr, nullptr, V_,
        p_beta, p_part_cond, T_ * K_, V_, KP_V);

    // ---- conversions + prep ----
    convbf_vec_k<<<dim3(ceil_div(KP_V / 8, 256), B_ * T_), 256>>>(bow, V_, p_bow_bf, KP_V, V_);
    convbf_vec_k<<<dim3(ceil_div(KP_V / 8, 256), HE_), 256>>>(qeW, V_, p_qew_bf, KP_V, V_);
    convbf_vec_k<<<dim3(ceil_div(KP_V / 8, 256), B_), 256>>>(nb, V_, p_nb_bf, KP_V, V_);
    convbf_row_k<<<dim3(ceil_div(KP_V, 256), HT_), 256>>>(W1, VK_, p_w1_bf, KP_V, V_);
    convbf_vec_k<<<dim3(ceil_div(HT_ / 8, 256), HT_), 256>>>(W2, HT_, p_w2_bf, HT_, HT_);
    {
        int preptotal = HE_ * 4 * HE_ + 4 * HE_ * HE_ + 4 * HE_ + 128 * HT_ + 128;
        prep_fused_k<<<(preptotal + 255) / 256, 256>>>(Wih, Whh, bih, bhh, mutW, mutb, lstW, lstb);
    }

    // ---- inp (split-K) -> bf16 combine -> gx (TC) -> LSTM scan -> eta scan ----
    tc_gemm_k<false, false, false, false><<<dim3(2, 48, INP_SPLIT), 256, TC_SMEM_BYTES>>>(
        p_bow_bf, KP_V, p_qew_bf, KP_V, nullptr, p_inp_part, nullptr, HE_,
        nullptr, nullptr, B_ * T_, HE_, KP_V);
    combine_inp_k<<<ceil_div(B_ * T_ * HE_, 256), 256>>>(qeb);
    tc_gemm_k<true, false, false, false><<<dim3(8, 48), 256, TC_SMEM_BYTES>>>(
        p_inp_bf, HE_, p_wih_bf, HE_, p_bi_int, p_gx, nullptr, 4 * HE_,
        nullptr, nullptr, B_ * T_, 4 * HE_, HE_);
    lstm_scan_k<<<128, 256>>>();
    eta_scan_k<<<64, 256, ETA_SMEM>>>(mueW, mueb, lseW, lseb);

    // ---- theta encoder ----
    gemm_k<false><<<dim3(13, 48), 256>>>(
        p_etas, K_, W1 + V_, VK_, b1, p_h1e, HT_, T_ * B_, HT_, K_);
    tc_gemm_k<false, false, false, false><<<dim3(7, 4, H1B_SPLIT), 256, TC_SMEM_BYTES>>>(
        p_nb_bf, KP_V, p_w1_bf, KP_V, nullptr, p_h1b_part, nullptr, HT_,
        nullptr, nullptr, B_, HT_, KP_V);
    combine_h1_kernel<<<dim3(ceil_div(HT_, 256), T_ * B_), 256>>>();
    tc_gemm_k<true, true, true, false><<<dim3(7, 48), 256, TC_SMEM_BYTES>>>(
        p_h1_bf, HT_, p_w2_bf, HT_, b2, nullptr, p_h2_bf, HT_,
        nullptr, nullptr, T_ * B_, HT_, HT_);
    tc_gemm_k<true, false, false, false><<<dim3(1, 48), 256, TC_SMEM_BYTES>>>(
        p_h2_bf, HT_, p_wml_bf, HT_, p_wmlb, p_mls, nullptr, 100,
        nullptr, nullptr, T_ * B_, 100, HT_);

    // ---- theta + NLL + final ----
    theta_kernel<<<T_ * B_, 64>>>();
    tc_nll_k<<<dim3(40, 2, T_), 256>>>(bow);
    final_reduce_kernel<<<1, 256>>>(out, out_size);
}